// round 1
// baseline (speedup 1.0000x reference)
#include <cuda_runtime.h>
#include <math.h>

#define Bb 4
#define Ss 2048
#define Dd 1024
#define Hh 16
#define DK 64

static const size_t OUT_ELEMS  = (size_t)Bb * Ss * Dd;        // 8388608
static const size_t ATTN_ELEMS = (size_t)Bb * Hh * Ss * Ss;   // 268435456

// Scratch (device globals — allocation-free per harness rules)
__device__ float g_h[(size_t)Bb * Ss * Dd];
__device__ float g_q[(size_t)Bb * Hh * Ss * DK];
__device__ float g_k[(size_t)Bb * Hh * Ss * DK];
__device__ float g_v[(size_t)Bb * Hh * Ss * DK];
__device__ float g_o[(size_t)Bb * Ss * Dd];
__device__ float g_attn_scratch[(size_t)Bb * Hh * Ss * Ss];  // fallback if attn not in d_out

// ---------------------------------------------------------------------------
// Block reductions (blockDim.x == 256)
// ---------------------------------------------------------------------------
__device__ __forceinline__ float blockReduceSum(float val) {
    __shared__ float sh[32];
    int lane = threadIdx.x & 31, wid = threadIdx.x >> 5;
    #pragma unroll
    for (int o = 16; o; o >>= 1) val += __shfl_down_sync(0xffffffffu, val, o);
    if (lane == 0) sh[wid] = val;
    __syncthreads();
    val = (threadIdx.x < 8) ? sh[lane] : 0.0f;
    if (wid == 0) {
        #pragma unroll
        for (int o = 4; o; o >>= 1) val += __shfl_down_sync(0xffffffffu, val, o);
    }
    __syncthreads();
    return val;  // valid on thread 0
}

__device__ __forceinline__ float blockReduceMax(float val) {
    __shared__ float sh[32];
    int lane = threadIdx.x & 31, wid = threadIdx.x >> 5;
    #pragma unroll
    for (int o = 16; o; o >>= 1) val = fmaxf(val, __shfl_down_sync(0xffffffffu, val, o));
    if (lane == 0) sh[wid] = val;
    __syncthreads();
    val = (threadIdx.x < 8) ? sh[lane] : -INFINITY;
    if (wid == 0) {
        #pragma unroll
        for (int o = 4; o; o >>= 1) val = fmaxf(val, __shfl_down_sync(0xffffffffu, val, o));
    }
    __syncthreads();
    return val;  // valid on thread 0
}

// ---------------------------------------------------------------------------
// LayerNorm (reference quirk: unbiased variance /(D-1), denom = std + eps)
// one block per row, 256 threads, 4 floats each
// ---------------------------------------------------------------------------
__global__ __launch_bounds__(256) void ln_kernel(
    const float* __restrict__ x, const float* __restrict__ a,
    const float* __restrict__ bvec, float* __restrict__ h)
{
    int row = blockIdx.x;
    const float4* xr = (const float4*)(x + (size_t)row * Dd);
    float4 v = xr[threadIdx.x];

    float s = blockReduceSum(v.x + v.y + v.z + v.w);
    __shared__ float mean_s, inv_s;
    if (threadIdx.x == 0) mean_s = s * (1.0f / Dd);
    __syncthreads();
    float mean = mean_s;

    float dx = v.x - mean, dy = v.y - mean, dz = v.z - mean, dw = v.w - mean;
    float sq = blockReduceSum(dx * dx + dy * dy + dz * dz + dw * dw);
    if (threadIdx.x == 0) inv_s = 1.0f / (sqrtf(sq * (1.0f / (Dd - 1))) + 1e-6f);
    __syncthreads();
    float inv = inv_s;

    float4 av = ((const float4*)a)[threadIdx.x];
    float4 bv = ((const float4*)bvec)[threadIdx.x];
    float4 o;
    o.x = av.x * dx * inv + bv.x;
    o.y = av.y * dy * inv + bv.y;
    o.z = av.z * dz * inv + bv.z;
    o.w = av.w * dw * inv + bv.w;
    ((float4*)(h + (size_t)row * Dd))[threadIdx.x] = o;
}

// ---------------------------------------------------------------------------
// QKV projection: C[m,n] = sum_k h[m,k] * W[n,k] + bias[n]
// scattered to [B,H,S,DK] layout. 64x64x16 tiles, 4x4 microtile.
// ---------------------------------------------------------------------------
__global__ __launch_bounds__(256) void gemm_qkv_kernel(
    const float* __restrict__ A, const float* __restrict__ W,
    const float* __restrict__ bias, float* __restrict__ out)
{
    __shared__ __align__(16) float As[16][68];
    __shared__ __align__(16) float Bs[16][68];
    const int K = Dd;
    int tx = threadIdx.x, ty = threadIdx.y;
    int tid = ty * 16 + tx;
    int m0 = blockIdx.y * 64, n0 = blockIdx.x * 64;
    int lr = tid >> 2;
    int lc = (tid & 3) * 4;
    const float* Ap = A + (size_t)(m0 + lr) * K + lc;
    const float* Wp = W + (size_t)(n0 + lr) * K + lc;
    float acc[4][4] = {};

    for (int k0 = 0; k0 < K; k0 += 16) {
        float4 a4 = *(const float4*)(Ap + k0);
        float4 b4 = *(const float4*)(Wp + k0);
        As[lc + 0][lr] = a4.x; As[lc + 1][lr] = a4.y; As[lc + 2][lr] = a4.z; As[lc + 3][lr] = a4.w;
        Bs[lc + 0][lr] = b4.x; Bs[lc + 1][lr] = b4.y; Bs[lc + 2][lr] = b4.z; Bs[lc + 3][lr] = b4.w;
        __syncthreads();
        #pragma unroll
        for (int kk = 0; kk < 16; kk++) {
            float4 a = *(const float4*)&As[kk][ty * 4];
            float4 b = *(const float4*)&Bs[kk][tx * 4];
            float ar[4] = {a.x, a.y, a.z, a.w};
            float br[4] = {b.x, b.y, b.z, b.w};
            #pragma unroll
            for (int i = 0; i < 4; i++)
                #pragma unroll
                for (int j = 0; j < 4; j++)
                    acc[i][j] = fmaf(ar[i], br[j], acc[i][j]);
        }
        __syncthreads();
    }
    #pragma unroll
    for (int i = 0; i < 4; i++) {
        int m = m0 + ty * 4 + i;
        int b = m >> 11, s = m & (Ss - 1);
        #pragma unroll
        for (int j = 0; j < 4; j++) {
            int n = n0 + tx * 4 + j;
            int hh = n >> 6, d = n & 63;
            out[(((size_t)(b * Hh + hh) * Ss) + s) * DK + d] = acc[i][j] + bias[n];
        }
    }
}

// ---------------------------------------------------------------------------
// Scores: logits[bh, m, n] = scale * Q[bh,m,:] . K[bh,n,:]; mask==0 -> -1e9
// ---------------------------------------------------------------------------
__global__ __launch_bounds__(256) void scores_kernel(
    const float* __restrict__ Q, const float* __restrict__ Kt,
    const int* __restrict__ mask, float* __restrict__ attn)
{
    __shared__ __align__(16) float As[16][68];
    __shared__ __align__(16) float Bs[16][68];
    int bh = blockIdx.z;
    const float* Qp = Q + (size_t)bh * Ss * DK;
    const float* Kp = Kt + (size_t)bh * Ss * DK;
    const int* mrow = mask + (size_t)(bh >> 4) * Ss * Ss;
    float* arow = attn + (size_t)bh * Ss * Ss;

    int tx = threadIdx.x, ty = threadIdx.y;
    int tid = ty * 16 + tx;
    int m0 = blockIdx.y * 64, n0 = blockIdx.x * 64;
    int lr = tid >> 2;
    int lc = (tid & 3) * 4;
    const float* Ap = Qp + (size_t)(m0 + lr) * DK + lc;
    const float* Bp = Kp + (size_t)(n0 + lr) * DK + lc;
    float acc[4][4] = {};

    #pragma unroll
    for (int k0 = 0; k0 < DK; k0 += 16) {
        float4 a4 = *(const float4*)(Ap + k0);
        float4 b4 = *(const float4*)(Bp + k0);
        As[lc + 0][lr] = a4.x; As[lc + 1][lr] = a4.y; As[lc + 2][lr] = a4.z; As[lc + 3][lr] = a4.w;
        Bs[lc + 0][lr] = b4.x; Bs[lc + 1][lr] = b4.y; Bs[lc + 2][lr] = b4.z; Bs[lc + 3][lr] = b4.w;
        __syncthreads();
        #pragma unroll
        for (int kk = 0; kk < 16; kk++) {
            float4 a = *(const float4*)&As[kk][ty * 4];
            float4 b = *(const float4*)&Bs[kk][tx * 4];
            float ar[4] = {a.x, a.y, a.z, a.w};
            float br[4] = {b.x, b.y, b.z, b.w};
            #pragma unroll
            for (int i = 0; i < 4; i++)
                #pragma unroll
                for (int j = 0; j < 4; j++)
                    acc[i][j] = fmaf(ar[i], br[j], acc[i][j]);
        }
        __syncthreads();
    }
    const float scale = 0.125f;  // 1/sqrt(64)
    #pragma unroll
    for (int i = 0; i < 4; i++) {
        int m = m0 + ty * 4 + i;
        #pragma unroll
        for (int j = 0; j < 4; j++) {
            int n = n0 + tx * 4 + j;
            size_t idx = (size_t)m * Ss + n;
            float val = acc[i][j] * scale;
            if (mrow[idx] == 0) val = -1e9f;
            arow[idx] = val;
        }
    }
}

// ---------------------------------------------------------------------------
// Row softmax over 2048 elements (in place). One block per row.
// ---------------------------------------------------------------------------
__global__ __launch_bounds__(256) void softmax_kernel(float* __restrict__ attn)
{
    float* p = attn + (size_t)blockIdx.x * Ss;
    float4 v0 = ((float4*)p)[threadIdx.x * 2];
    float4 v1 = ((float4*)p)[threadIdx.x * 2 + 1];

    float mx = fmaxf(fmaxf(fmaxf(v0.x, v0.y), fmaxf(v0.z, v0.w)),
                     fmaxf(fmaxf(v1.x, v1.y), fmaxf(v1.z, v1.w)));
    mx = blockReduceMax(mx);
    __shared__ float mx_s, inv_s;
    if (threadIdx.x == 0) mx_s = mx;
    __syncthreads();
    mx = mx_s;

    float4 e0, e1;
    e0.x = expf(v0.x - mx); e0.y = expf(v0.y - mx);
    e0.z = expf(v0.z - mx); e0.w = expf(v0.w - mx);
    e1.x = expf(v1.x - mx); e1.y = expf(v1.y - mx);
    e1.z = expf(v1.z - mx); e1.w = expf(v1.w - mx);

    float s = (e0.x + e0.y + e0.z + e0.w) + (e1.x + e1.y + e1.z + e1.w);
    s = blockReduceSum(s);
    if (threadIdx.x == 0) inv_s = 1.0f / s;
    __syncthreads();
    float inv = inv_s;

    e0.x *= inv; e0.y *= inv; e0.z *= inv; e0.w *= inv;
    e1.x *= inv; e1.y *= inv; e1.z *= inv; e1.w *= inv;
    ((float4*)p)[threadIdx.x * 2]     = e0;
    ((float4*)p)[threadIdx.x * 2 + 1] = e1;
}

// ---------------------------------------------------------------------------
// AV: O[b, m, h*64 + n] = sum_k attn[bh,m,k] * V[bh,k,n]   (NN gemm, N=64)
// ---------------------------------------------------------------------------
__global__ __launch_bounds__(256) void av_kernel(
    const float* __restrict__ attn, const float* __restrict__ V,
    float* __restrict__ O)
{
    __shared__ __align__(16) float As[16][68];
    __shared__ __align__(16) float Bs[16][68];
    int bh = blockIdx.z;
    int b = bh >> 4, hh = bh & 15;
    const float* Ap0 = attn + (size_t)bh * Ss * Ss;
    const float* Vp = V + (size_t)bh * Ss * DK;

    int tx = threadIdx.x, ty = threadIdx.y;
    int tid = ty * 16 + tx;
    int m0 = blockIdx.y * 64;
    int lr = tid >> 2;
    int lc = (tid & 3) * 4;
    int vr = tid >> 4;         // 0..15 (k row in tile)
    int vc = (tid & 15) * 4;   // 0..60
    const float* Ap = Ap0 + (size_t)(m0 + lr) * Ss + lc;
    float acc[4][4] = {};

    for (int k0 = 0; k0 < Ss; k0 += 16) {
        float4 a4 = *(const float4*)(Ap + k0);
        float4 b4 = *(const float4*)(Vp + (size_t)(k0 + vr) * DK + vc);
        As[lc + 0][lr] = a4.x; As[lc + 1][lr] = a4.y; As[lc + 2][lr] = a4.z; As[lc + 3][lr] = a4.w;
        Bs[vr][vc + 0] = b4.x; Bs[vr][vc + 1] = b4.y; Bs[vr][vc + 2] = b4.z; Bs[vr][vc + 3] = b4.w;
        __syncthreads();
        #pragma unroll
        for (int kk = 0; kk < 16; kk++) {
            float4 a = *(const float4*)&As[kk][ty * 4];
            float4 b = *(const float4*)&Bs[kk][tx * 4];
            float ar[4] = {a.x, a.y, a.z, a.w};
            float br[4] = {b.x, b.y, b.z, b.w};
            #pragma unroll
            for (int i = 0; i < 4; i++)
                #pragma unroll
                for (int j = 0; j < 4; j++)
                    acc[i][j] = fmaf(ar[i], br[j], acc[i][j]);
        }
        __syncthreads();
    }
    #pragma unroll
    for (int i = 0; i < 4; i++) {
        int m = m0 + ty * 4 + i;
        #pragma unroll
        for (int j = 0; j < 4; j++) {
            int n = tx * 4 + j;
            O[((size_t)b * Ss + m) * Dd + hh * DK + n] = acc[i][j];
        }
    }
}

// ---------------------------------------------------------------------------
// FC + residual: out[m,n] = sum_k O[m,k] * fc_w[n,k] + fc_b[n] + x[m,n]
// ---------------------------------------------------------------------------
__global__ __launch_bounds__(256) void gemm_fc_kernel(
    const float* __restrict__ A, const float* __restrict__ W,
    const float* __restrict__ bias, const float* __restrict__ x,
    float* __restrict__ out)
{
    __shared__ __align__(16) float As[16][68];
    __shared__ __align__(16) float Bs[16][68];
    const int K = Dd;
    int tx = threadIdx.x, ty = threadIdx.y;
    int tid = ty * 16 + tx;
    int m0 = blockIdx.y * 64, n0 = blockIdx.x * 64;
    int lr = tid >> 2;
    int lc = (tid & 3) * 4;
    const float* Ap = A + (size_t)(m0 + lr) * K + lc;
    const float* Wp = W + (size_t)(n0 + lr) * K + lc;
    float acc[4][4] = {};

    for (int k0 = 0; k0 < K; k0 += 16) {
        float4 a4 = *(const float4*)(Ap + k0);
        float4 b4 = *(const float4*)(Wp + k0);
        As[lc + 0][lr] = a4.x; As[lc + 1][lr] = a4.y; As[lc + 2][lr] = a4.z; As[lc + 3][lr] = a4.w;
        Bs[lc + 0][lr] = b4.x; Bs[lc + 1][lr] = b4.y; Bs[lc + 2][lr] = b4.z; Bs[lc + 3][lr] = b4.w;
        __syncthreads();
        #pragma unroll
        for (int kk = 0; kk < 16; kk++) {
            float4 a = *(const float4*)&As[kk][ty * 4];
            float4 b = *(const float4*)&Bs[kk][tx * 4];
            float ar[4] = {a.x, a.y, a.z, a.w};
            float br[4] = {b.x, b.y, b.z, b.w};
            #pragma unroll
            for (int i = 0; i < 4; i++)
                #pragma unroll
                for (int j = 0; j < 4; j++)
                    acc[i][j] = fmaf(ar[i], br[j], acc[i][j]);
        }
        __syncthreads();
    }
    #pragma unroll
    for (int i = 0; i < 4; i++) {
        int m = m0 + ty * 4 + i;
        #pragma unroll
        for (int j = 0; j < 4; j++) {
            int n = n0 + tx * 4 + j;
            size_t idx = (size_t)m * Dd + n;
            out[idx] = acc[i][j] + bias[n] + x[idx];
        }
    }
}

// ---------------------------------------------------------------------------
extern "C" void kernel_launch(void* const* d_in, const int* in_sizes, int n_in,
                              void* d_out, int out_size)
{
    const float* x    = (const float*)d_in[0];
    const int*   mask = (const int*)d_in[1];
    const float* ln_a = (const float*)d_in[2];
    const float* ln_b = (const float*)d_in[3];
    const float* wq_w = (const float*)d_in[4];
    const float* wq_b = (const float*)d_in[5];
    const float* wk_w = (const float*)d_in[6];
    const float* wk_b = (const float*)d_in[7];
    const float* wv_w = (const float*)d_in[8];
    const float* wv_b = (const float*)d_in[9];
    const float* fc_w = (const float*)d_in[10];
    const float* fc_b = (const float*)d_in[11];
    float* out = (float*)d_out;

    void *ph, *pq, *pk, *pv, *po;
    cudaGetSymbolAddress(&ph, g_h);
    cudaGetSymbolAddress(&pq, g_q);
    cudaGetSymbolAddress(&pk, g_k);
    cudaGetSymbolAddress(&pv, g_v);
    cudaGetSymbolAddress(&po, g_o);
    float* h = (float*)ph;
    float* q = (float*)pq;
    float* k = (float*)pk;
    float* v = (float*)pv;
    float* o = (float*)po;

    float* attn;
    if ((size_t)out_size >= OUT_ELEMS + ATTN_ELEMS) {
        attn = out + OUT_ELEMS;  // tuple (out, attn) flattened
    } else {
        void* pa;
        cudaGetSymbolAddress(&pa, g_attn_scratch);
        attn = (float*)pa;
    }

    dim3 thr(16, 16);

    // 1. LayerNorm
    ln_kernel<<<Bb * Ss, 256>>>(x, ln_a, ln_b, h);

    // 2. Q, K, V projections
    gemm_qkv_kernel<<<dim3(16, 128), thr>>>(h, wq_w, wq_b, q);
    gemm_qkv_kernel<<<dim3(16, 128), thr>>>(h, wk_w, wk_b, k);
    gemm_qkv_kernel<<<dim3(16, 128), thr>>>(h, wv_w, wv_b, v);

    // 3. Scores + mask -> logits in attn region
    scores_kernel<<<dim3(32, 32, Bb * Hh), thr>>>(q, k, mask, attn);

    // 4. Softmax in place
    softmax_kernel<<<Bb * Hh * Ss, 256>>>(attn);

    // 5. attn @ V -> O (reassembled [B,S,H*Dv])
    av_kernel<<<dim3(1, 32, Bb * Hh), thr>>>(attn, v, o);

    // 6. FC + bias + residual
    gemm_fc_kernel<<<dim3(16, 128), thr>>>(o, fc_w, fc_b, x, out);
}

// round 2
// speedup vs baseline: 2.4063x; 2.4063x over previous
#include <cuda_runtime.h>
#include <math.h>
#include <stdint.h>

#define Bb 4
#define Ss 2048
#define Dd 1024
#define Hh 16
#define DK 64

static const size_t OUT_ELEMS  = (size_t)Bb * Ss * Dd;        // 8388608
static const size_t ATTN_ELEMS = (size_t)Bb * Hh * Ss * Ss;   // 268435456

// Scratch (device globals — allocation-free per harness rules)
__device__ float g_h[(size_t)Bb * Ss * Dd];
__device__ float g_q[(size_t)Bb * Hh * Ss * DK];
__device__ float g_k[(size_t)Bb * Hh * Ss * DK];
__device__ float g_vt[(size_t)Bb * Hh * DK * Ss];   // V transposed: [bh][d][s]
__device__ float g_o[(size_t)Bb * Ss * Dd];
__device__ float g_attn_scratch[(size_t)Bb * Hh * Ss * Ss];  // fallback

// ---------------------------------------------------------------------------
__device__ __forceinline__ float blockReduceSum(float val) {
    __shared__ float sh[32];
    int lane = threadIdx.x & 31, wid = threadIdx.x >> 5;
    #pragma unroll
    for (int o = 16; o; o >>= 1) val += __shfl_down_sync(0xffffffffu, val, o);
    if (lane == 0) sh[wid] = val;
    __syncthreads();
    val = (threadIdx.x < 8) ? sh[lane] : 0.0f;
    if (wid == 0) {
        #pragma unroll
        for (int o = 4; o; o >>= 1) val += __shfl_down_sync(0xffffffffu, val, o);
    }
    __syncthreads();
    return val;
}

__device__ __forceinline__ float blockReduceMax(float val) {
    __shared__ float sh[32];
    int lane = threadIdx.x & 31, wid = threadIdx.x >> 5;
    #pragma unroll
    for (int o = 16; o; o >>= 1) val = fmaxf(val, __shfl_down_sync(0xffffffffu, val, o));
    if (lane == 0) sh[wid] = val;
    __syncthreads();
    val = (threadIdx.x < 8) ? sh[lane] : -INFINITY;
    if (wid == 0) {
        #pragma unroll
        for (int o = 4; o; o >>= 1) val = fmaxf(val, __shfl_down_sync(0xffffffffu, val, o));
    }
    __syncthreads();
    return val;
}

// ---------------------------------------------------------------------------
// LayerNorm (reference quirk: unbiased variance /(D-1), denom = std + eps)
// ---------------------------------------------------------------------------
__global__ __launch_bounds__(256) void ln_kernel(
    const float* __restrict__ x, const float* __restrict__ a,
    const float* __restrict__ bvec, float* __restrict__ h)
{
    int row = blockIdx.x;
    const float4* xr = (const float4*)(x + (size_t)row * Dd);
    float4 v = xr[threadIdx.x];

    float s = blockReduceSum(v.x + v.y + v.z + v.w);
    __shared__ float mean_s, inv_s;
    if (threadIdx.x == 0) mean_s = s * (1.0f / Dd);
    __syncthreads();
    float mean = mean_s;

    float dx = v.x - mean, dy = v.y - mean, dz = v.z - mean, dw = v.w - mean;
    float sq = blockReduceSum(dx * dx + dy * dy + dz * dz + dw * dw);
    if (threadIdx.x == 0) inv_s = 1.0f / (sqrtf(sq * (1.0f / (Dd - 1))) + 1e-6f);
    __syncthreads();
    float inv = inv_s;

    float4 av = ((const float4*)a)[threadIdx.x];
    float4 bv = ((const float4*)bvec)[threadIdx.x];
    float4 o;
    o.x = av.x * dx * inv + bv.x;
    o.y = av.y * dy * inv + bv.y;
    o.z = av.z * dz * inv + bv.z;
    o.w = av.w * dw * inv + bv.w;
    ((float4*)(h + (size_t)row * Dd))[threadIdx.x] = o;
}

// ---------------------------------------------------------------------------
// Row softmax over 2048 elements (in place).
// ---------------------------------------------------------------------------
__global__ __launch_bounds__(256) void softmax_kernel(float* __restrict__ attn)
{
    float* p = attn + (size_t)blockIdx.x * Ss;
    float4 v0 = ((float4*)p)[threadIdx.x * 2];
    float4 v1 = ((float4*)p)[threadIdx.x * 2 + 1];

    float mx = fmaxf(fmaxf(fmaxf(v0.x, v0.y), fmaxf(v0.z, v0.w)),
                     fmaxf(fmaxf(v1.x, v1.y), fmaxf(v1.z, v1.w)));
    mx = blockReduceMax(mx);
    __shared__ float mx_s, inv_s;
    if (threadIdx.x == 0) mx_s = mx;
    __syncthreads();
    mx = mx_s;

    float4 e0, e1;
    e0.x = expf(v0.x - mx); e0.y = expf(v0.y - mx);
    e0.z = expf(v0.z - mx); e0.w = expf(v0.w - mx);
    e1.x = expf(v1.x - mx); e1.y = expf(v1.y - mx);
    e1.z = expf(v1.z - mx); e1.w = expf(v1.w - mx);

    float s = (e0.x + e0.y + e0.z + e0.w) + (e1.x + e1.y + e1.z + e1.w);
    s = blockReduceSum(s);
    if (threadIdx.x == 0) inv_s = 1.0f / s;
    __syncthreads();
    float inv = inv_s;

    e0.x *= inv; e0.y *= inv; e0.z *= inv; e0.w *= inv;
    e1.x *= inv; e1.y *= inv; e1.z *= inv; e1.w *= inv;
    ((float4*)p)[threadIdx.x * 2]     = e0;
    ((float4*)p)[threadIdx.x * 2 + 1] = e1;
}

// ---------------------------------------------------------------------------
// tf32 tensor-core GEMM:  C = A(MxK, K-contig) @ B(NxK, K-contig)^T
// Block: 128 x BN x 32.  8 warps (2x4).  Warp tile: 64 x BN/4.
// MODE 0: QK proj  -> scatter to [bh][s][d], + bias
// MODE 1: V proj   -> scatter to Vt [bh][d][s], + bias
// MODE 2: scores   -> *0.125, mask, write attn[bh] (A,B indexed by blockIdx.z)
// MODE 3: AV       -> write O[b][s][h*64+n] (A=attn[bh], B=Vt[bh])
// MODE 4: FC       -> + bias + residual x
// ---------------------------------------------------------------------------
__device__ __forceinline__ uint32_t f2tf32(float x) {
    uint32_t u;
    asm("cvt.rna.tf32.f32 %0, %1;" : "=r"(u) : "f"(x));
    return u;
}

template<int BN, int MODE>
__global__ __launch_bounds__(256, 2) void gemm_tc(
    const float* __restrict__ A, const float* __restrict__ B,
    const float* __restrict__ bias, const void* __restrict__ extra,
    float* __restrict__ C, int M, int N, int K)
{
    constexpr int BM = 128, BK = 32, PAD = BK + 4;
    constexpr int NF = BN / 32;   // n-fragments per warp
    __shared__ float As[BM][PAD];
    __shared__ float Bs[BN][PAD];

    int tid = threadIdx.x;
    int bz = blockIdx.z;

    if (MODE == 2) {
        A += (size_t)bz * Ss * DK;
        B += (size_t)bz * Ss * DK;
        C += (size_t)bz * Ss * Ss;
    }
    if (MODE == 3) {
        A += (size_t)bz * Ss * Ss;
        B += (size_t)bz * DK * Ss;
    }

    int m0 = blockIdx.y * BM;
    int n0 = blockIdx.x * BN;

    int lane = tid & 31, warp = tid >> 5;
    int wm = warp >> 2, wn = warp & 3;
    int row = lane >> 2, tcol = lane & 3;
    int mb = wm * 64;
    int nb = wn * (BN / 4);

    float acc[4][NF][4];
    #pragma unroll
    for (int i = 0; i < 4; i++)
        #pragma unroll
        for (int j = 0; j < NF; j++)
            #pragma unroll
            for (int r = 0; r < 4; r++) acc[i][j][r] = 0.0f;

    for (int k0 = 0; k0 < K; k0 += BK) {
        #pragma unroll
        for (int i = 0; i < 4; i++) {
            int lin = tid + i * 256;
            int r = lin >> 3, c = (lin & 7) * 4;
            float4 v = *(const float4*)(A + (size_t)(m0 + r) * K + k0 + c);
            v.x = __uint_as_float(f2tf32(v.x));
            v.y = __uint_as_float(f2tf32(v.y));
            v.z = __uint_as_float(f2tf32(v.z));
            v.w = __uint_as_float(f2tf32(v.w));
            *(float4*)&As[r][c] = v;
        }
        #pragma unroll
        for (int i = 0; i < NF; i++) {
            int lin = tid + i * 256;
            int r = lin >> 3, c = (lin & 7) * 4;
            float4 v = *(const float4*)(B + (size_t)(n0 + r) * K + k0 + c);
            v.x = __uint_as_float(f2tf32(v.x));
            v.y = __uint_as_float(f2tf32(v.y));
            v.z = __uint_as_float(f2tf32(v.z));
            v.w = __uint_as_float(f2tf32(v.w));
            *(float4*)&Bs[r][c] = v;
        }
        __syncthreads();

        #pragma unroll
        for (int ks = 0; ks < 4; ks++) {
            int kb = ks * 8;
            uint32_t a[4][4], b[NF][2];
            #pragma unroll
            for (int i = 0; i < 4; i++) {
                a[i][0] = __float_as_uint(As[mb + i * 16 + row][kb + tcol]);
                a[i][1] = __float_as_uint(As[mb + i * 16 + row + 8][kb + tcol]);
                a[i][2] = __float_as_uint(As[mb + i * 16 + row][kb + tcol + 4]);
                a[i][3] = __float_as_uint(As[mb + i * 16 + row + 8][kb + tcol + 4]);
            }
            #pragma unroll
            for (int j = 0; j < NF; j++) {
                b[j][0] = __float_as_uint(Bs[nb + j * 8 + row][kb + tcol]);
                b[j][1] = __float_as_uint(Bs[nb + j * 8 + row][kb + tcol + 4]);
            }
            #pragma unroll
            for (int i = 0; i < 4; i++)
                #pragma unroll
                for (int j = 0; j < NF; j++) {
                    asm volatile(
                        "mma.sync.aligned.m16n8k8.row.col.f32.tf32.tf32.f32 "
                        "{%0,%1,%2,%3}, {%4,%5,%6,%7}, {%8,%9}, {%0,%1,%2,%3};"
                        : "+f"(acc[i][j][0]), "+f"(acc[i][j][1]),
                          "+f"(acc[i][j][2]), "+f"(acc[i][j][3])
                        : "r"(a[i][0]), "r"(a[i][1]), "r"(a[i][2]), "r"(a[i][3]),
                          "r"(b[j][0]), "r"(b[j][1]));
                }
        }
        __syncthreads();
    }

    // Epilogue
    #pragma unroll
    for (int i = 0; i < 4; i++) {
        int gm = m0 + mb + i * 16 + row;
        #pragma unroll
        for (int j = 0; j < NF; j++) {
            int gn = n0 + nb + j * 8 + tcol * 2;
            #pragma unroll
            for (int half = 0; half < 2; half++) {
                int m = gm + half * 8;
                float v0 = acc[i][j][half * 2];
                float v1 = acc[i][j][half * 2 + 1];

                if (MODE == 0) {
                    int bi = m >> 11, s = m & (Ss - 1);
                    int hh = gn >> 6, d = gn & 63;
                    float2 o = make_float2(v0 + bias[gn], v1 + bias[gn + 1]);
                    *(float2*)&C[(((size_t)(bi * Hh + hh) * Ss) + s) * DK + d] = o;
                } else if (MODE == 1) {
                    int bi = m >> 11, s = m & (Ss - 1);
                    int hh = gn >> 6, d = gn & 63;
                    size_t base = ((size_t)(bi * Hh + hh) * DK + d) * Ss + s;
                    C[base]      = v0 + bias[gn];
                    C[base + Ss] = v1 + bias[gn + 1];
                } else if (MODE == 2) {
                    const int* mk = (const int*)extra + (size_t)(bz >> 4) * Ss * Ss;
                    size_t idx = (size_t)m * Ss + gn;
                    float s0 = v0 * 0.125f, s1 = v1 * 0.125f;
                    int2 mv = *(const int2*)&mk[idx];
                    if (mv.x == 0) s0 = -1e9f;
                    if (mv.y == 0) s1 = -1e9f;
                    *(float2*)&C[idx] = make_float2(s0, s1);
                } else if (MODE == 3) {
                    int bi = bz >> 4, hh = bz & 15;
                    size_t idx = ((size_t)bi * Ss + m) * Dd + hh * DK + gn;
                    *(float2*)&C[idx] = make_float2(v0, v1);
                } else {  // MODE 4
                    const float* xr = (const float*)extra;
                    size_t idx = (size_t)m * Dd + gn;
                    float2 xv = *(const float2*)&xr[idx];
                    *(float2*)&C[idx] = make_float2(v0 + bias[gn] + xv.x,
                                                    v1 + bias[gn + 1] + xv.y);
                }
            }
        }
    }
}

// ---------------------------------------------------------------------------
extern "C" void kernel_launch(void* const* d_in, const int* in_sizes, int n_in,
                              void* d_out, int out_size)
{
    const float* x    = (const float*)d_in[0];
    const int*   mask = (const int*)d_in[1];
    const float* ln_a = (const float*)d_in[2];
    const float* ln_b = (const float*)d_in[3];
    const float* wq_w = (const float*)d_in[4];
    const float* wq_b = (const float*)d_in[5];
    const float* wk_w = (const float*)d_in[6];
    const float* wk_b = (const float*)d_in[7];
    const float* wv_w = (const float*)d_in[8];
    const float* wv_b = (const float*)d_in[9];
    const float* fc_w = (const float*)d_in[10];
    const float* fc_b = (const float*)d_in[11];
    float* out = (float*)d_out;

    void *ph, *pq, *pk, *pvt, *po;
    cudaGetSymbolAddress(&ph, g_h);
    cudaGetSymbolAddress(&pq, g_q);
    cudaGetSymbolAddress(&pk, g_k);
    cudaGetSymbolAddress(&pvt, g_vt);
    cudaGetSymbolAddress(&po, g_o);
    float* h  = (float*)ph;
    float* q  = (float*)pq;
    float* k  = (float*)pk;
    float* vt = (float*)pvt;
    float* o  = (float*)po;

    float* attn;
    if ((size_t)out_size >= OUT_ELEMS + ATTN_ELEMS) {
        attn = out + OUT_ELEMS;
    } else {
        void* pa;
        cudaGetSymbolAddress(&pa, g_attn_scratch);
        attn = (float*)pa;
    }

    // 1. LayerNorm
    ln_kernel<<<Bb * Ss, 256>>>(x, ln_a, ln_b, h);

    // 2. QKV projections (tensor cores)
    gemm_tc<128, 0><<<dim3(8, 64, 1), 256>>>(h, wq_w, wq_b, nullptr, q,
                                             Bb * Ss, Dd, Dd);
    gemm_tc<128, 0><<<dim3(8, 64, 1), 256>>>(h, wk_w, wk_b, nullptr, k,
                                             Bb * Ss, Dd, Dd);
    gemm_tc<128, 1><<<dim3(8, 64, 1), 256>>>(h, wv_w, wv_b, nullptr, vt,
                                             Bb * Ss, Dd, Dd);

    // 3. Scores + scale + mask -> logits
    gemm_tc<128, 2><<<dim3(16, 16, Bb * Hh), 256>>>(q, k, nullptr, mask, attn,
                                                    Ss, Ss, DK);

    // 4. Softmax in place
    softmax_kernel<<<Bb * Hh * Ss, 256>>>(attn);

    // 5. attn @ V -> O
    gemm_tc<64, 3><<<dim3(1, 16, Bb * Hh), 256>>>(attn, vt, nullptr, nullptr, o,
                                                  Ss, DK, Ss);

    // 6. FC + bias + residual
    gemm_tc<128, 4><<<dim3(8, 64, 1), 256>>>(o, fc_w, fc_b, x, out,
                                             Bb * Ss, Dd, Dd);
}

// round 4
// speedup vs baseline: 2.4916x; 1.0355x over previous
#include <cuda_runtime.h>
#include <math.h>
#include <stdint.h>

#define Bb 4
#define Ss 2048
#define Dd 1024
#define Hh 16
#define DK 64

static const size_t OUT_ELEMS  = (size_t)Bb * Ss * Dd;        // 8388608
static const size_t ATTN_ELEMS = (size_t)Bb * Hh * Ss * Ss;   // 268435456

// Scratch (device globals — allocation-free per harness rules)
__device__ float g_h[(size_t)Bb * Ss * Dd];
__device__ float g_q[(size_t)Bb * Hh * Ss * DK];
__device__ float g_k[(size_t)Bb * Hh * Ss * DK];
__device__ float g_vt[(size_t)Bb * Hh * DK * Ss];   // V transposed: [bh][d][s]
__device__ float g_o[(size_t)Bb * Ss * Dd];
__device__ float g_wq[(size_t)Dd * Dd];
__device__ float g_wk[(size_t)Dd * Dd];
__device__ float g_wv[(size_t)Dd * Dd];
__device__ float g_wf[(size_t)Dd * Dd];
__device__ float g_pmax[(size_t)Bb * Hh * Ss * 16];
__device__ float g_psum[(size_t)Bb * Hh * Ss * 16];
__device__ float g_rmax[(size_t)Bb * Hh * Ss];
__device__ float g_rinv[(size_t)Bb * Hh * Ss];

// ---------------------------------------------------------------------------
__device__ __forceinline__ float f2tf32f(float x) {
    uint32_t u;
    asm("cvt.rna.tf32.f32 %0, %1;" : "=r"(u) : "f"(x));
    return __uint_as_float(u);
}

#define CP16(dst_u32, src_ptr) \
    asm volatile("cp.async.cg.shared.global [%0], [%1], 16;\n" :: "r"(dst_u32), "l"(src_ptr))
#define CP_COMMIT() asm volatile("cp.async.commit_group;\n" ::)
#define CP_WAIT(N)  asm volatile("cp.async.wait_group %0;\n" :: "n"(N))

__device__ __forceinline__ float blockReduceSum(float val) {
    __shared__ float sh[32];
    int lane = threadIdx.x & 31, wid = threadIdx.x >> 5;
    #pragma unroll
    for (int o = 16; o; o >>= 1) val += __shfl_down_sync(0xffffffffu, val, o);
    if (lane == 0) sh[wid] = val;
    __syncthreads();
    val = (threadIdx.x < 8) ? sh[lane] : 0.0f;
    if (wid == 0) {
        #pragma unroll
        for (int o = 4; o; o >>= 1) val += __shfl_down_sync(0xffffffffu, val, o);
    }
    __syncthreads();
    return val;
}

// ---------------------------------------------------------------------------
// LayerNorm — writes tf32-rounded h (h only feeds tensor-core GEMMs)
// ---------------------------------------------------------------------------
__global__ __launch_bounds__(256) void ln_kernel(
    const float* __restrict__ x, const float* __restrict__ a,
    const float* __restrict__ bvec, float* __restrict__ h)
{
    int row = blockIdx.x;
    const float4* xr = (const float4*)(x + (size_t)row * Dd);
    float4 v = xr[threadIdx.x];

    float s = blockReduceSum(v.x + v.y + v.z + v.w);
    __shared__ float mean_s, inv_s;
    if (threadIdx.x == 0) mean_s = s * (1.0f / Dd);
    __syncthreads();
    float mean = mean_s;

    float dx = v.x - mean, dy = v.y - mean, dz = v.z - mean, dw = v.w - mean;
    float sq = blockReduceSum(dx * dx + dy * dy + dz * dz + dw * dw);
    if (threadIdx.x == 0) inv_s = 1.0f / (sqrtf(sq * (1.0f / (Dd - 1))) + 1e-6f);
    __syncthreads();
    float inv = inv_s;

    float4 av = ((const float4*)a)[threadIdx.x];
    float4 bv = ((const float4*)bvec)[threadIdx.x];
    float4 o;
    o.x = f2tf32f(av.x * dx * inv + bv.x);
    o.y = f2tf32f(av.y * dy * inv + bv.y);
    o.z = f2tf32f(av.z * dz * inv + bv.z);
    o.w = f2tf32f(av.w * dw * inv + bv.w);
    ((float4*)(h + (size_t)row * Dd))[threadIdx.x] = o;
}

// ---------------------------------------------------------------------------
// Weight pre-rounding to tf32 (one elementwise pass per weight)
// ---------------------------------------------------------------------------
__global__ __launch_bounds__(256) void wround_kernel(
    const float* __restrict__ src, float* __restrict__ dst)
{
    int i = blockIdx.x * 256 + threadIdx.x;
    float4 v = ((const float4*)src)[i];
    v.x = f2tf32f(v.x); v.y = f2tf32f(v.y);
    v.z = f2tf32f(v.z); v.w = f2tf32f(v.w);
    ((float4*)dst)[i] = v;
}

// ---------------------------------------------------------------------------
// Projection / FC GEMM: C = A(MxK) @ B(NxK)^T, cp.async 2-stage pipeline.
// BM=128, BN=128, BK=32. 8 warps. Inputs pre-rounded to tf32 — no cvt here.
// MODE 0: QK proj  -> tf32(acc+bias) scattered to [bh][s][d]
// MODE 1: V proj   -> tf32(acc+bias) scattered to Vt [bh][d][s]
// MODE 4: FC       -> acc + bias + residual (full fp32 out)
// ---------------------------------------------------------------------------
template<int MODE>
__global__ __launch_bounds__(256, 2) void gemm_proj(
    const float* __restrict__ A, const float* __restrict__ B,
    const float* __restrict__ bias, const float* __restrict__ extra,
    float* __restrict__ C, int K)
{
    extern __shared__ __align__(16) float dsm[];
    // As: [2][128][36] at 0, Bs: [2][128][36] at 9216 floats
    const int ASTG = 4608, BOFF = 9216;
    uint32_t smem_u = (uint32_t)__cvta_generic_to_shared(dsm);

    int tid = threadIdx.x;
    int m0 = blockIdx.y * 128, n0 = blockIdx.x * 128;
    int lane = tid & 31, warp = tid >> 5;
    int wm = warp >> 2, wn = warp & 3;
    int row = lane >> 2, tig = lane & 3;
    int mb = wm * 64, nb = wn * 32;

    float acc[4][4][4] = {};

    int r_ld = tid >> 3;
    int c_ld = (tid & 7) * 4;

    auto loadTile = [&](int kt, int s) {
        int kof = kt * 32;
        #pragma unroll
        for (int i = 0; i < 4; i++) {
            int r = r_ld + i * 32;
            CP16(smem_u + (s * ASTG + r * 36 + c_ld) * 4,
                 A + (size_t)(m0 + r) * K + kof + c_ld);
        }
        #pragma unroll
        for (int i = 0; i < 4; i++) {
            int r = r_ld + i * 32;
            CP16(smem_u + (BOFF + s * ASTG + r * 36 + c_ld) * 4,
                 B + (size_t)(n0 + r) * K + kof + c_ld);
        }
    };

    int NT = K / 32;
    loadTile(0, 0);
    CP_COMMIT();

    for (int it = 0; it < NT; it++) {
        int s = it & 1;
        if (it + 1 < NT) {
            loadTile(it + 1, s ^ 1);
            CP_COMMIT();
            CP_WAIT(1);
        } else {
            CP_WAIT(0);
        }
        __syncthreads();

        const float* As = dsm + s * ASTG;
        const float* Bs = dsm + BOFF + s * ASTG;
        #pragma unroll
        for (int ks = 0; ks < 4; ks++) {
            int kb = ks * 8;
            uint32_t a[4][4], b[4][2];
            #pragma unroll
            for (int i = 0; i < 4; i++) {
                a[i][0] = __float_as_uint(As[(mb + i * 16 + row) * 36 + kb + tig]);
                a[i][1] = __float_as_uint(As[(mb + i * 16 + row + 8) * 36 + kb + tig]);
                a[i][2] = __float_as_uint(As[(mb + i * 16 + row) * 36 + kb + tig + 4]);
                a[i][3] = __float_as_uint(As[(mb + i * 16 + row + 8) * 36 + kb + tig + 4]);
            }
            #pragma unroll
            for (int j = 0; j < 4; j++) {
                b[j][0] = __float_as_uint(Bs[(nb + j * 8 + row) * 36 + kb + tig]);
                b[j][1] = __float_as_uint(Bs[(nb + j * 8 + row) * 36 + kb + tig + 4]);
            }
            #pragma unroll
            for (int i = 0; i < 4; i++)
                #pragma unroll
                for (int j = 0; j < 4; j++) {
                    asm volatile(
                        "mma.sync.aligned.m16n8k8.row.col.f32.tf32.tf32.f32 "
                        "{%0,%1,%2,%3}, {%4,%5,%6,%7}, {%8,%9}, {%0,%1,%2,%3};"
                        : "+f"(acc[i][j][0]), "+f"(acc[i][j][1]),
                          "+f"(acc[i][j][2]), "+f"(acc[i][j][3])
                        : "r"(a[i][0]), "r"(a[i][1]), "r"(a[i][2]), "r"(a[i][3]),
                          "r"(b[j][0]), "r"(b[j][1]));
                }
        }
        __syncthreads();
    }

    #pragma unroll
    for (int i = 0; i < 4; i++) {
        int gm = m0 + mb + i * 16 + row;
        #pragma unroll
        for (int j = 0; j < 4; j++) {
            int gn = n0 + nb + j * 8 + tig * 2;
            #pragma unroll
            for (int half = 0; half < 2; half++) {
                int m = gm + half * 8;
                float v0 = acc[i][j][half * 2];
                float v1 = acc[i][j][half * 2 + 1];
                if (MODE == 0) {
                    int bi = m >> 11, s2 = m & (Ss - 1);
                    int hh = gn >> 6, d = gn & 63;
                    float2 o = make_float2(f2tf32f(v0 + bias[gn]),
                                           f2tf32f(v1 + bias[gn + 1]));
                    *(float2*)&C[(((size_t)(bi * Hh + hh) * Ss) + s2) * DK + d] = o;
                } else if (MODE == 1) {
                    int bi = m >> 11, s2 = m & (Ss - 1);
                    int hh = gn >> 6, d = gn & 63;
                    size_t base = ((size_t)(bi * Hh + hh) * DK + d) * Ss + s2;
                    C[base]      = f2tf32f(v0 + bias[gn]);
                    C[base + Ss] = f2tf32f(v1 + bias[gn + 1]);
                } else {  // MODE 4: FC + bias + residual
                    size_t idx = (size_t)m * Dd + gn;
                    float2 xv = *(const float2*)&extra[idx];
                    *(float2*)&C[idx] = make_float2(v0 + bias[gn] + xv.x,
                                                    v1 + bias[gn + 1] + xv.y);
                }
            }
        }
    }
}

// ---------------------------------------------------------------------------
// Scores: logits = 0.125 * Q@K^T masked; writes logits + per-block row stats.
// BM=128, BN=128, K=64 (single smem tile). grid (16, 16, 64)
// ---------------------------------------------------------------------------
__global__ __launch_bounds__(256, 2) void scores_kernel(
    const float* __restrict__ Q, const float* __restrict__ Kk,
    const int* __restrict__ mask, float* __restrict__ attn,
    float* __restrict__ pmax, float* __restrict__ psum)
{
    extern __shared__ __align__(16) float dsm[];
    // Qs [128][68] at 0, Ks [128][68] at 8704, rmax_s [128][4] at 17408, rsum_s at 17920
    const int KOFF = 8704, RMO = 17408, RSO = 17920;
    uint32_t smem_u = (uint32_t)__cvta_generic_to_shared(dsm);

    int tid = threadIdx.x;
    int bz = blockIdx.z;
    const float* Qp = Q + (size_t)bz * Ss * DK;
    const float* Kp = Kk + (size_t)bz * Ss * DK;
    const int* mrow = mask + (size_t)(bz >> 4) * Ss * Ss;
    float* arow = attn + (size_t)bz * Ss * Ss;

    int m0 = blockIdx.y * 128, n0 = blockIdx.x * 128;
    int lane = tid & 31, warp = tid >> 5;
    int wm = warp >> 2, wn = warp & 3;
    int row = lane >> 2, tig = lane & 3;
    int mb = wm * 64, nb = wn * 32;

    // Load full 128x64 Q and K tiles via cp.async
    {
        int r = tid >> 4;
        int c = (tid & 15) * 4;
        #pragma unroll
        for (int i = 0; i < 8; i++) {
            int rr = r + i * 16;
            CP16(smem_u + (rr * 68 + c) * 4, Qp + (size_t)(m0 + rr) * DK + c);
        }
        #pragma unroll
        for (int i = 0; i < 8; i++) {
            int rr = r + i * 16;
            CP16(smem_u + (KOFF + rr * 68 + c) * 4, Kp + (size_t)(n0 + rr) * DK + c);
        }
        CP_COMMIT();
        CP_WAIT(0);
    }
    __syncthreads();

    float acc[4][4][4] = {};
    #pragma unroll
    for (int ks = 0; ks < 8; ks++) {
        int kb = ks * 8;
        uint32_t a[4][4], b[4][2];
        #pragma unroll
        for (int i = 0; i < 4; i++) {
            a[i][0] = __float_as_uint(dsm[(mb + i * 16 + row) * 68 + kb + tig]);
            a[i][1] = __float_as_uint(dsm[(mb + i * 16 + row + 8) * 68 + kb + tig]);
            a[i][2] = __float_as_uint(dsm[(mb + i * 16 + row) * 68 + kb + tig + 4]);
            a[i][3] = __float_as_uint(dsm[(mb + i * 16 + row + 8) * 68 + kb + tig + 4]);
        }
        #pragma unroll
        for (int j = 0; j < 4; j++) {
            b[j][0] = __float_as_uint(dsm[KOFF + (nb + j * 8 + row) * 68 + kb + tig]);
            b[j][1] = __float_as_uint(dsm[KOFF + (nb + j * 8 + row) * 68 + kb + tig + 4]);
        }
        #pragma unroll
        for (int i = 0; i < 4; i++)
            #pragma unroll
            for (int j = 0; j < 4; j++) {
                asm volatile(
                    "mma.sync.aligned.m16n8k8.row.col.f32.tf32.tf32.f32 "
                    "{%0,%1,%2,%3}, {%4,%5,%6,%7}, {%8,%9}, {%0,%1,%2,%3};"
                    : "+f"(acc[i][j][0]), "+f"(acc[i][j][1]),
                      "+f"(acc[i][j][2]), "+f"(acc[i][j][3])
                    : "r"(a[i][0]), "r"(a[i][1]), "r"(a[i][2]), "r"(a[i][3]),
                      "r"(b[j][0]), "r"(b[j][1]));
            }
    }
    __syncthreads();   // tiles dead; smem reused for reductions

    // Phase 1: mask + scale, write logits, per-warp row max
    #pragma unroll
    for (int i = 0; i < 4; i++) {
        #pragma unroll
        for (int half = 0; half < 2; half++) {
            int rloc = mb + i * 16 + half * 8 + row;
            int m = m0 + rloc;
            float mx = -INFINITY;
            #pragma unroll
            for (int j = 0; j < 4; j++) {
                int gn = n0 + nb + j * 8 + tig * 2;
                size_t idx = (size_t)m * Ss + gn;
                float s0 = acc[i][j][half * 2] * 0.125f;
                float s1 = acc[i][j][half * 2 + 1] * 0.125f;
                int2 mv = *(const int2*)&mrow[idx];
                if (mv.x == 0) s0 = -1e9f;
                if (mv.y == 0) s1 = -1e9f;
                acc[i][j][half * 2]     = s0;
                acc[i][j][half * 2 + 1] = s1;
                *(float2*)&arow[idx] = make_float2(s0, s1);
                mx = fmaxf(mx, fmaxf(s0, s1));
            }
            mx = fmaxf(mx, __shfl_xor_sync(0xffffffffu, mx, 1));
            mx = fmaxf(mx, __shfl_xor_sync(0xffffffffu, mx, 2));
            if (tig == 0) dsm[RMO + rloc * 4 + wn] = mx;
        }
    }
    __syncthreads();

    // Phase 2: block row max -> sumexp partials per warp
    #pragma unroll
    for (int i = 0; i < 4; i++) {
        #pragma unroll
        for (int half = 0; half < 2; half++) {
            int rloc = mb + i * 16 + half * 8 + row;
            float bm = fmaxf(fmaxf(dsm[RMO + rloc * 4], dsm[RMO + rloc * 4 + 1]),
                             fmaxf(dsm[RMO + rloc * 4 + 2], dsm[RMO + rloc * 4 + 3]));
            float se = 0.0f;
            #pragma unroll
            for (int j = 0; j < 4; j++) {
                se += expf(acc[i][j][half * 2] - bm);
                se += expf(acc[i][j][half * 2 + 1] - bm);
            }
            se += __shfl_xor_sync(0xffffffffu, se, 1);
            se += __shfl_xor_sync(0xffffffffu, se, 2);
            if (tig == 0) dsm[RSO + rloc * 4 + wn] = se;
        }
    }
    __syncthreads();

    // Phase 3: one thread per row writes (max, sum) partials
    if (tid < 128) {
        float bm = fmaxf(fmaxf(dsm[RMO + tid * 4], dsm[RMO + tid * 4 + 1]),
                         fmaxf(dsm[RMO + tid * 4 + 2], dsm[RMO + tid * 4 + 3]));
        float z = dsm[RSO + tid * 4] + dsm[RSO + tid * 4 + 1] +
                  dsm[RSO + tid * 4 + 2] + dsm[RSO + tid * 4 + 3];
        size_t ridx = ((size_t)bz * Ss + m0 + tid) * 16 + blockIdx.x;
        pmax[ridx] = bm;
        psum[ridx] = z;
    }
}

// ---------------------------------------------------------------------------
// Reduce 16 partials per row -> final (max, 1/Z)
// ---------------------------------------------------------------------------
__global__ __launch_bounds__(256) void stats_kernel(
    const float* __restrict__ pmax, const float* __restrict__ psum,
    float* __restrict__ rmax, float* __restrict__ rinv)
{
    int r = blockIdx.x * 256 + threadIdx.x;
    const float* pm = pmax + (size_t)r * 16;
    const float* ps = psum + (size_t)r * 16;
    float M = -INFINITY;
    #pragma unroll
    for (int t = 0; t < 16; t++) M = fmaxf(M, pm[t]);
    float Z = 0.0f;
    #pragma unroll
    for (int t = 0; t < 16; t++) Z += ps[t] * expf(pm[t] - M);
    rmax[r] = M;
    rinv[r] = 1.0f / Z;
}

// ---------------------------------------------------------------------------
// AV: reads logits, applies p=exp(l-m)*invZ, writes normalized attn (in place),
// and accumulates O = P @ Vt^T. BM=128, BN=64, BK=32. grid (16, 64)
// ---------------------------------------------------------------------------
__global__ __launch_bounds__(256, 2) void av_kernel(
    const float* __restrict__ Vt, const float* __restrict__ rmax,
    const float* __restrict__ rinv, float* __restrict__ attn,
    float* __restrict__ O)
{
    __shared__ __align__(16) float As[128][36];
    __shared__ __align__(16) float Bs[64][36];
    __shared__ float sm_m[128], sm_i[128];
    uint32_t bs_u = (uint32_t)__cvta_generic_to_shared(&Bs[0][0]);

    int tid = threadIdx.x;
    int bz = blockIdx.y;             // bh
    int m0 = blockIdx.x * 128;
    const float* Vp = Vt + (size_t)bz * DK * Ss;
    float* arow = attn + (size_t)bz * Ss * Ss;

    if (tid < 128) {
        sm_m[tid] = rmax[(size_t)bz * Ss + m0 + tid];
        sm_i[tid] = rinv[(size_t)bz * Ss + m0 + tid];
    }
    __syncthreads();

    int lane = tid & 31, warp = tid >> 5;
    int wm = warp >> 2, wn = warp & 3;
    int row = lane >> 2, tig = lane & 3;
    int mb = wm * 64, nb = wn * 16;

    int r_ld = tid >> 3;
    int c_ld = (tid & 7) * 4;

    float acc[4][2][4] = {};

    for (int k0 = 0; k0 < Ss; k0 += 32) {
        // B tile: Vt rows (d) 0..63, cols k0..k0+31 via cp.async
        #pragma unroll
        for (int i = 0; i < 2; i++) {
            int r = r_ld + i * 32;
            if (r < 64)
                CP16(bs_u + (r * 36 + c_ld) * 4, Vp + (size_t)r * Ss + k0 + c_ld);
        }
        CP_COMMIT();

        // A tile: logits -> p (write back normalized attn), store to smem
        #pragma unroll
        for (int i = 0; i < 4; i++) {
            int r = r_ld + i * 32;
            size_t gidx = (size_t)(m0 + r) * Ss + k0 + c_ld;
            float4 l = *(const float4*)&arow[gidx];
            float mrow_ = sm_m[r], irow_ = sm_i[r];
            float4 p;
            p.x = expf(l.x - mrow_) * irow_;
            p.y = expf(l.y - mrow_) * irow_;
            p.z = expf(l.z - mrow_) * irow_;
            p.w = expf(l.w - mrow_) * irow_;
            *(float4*)&arow[gidx] = p;
            As[r][c_ld]     = f2tf32f(p.x);
            As[r][c_ld + 1] = f2tf32f(p.y);
            As[r][c_ld + 2] = f2tf32f(p.z);
            As[r][c_ld + 3] = f2tf32f(p.w);
        }
        CP_WAIT(0);
        __syncthreads();

        #pragma unroll
        for (int ks = 0; ks < 4; ks++) {
            int kb = ks * 8;
            uint32_t a[4][4], b[2][2];
            #pragma unroll
            for (int i = 0; i < 4; i++) {
                a[i][0] = __float_as_uint(As[mb + i * 16 + row][kb + tig]);
                a[i][1] = __float_as_uint(As[mb + i * 16 + row + 8][kb + tig]);
                a[i][2] = __float_as_uint(As[mb + i * 16 + row][kb + tig + 4]);
                a[i][3] = __float_as_uint(As[mb + i * 16 + row + 8][kb + tig + 4]);
            }
            #pragma unroll
            for (int j = 0; j < 2; j++) {
                b[j][0] = __float_as_uint(Bs[nb + j * 8 + row][kb + tig]);
                b[j][1] = __float_as_uint(Bs[nb + j * 8 + row][kb + tig + 4]);
            }
            #pragma unroll
            for (int i = 0; i < 4; i++)
                #pragma unroll
                for (int j = 0; j < 2; j++) {
                    asm volatile(
                        "mma.sync.aligned.m16n8k8.row.col.f32.tf32.tf32.f32 "
                        "{%0,%1,%2,%3}, {%4,%5,%6,%7}, {%8,%9}, {%0,%1,%2,%3};"
                        : "+f"(acc[i][j][0]), "+f"(acc[i][j][1]),
                          "+f"(acc[i][j][2]), "+f"(acc[i][j][3])
                        : "r"(a[i][0]), "r"(a[i][1]), "r"(a[i][2]), "r"(a[i][3]),
                          "r"(b[j][0]), "r"(b[j][1]));
                }
        }
        __syncthreads();
    }

    int bi = bz >> 4, hh = bz & 15;
    #pragma unroll
    for (int i = 0; i < 4; i++) {
        int gm = m0 + mb + i * 16 + row;
        #pragma unroll
        for (int j = 0; j < 2; j++) {
            int gn = nb + j * 8 + tig * 2;
            #pragma unroll
            for (int half = 0; half < 2; half++) {
                int m = gm + half * 8;
                size_t idx = ((size_t)bi * Ss + m) * Dd + hh * DK + gn;
                *(float2*)&O[idx] = make_float2(
                    f2tf32f(acc[i][j][half * 2]),
                    f2tf32f(acc[i][j][half * 2 + 1]));
            }
        }
    }
}

// ---------------------------------------------------------------------------
extern "C" void kernel_launch(void* const* d_in, const int* in_sizes, int n_in,
                              void* d_out, int out_size)
{
    const float* x    = (const float*)d_in[0];
    const int*   mask = (const int*)d_in[1];
    const float* ln_a = (const float*)d_in[2];
    const float* ln_b = (const float*)d_in[3];
    const float* wq_w = (const float*)d_in[4];
    const float* wq_b = (const float*)d_in[5];
    const float* wk_w = (const float*)d_in[6];
    const float* wk_b = (const float*)d_in[7];
    const float* wv_w = (const float*)d_in[8];
    const float* wv_b = (const float*)d_in[9];
    const float* fc_w = (const float*)d_in[10];
    const float* fc_b = (const float*)d_in[11];
    float* out = (float*)d_out;

    void *ph, *pq, *pk, *pvt, *po, *pwq, *pwk, *pwv, *pwf, *ppm, *pps, *prm, *pri;
    cudaGetSymbolAddress(&ph,  g_h);
    cudaGetSymbolAddress(&pq,  g_q);
    cudaGetSymbolAddress(&pk,  g_k);
    cudaGetSymbolAddress(&pvt, g_vt);
    cudaGetSymbolAddress(&po,  g_o);
    cudaGetSymbolAddress(&pwq, g_wq);
    cudaGetSymbolAddress(&pwk, g_wk);
    cudaGetSymbolAddress(&pwv, g_wv);
    cudaGetSymbolAddress(&pwf, g_wf);
    cudaGetSymbolAddress(&ppm, g_pmax);
    cudaGetSymbolAddress(&pps, g_psum);
    cudaGetSymbolAddress(&prm, g_rmax);
    cudaGetSymbolAddress(&pri, g_rinv);
    float* h   = (float*)ph;
    float* q   = (float*)pq;
    float* k   = (float*)pk;
    float* vt  = (float*)pvt;
    float* o   = (float*)po;
    float* wqr = (float*)pwq;
    float* wkr = (float*)pwk;
    float* wvr = (float*)pwv;
    float* wfr = (float*)pwf;

    float* attn = out + OUT_ELEMS;

    const int DSM = 73728;
    cudaFuncSetAttribute(gemm_proj<0>, cudaFuncAttributeMaxDynamicSharedMemorySize, DSM);
    cudaFuncSetAttribute(gemm_proj<1>, cudaFuncAttributeMaxDynamicSharedMemorySize, DSM);
    cudaFuncSetAttribute(gemm_proj<4>, cudaFuncAttributeMaxDynamicSharedMemorySize, DSM);
    cudaFuncSetAttribute(scores_kernel, cudaFuncAttributeMaxDynamicSharedMemorySize, DSM);

    // 0. Pre-round weights to tf32
    wround_kernel<<<1024, 256>>>(wq_w, wqr);
    wround_kernel<<<1024, 256>>>(wk_w, wkr);
    wround_kernel<<<1024, 256>>>(wv_w, wvr);
    wround_kernel<<<1024, 256>>>(fc_w, wfr);

    // 1. LayerNorm (tf32-rounded output)
    ln_kernel<<<Bb * Ss, 256>>>(x, ln_a, ln_b, h);

    // 2. QKV projections
    gemm_proj<0><<<dim3(8, 64), 256, DSM>>>(h, wqr, wq_b, nullptr, q, Dd);
    gemm_proj<0><<<dim3(8, 64), 256, DSM>>>(h, wkr, wk_b, nullptr, k, Dd);
    gemm_proj<1><<<dim3(8, 64), 256, DSM>>>(h, wvr, wv_b, nullptr, vt, Dd);

    // 3. Scores + mask + per-block softmax partials
    scores_kernel<<<dim3(16, 16, Bb * Hh), 256, DSM>>>(
        q, k, mask, attn, (float*)ppm, (float*)pps);

    // 4. Finalize per-row (max, 1/Z)
    stats_kernel<<<(Bb * Hh * Ss) / 256, 256>>>(
        (float*)ppm, (float*)pps, (float*)prm, (float*)pri);

    // 5. AV: normalize attn in place + P @ V
    av_kernel<<<dim3(16, Bb * Hh), 256>>>(vt, (float*)prm, (float*)pri, attn, o);

    // 6. FC + bias + residual
    gemm_proj<4><<<dim3(8, 64), 256, DSM>>>(o, wfr, fc_b, x, out, Dd);
}

// round 5
// speedup vs baseline: 2.7407x; 1.1000x over previous
#include <cuda_runtime.h>
#include <math.h>
#include <stdint.h>

#define Bb 4
#define Ss 2048
#define Dd 1024
#define Hh 16
#define DK 64

static const size_t OUT_ELEMS  = (size_t)Bb * Ss * Dd;        // 8388608

// Scratch (device globals — allocation-free per harness rules)
__device__ float g_h[(size_t)Bb * Ss * Dd];
__device__ float g_q[(size_t)Bb * Hh * Ss * DK];
__device__ float g_k[(size_t)Bb * Hh * Ss * DK];
__device__ float g_vt[(size_t)Bb * Hh * DK * Ss];   // V transposed: [bh][d][s]
__device__ float g_o[(size_t)Bb * Ss * Dd];
__device__ float g_wq[(size_t)Dd * Dd];
__device__ float g_wk[(size_t)Dd * Dd];
__device__ float g_wv[(size_t)Dd * Dd];
__device__ float g_wf[(size_t)Dd * Dd];

// ---------------------------------------------------------------------------
__device__ __forceinline__ float f2tf32f(float x) {
    uint32_t u;
    asm("cvt.rna.tf32.f32 %0, %1;" : "=r"(u) : "f"(x));
    return __uint_as_float(u);
}

#define CP16(dst_u32, src_ptr) \
    asm volatile("cp.async.cg.shared.global [%0], [%1], 16;\n" :: "r"(dst_u32), "l"(src_ptr))
#define CP_COMMIT() asm volatile("cp.async.commit_group;\n" ::)
#define CP_WAIT(N)  asm volatile("cp.async.wait_group %0;\n" :: "n"(N))

#define MMA_TF32(acc, a, b) \
    asm volatile( \
        "mma.sync.aligned.m16n8k8.row.col.f32.tf32.tf32.f32 " \
        "{%0,%1,%2,%3}, {%4,%5,%6,%7}, {%8,%9}, {%0,%1,%2,%3};" \
        : "+f"(acc[0]), "+f"(acc[1]), "+f"(acc[2]), "+f"(acc[3]) \
        : "r"(a[0]), "r"(a[1]), "r"(a[2]), "r"(a[3]), "r"(b[0]), "r"(b[1]))

__device__ __forceinline__ float blockReduceSum(float val) {
    __shared__ float sh[32];
    int lane = threadIdx.x & 31, wid = threadIdx.x >> 5;
    #pragma unroll
    for (int o = 16; o; o >>= 1) val += __shfl_down_sync(0xffffffffu, val, o);
    if (lane == 0) sh[wid] = val;
    __syncthreads();
    val = (threadIdx.x < 8) ? sh[lane] : 0.0f;
    if (wid == 0) {
        #pragma unroll
        for (int o = 4; o; o >>= 1) val += __shfl_down_sync(0xffffffffu, val, o);
    }
    __syncthreads();
    return val;
}

// ---------------------------------------------------------------------------
// LayerNorm — writes tf32-rounded h
// ---------------------------------------------------------------------------
__global__ __launch_bounds__(256) void ln_kernel(
    const float* __restrict__ x, const float* __restrict__ a,
    const float* __restrict__ bvec, float* __restrict__ h)
{
    int row = blockIdx.x;
    const float4* xr = (const float4*)(x + (size_t)row * Dd);
    float4 v = xr[threadIdx.x];

    float s = blockReduceSum(v.x + v.y + v.z + v.w);
    __shared__ float mean_s, inv_s;
    if (threadIdx.x == 0) mean_s = s * (1.0f / Dd);
    __syncthreads();
    float mean = mean_s;

    float dx = v.x - mean, dy = v.y - mean, dz = v.z - mean, dw = v.w - mean;
    float sq = blockReduceSum(dx * dx + dy * dy + dz * dz + dw * dw);
    if (threadIdx.x == 0) inv_s = 1.0f / (sqrtf(sq * (1.0f / (Dd - 1))) + 1e-6f);
    __syncthreads();
    float inv = inv_s;

    float4 av = ((const float4*)a)[threadIdx.x];
    float4 bv = ((const float4*)bvec)[threadIdx.x];
    float4 o;
    o.x = f2tf32f(av.x * dx * inv + bv.x);
    o.y = f2tf32f(av.y * dy * inv + bv.y);
    o.z = f2tf32f(av.z * dz * inv + bv.z);
    o.w = f2tf32f(av.w * dw * inv + bv.w);
    ((float4*)(h + (size_t)row * Dd))[threadIdx.x] = o;
}

__global__ __launch_bounds__(256) void wround_kernel(
    const float* __restrict__ src, float* __restrict__ dst)
{
    int i = blockIdx.x * 256 + threadIdx.x;
    float4 v = ((const float4*)src)[i];
    v.x = f2tf32f(v.x); v.y = f2tf32f(v.y);
    v.z = f2tf32f(v.z); v.w = f2tf32f(v.w);
    ((float4*)dst)[i] = v;
}

// ---------------------------------------------------------------------------
// Combined QKV projection GEMM. blockIdx.z selects {Q,K,V}.
// C = h(Mx1024) @ W(1024x1024)^T + bias; Q/K scatter [bh][s][d], V -> Vt.
// ---------------------------------------------------------------------------
__global__ __launch_bounds__(256, 2) void gemm_qkv(
    const float* __restrict__ A,
    const float* __restrict__ wq, const float* __restrict__ wk,
    const float* __restrict__ wv,
    const float* __restrict__ bq, const float* __restrict__ bk,
    const float* __restrict__ bv,
    float* __restrict__ q, float* __restrict__ k, float* __restrict__ vt)
{
    extern __shared__ __align__(16) float dsm[];
    const int ASTG = 4608, BOFF = 9216;
    uint32_t smem_u = (uint32_t)__cvta_generic_to_shared(dsm);

    int z = blockIdx.z;
    const float* B    = (z == 0) ? wq : (z == 1) ? wk : wv;
    const float* bias = (z == 0) ? bq : (z == 1) ? bk : bv;

    const int K = Dd;
    int tid = threadIdx.x;
    int m0 = blockIdx.y * 128, n0 = blockIdx.x * 128;
    int lane = tid & 31, warp = tid >> 5;
    int wm = warp >> 2, wn = warp & 3;
    int row = lane >> 2, tig = lane & 3;
    int mb = wm * 64, nb = wn * 32;

    float acc[4][4][4] = {};
    int r_ld = tid >> 3;
    int c_ld = (tid & 7) * 4;

    auto loadTile = [&](int kt, int s) {
        int kof = kt * 32;
        #pragma unroll
        for (int i = 0; i < 4; i++) {
            int r = r_ld + i * 32;
            CP16(smem_u + (s * ASTG + r * 36 + c_ld) * 4,
                 A + (size_t)(m0 + r) * K + kof + c_ld);
        }
        #pragma unroll
        for (int i = 0; i < 4; i++) {
            int r = r_ld + i * 32;
            CP16(smem_u + (BOFF + s * ASTG + r * 36 + c_ld) * 4,
                 B + (size_t)(n0 + r) * K + kof + c_ld);
        }
    };

    loadTile(0, 0);
    CP_COMMIT();

    for (int it = 0; it < 32; it++) {
        int s = it & 1;
        if (it + 1 < 32) {
            loadTile(it + 1, s ^ 1);
            CP_COMMIT();
            CP_WAIT(1);
        } else {
            CP_WAIT(0);
        }
        __syncthreads();

        const float* As = dsm + s * ASTG;
        const float* Bs = dsm + BOFF + s * ASTG;
        #pragma unroll
        for (int ks = 0; ks < 4; ks++) {
            int kb = ks * 8;
            uint32_t a[4][4], b[4][2];
            #pragma unroll
            for (int i = 0; i < 4; i++) {
                a[i][0] = __float_as_uint(As[(mb + i * 16 + row) * 36 + kb + tig]);
                a[i][1] = __float_as_uint(As[(mb + i * 16 + row + 8) * 36 + kb + tig]);
                a[i][2] = __float_as_uint(As[(mb + i * 16 + row) * 36 + kb + tig + 4]);
                a[i][3] = __float_as_uint(As[(mb + i * 16 + row + 8) * 36 + kb + tig + 4]);
            }
            #pragma unroll
            for (int j = 0; j < 4; j++) {
                b[j][0] = __float_as_uint(Bs[(nb + j * 8 + row) * 36 + kb + tig]);
                b[j][1] = __float_as_uint(Bs[(nb + j * 8 + row) * 36 + kb + tig + 4]);
            }
            #pragma unroll
            for (int i = 0; i < 4; i++)
                #pragma unroll
                for (int j = 0; j < 4; j++)
                    MMA_TF32(acc[i][j], a[i], b[j]);
        }
        __syncthreads();
    }

    #pragma unroll
    for (int i = 0; i < 4; i++) {
        int gm = m0 + mb + i * 16 + row;
        #pragma unroll
        for (int j = 0; j < 4; j++) {
            int gn = n0 + nb + j * 8 + tig * 2;
            #pragma unroll
            for (int half = 0; half < 2; half++) {
                int m = gm + half * 8;
                float v0 = f2tf32f(acc[i][j][half * 2] + bias[gn]);
                float v1 = f2tf32f(acc[i][j][half * 2 + 1] + bias[gn + 1]);
                int bi = m >> 11, s2 = m & (Ss - 1);
                int hh = gn >> 6, d = gn & 63;
                if (z < 2) {
                    float* C = (z == 0) ? q : k;
                    *(float2*)&C[(((size_t)(bi * Hh + hh) * Ss) + s2) * DK + d] =
                        make_float2(v0, v1);
                } else {
                    size_t base = ((size_t)(bi * Hh + hh) * DK + d) * Ss + s2;
                    vt[base]      = v0;
                    vt[base + Ss] = v1;
                }
            }
        }
    }
}

// ---------------------------------------------------------------------------
// FC GEMM + bias + residual
// ---------------------------------------------------------------------------
__global__ __launch_bounds__(256, 2) void gemm_fc(
    const float* __restrict__ A, const float* __restrict__ B,
    const float* __restrict__ bias, const float* __restrict__ xres,
    float* __restrict__ C)
{
    extern __shared__ __align__(16) float dsm[];
    const int ASTG = 4608, BOFF = 9216;
    uint32_t smem_u = (uint32_t)__cvta_generic_to_shared(dsm);

    const int K = Dd;
    int tid = threadIdx.x;
    int m0 = blockIdx.y * 128, n0 = blockIdx.x * 128;
    int lane = tid & 31, warp = tid >> 5;
    int wm = warp >> 2, wn = warp & 3;
    int row = lane >> 2, tig = lane & 3;
    int mb = wm * 64, nb = wn * 32;

    float acc[4][4][4] = {};
    int r_ld = tid >> 3;
    int c_ld = (tid & 7) * 4;

    auto loadTile = [&](int kt, int s) {
        int kof = kt * 32;
        #pragma unroll
        for (int i = 0; i < 4; i++) {
            int r = r_ld + i * 32;
            CP16(smem_u + (s * ASTG + r * 36 + c_ld) * 4,
                 A + (size_t)(m0 + r) * K + kof + c_ld);
        }
        #pragma unroll
        for (int i = 0; i < 4; i++) {
            int r = r_ld + i * 32;
            CP16(smem_u + (BOFF + s * ASTG + r * 36 + c_ld) * 4,
                 B + (size_t)(n0 + r) * K + kof + c_ld);
        }
    };

    loadTile(0, 0);
    CP_COMMIT();

    for (int it = 0; it < 32; it++) {
        int s = it & 1;
        if (it + 1 < 32) {
            loadTile(it + 1, s ^ 1);
            CP_COMMIT();
            CP_WAIT(1);
        } else {
            CP_WAIT(0);
        }
        __syncthreads();

        const float* As = dsm + s * ASTG;
        const float* Bs = dsm + BOFF + s * ASTG;
        #pragma unroll
        for (int ks = 0; ks < 4; ks++) {
            int kb = ks * 8;
            uint32_t a[4][4], b[4][2];
            #pragma unroll
            for (int i = 0; i < 4; i++) {
                a[i][0] = __float_as_uint(As[(mb + i * 16 + row) * 36 + kb + tig]);
                a[i][1] = __float_as_uint(As[(mb + i * 16 + row + 8) * 36 + kb + tig]);
                a[i][2] = __float_as_uint(As[(mb + i * 16 + row) * 36 + kb + tig + 4]);
                a[i][3] = __float_as_uint(As[(mb + i * 16 + row + 8) * 36 + kb + tig + 4]);
            }
            #pragma unroll
            for (int j = 0; j < 4; j++) {
                b[j][0] = __float_as_uint(Bs[(nb + j * 8 + row) * 36 + kb + tig]);
                b[j][1] = __float_as_uint(Bs[(nb + j * 8 + row) * 36 + kb + tig + 4]);
            }
            #pragma unroll
            for (int i = 0; i < 4; i++)
                #pragma unroll
                for (int j = 0; j < 4; j++)
                    MMA_TF32(acc[i][j], a[i], b[j]);
        }
        __syncthreads();
    }

    #pragma unroll
    for (int i = 0; i < 4; i++) {
        int gm = m0 + mb + i * 16 + row;
        #pragma unroll
        for (int j = 0; j < 4; j++) {
            int gn = n0 + nb + j * 8 + tig * 2;
            #pragma unroll
            for (int half = 0; half < 2; half++) {
                int m = gm + half * 8;
                size_t idx = (size_t)m * Dd + gn;
                float2 xv = *(const float2*)&xres[idx];
                *(float2*)&C[idx] = make_float2(
                    acc[i][j][half * 2] + bias[gn] + xv.x,
                    acc[i][j][half * 2 + 1] + bias[gn + 1] + xv.y);
            }
        }
    }
}

// ---------------------------------------------------------------------------
// Fused attention: per (128-row strip, head):
//  pass 1: S = 0.125*Q@K^T masked -> write logits (stay in L2) + online (m,s)
//  pass 2: re-read own logits (L2), p = exp(l-M)*invZ -> write attn, O += P@V
// ---------------------------------------------------------------------------
__global__ __launch_bounds__(256, 2) void attn_fused(
    const float* __restrict__ Q, const float* __restrict__ Kk,
    const float* __restrict__ Vt, const int* __restrict__ mask,
    float* __restrict__ attn, float* __restrict__ O)
{
    extern __shared__ __align__(16) float dsm[];
    // floats: Qs[128][68]@0, Ks[2][128][68]@8704 (pass2 overlay: As[128][36]@8704,
    // Bs[64][36]@13312), ws_m[128][4]@26112, ws_s[128][4]@26624,
    // sm_m[128]@27136, sm_i[128]@27264  (total 27392 floats)
    const int KS = 8704, ASO = 8704, BSO = 13312;
    const int WSM = 26112, WSS = 26624, SMM = 27136, SMI = 27264;
    uint32_t smem_u = (uint32_t)__cvta_generic_to_shared(dsm);

    int tid = threadIdx.x;
    int bz = blockIdx.y;               // bh
    int m0 = blockIdx.x * 128;
    const float* Qp = Q  + (size_t)bz * Ss * DK;
    const float* Kp = Kk + (size_t)bz * Ss * DK;
    const float* Vp = Vt + (size_t)bz * DK * Ss;
    const int* mrow = mask + (size_t)(bz >> 4) * Ss * Ss;
    float* arow = attn + (size_t)bz * Ss * Ss;

    int lane = tid & 31, warp = tid >> 5;
    int wm = warp >> 2, wn = warp & 3;
    int row = lane >> 2, tig = lane & 3;
    int mb = wm * 64;

    // ---- load Q strip + first K tile ----
    {
        int r = tid >> 1;                 // 0..127
        int c = (tid & 1) * 32;           // two 32-float halves? no: 64 cols = 16 f4
        (void)c;
    }
    {
        // 128x64: 2048 float4 chunks, 8 per thread
        #pragma unroll
        for (int i = 0; i < 8; i++) {
            int idx = tid + i * 256;
            int r = idx >> 4, c = (idx & 15) * 4;
            CP16(smem_u + (r * 68 + c) * 4, Qp + (size_t)(m0 + r) * DK + c);
        }
        #pragma unroll
        for (int i = 0; i < 8; i++) {
            int idx = tid + i * 256;
            int r = idx >> 4, c = (idx & 15) * 4;
            CP16(smem_u + (KS + r * 68 + c) * 4, Kp + (size_t)r * DK + c);
        }
        CP_COMMIT();
    }

    float mrun[8], srun[8];
    #pragma unroll
    for (int s8 = 0; s8 < 8; s8++) { mrun[s8] = -INFINITY; srun[s8] = 0.0f; }

    // ---- pass 1 ----
    for (int kt = 0; kt < 16; kt++) {
        CP_WAIT(0);
        __syncthreads();

        const float* Ksb = dsm + KS + (kt & 1) * 8704;
        float acc[4][4][4] = {};
        #pragma unroll
        for (int ks = 0; ks < 8; ks++) {
            int kb = ks * 8;
            uint32_t a[4][4], b[4][2];
            #pragma unroll
            for (int i = 0; i < 4; i++) {
                a[i][0] = __float_as_uint(dsm[(mb + i * 16 + row) * 68 + kb + tig]);
                a[i][1] = __float_as_uint(dsm[(mb + i * 16 + row + 8) * 68 + kb + tig]);
                a[i][2] = __float_as_uint(dsm[(mb + i * 16 + row) * 68 + kb + tig + 4]);
                a[i][3] = __float_as_uint(dsm[(mb + i * 16 + row + 8) * 68 + kb + tig + 4]);
            }
            #pragma unroll
            for (int j = 0; j < 4; j++) {
                b[j][0] = __float_as_uint(Ksb[(wn * 32 + j * 8 + row) * 68 + kb + tig]);
                b[j][1] = __float_as_uint(Ksb[(wn * 32 + j * 8 + row) * 68 + kb + tig + 4]);
            }
            #pragma unroll
            for (int i = 0; i < 4; i++)
                #pragma unroll
                for (int j = 0; j < 4; j++)
                    MMA_TF32(acc[i][j], a[i], b[j]);
        }

        if (kt + 1 < 16) {
            int buf = (kt + 1) & 1;
            #pragma unroll
            for (int i = 0; i < 8; i++) {
                int idx = tid + i * 256;
                int r = idx >> 4, c = (idx & 15) * 4;
                CP16(smem_u + (KS + buf * 8704 + r * 68 + c) * 4,
                     Kp + (size_t)((kt + 1) * 128 + r) * DK + c);
            }
            CP_COMMIT();
        }

        // epilogue: mask+scale, write logits, online (m,s)
        #pragma unroll
        for (int i = 0; i < 4; i++) {
            #pragma unroll
            for (int half = 0; half < 2; half++) {
                int s8 = i * 2 + half;
                int m = m0 + mb + i * 16 + half * 8 + row;
                float vals[8];
                float lmax = -INFINITY;
                #pragma unroll
                for (int j = 0; j < 4; j++) {
                    int gn = kt * 128 + wn * 32 + j * 8 + tig * 2;
                    size_t idx = (size_t)m * Ss + gn;
                    float s0 = acc[i][j][half * 2] * 0.125f;
                    float s1 = acc[i][j][half * 2 + 1] * 0.125f;
                    int2 mv = *(const int2*)&mrow[idx];
                    if (mv.x == 0) s0 = -1e9f;
                    if (mv.y == 0) s1 = -1e9f;
                    *(float2*)&arow[idx] = make_float2(s0, s1);
                    vals[j * 2] = s0; vals[j * 2 + 1] = s1;
                    lmax = fmaxf(lmax, fmaxf(s0, s1));
                }
                float nm = fmaxf(mrun[s8], lmax);
                float se = 0.0f;
                #pragma unroll
                for (int j = 0; j < 8; j++) se += __expf(vals[j] - nm);
                srun[s8] = srun[s8] * __expf(mrun[s8] - nm) + se;
                mrun[s8] = nm;
            }
        }
    }

    // ---- stats merge: intra-warp (tig lanes), then cross-warp (wn) ----
    #pragma unroll
    for (int s8 = 0; s8 < 8; s8++) {
        #pragma unroll
        for (int d = 1; d <= 2; d <<= 1) {
            float om = __shfl_xor_sync(0xffffffffu, mrun[s8], d);
            float os = __shfl_xor_sync(0xffffffffu, srun[s8], d);
            float nm = fmaxf(mrun[s8], om);
            srun[s8] = srun[s8] * __expf(mrun[s8] - nm) + os * __expf(om - nm);
            mrun[s8] = nm;
        }
    }
    if (tig == 0) {
        #pragma unroll
        for (int s8 = 0; s8 < 8; s8++) {
            int rloc = mb + (s8 >> 1) * 16 + (s8 & 1) * 8 + row;
            dsm[WSM + rloc * 4 + wn] = mrun[s8];
            dsm[WSS + rloc * 4 + wn] = srun[s8];
        }
    }
    __syncthreads();
    if (tid < 128) {
        float M = -INFINITY;
        #pragma unroll
        for (int w = 0; w < 4; w++) M = fmaxf(M, dsm[WSM + tid * 4 + w]);
        float Z = 0.0f;
        #pragma unroll
        for (int w = 0; w < 4; w++)
            Z += dsm[WSS + tid * 4 + w] * __expf(dsm[WSM + tid * 4 + w] - M);
        dsm[SMM + tid] = M;
        dsm[SMI + tid] = 1.0f / Z;
    }
    __syncthreads();

    // ---- pass 2: normalize + P@V ----
    float* As = dsm + ASO;   // [128][36]
    float* Bs = dsm + BSO;   // [64][36]
    int r_ld = tid >> 3;
    int c_ld = (tid & 7) * 4;
    int nb2 = wn * 16;

    float oacc[4][2][4] = {};

    for (int k0 = 0; k0 < Ss; k0 += 32) {
        #pragma unroll
        for (int i = 0; i < 2; i++) {
            int r = r_ld + i * 32;
            if (r < 64)
                CP16(smem_u + (BSO + r * 36 + c_ld) * 4, Vp + (size_t)r * Ss + k0 + c_ld);
        }
        CP_COMMIT();

        #pragma unroll
        for (int i = 0; i < 4; i++) {
            int r = r_ld + i * 32;
            size_t gidx = (size_t)(m0 + r) * Ss + k0 + c_ld;
            float4 l = *(const float4*)&arow[gidx];
            float M = dsm[SMM + r], inv = dsm[SMI + r];
            float4 p;
            p.x = __expf(l.x - M) * inv;
            p.y = __expf(l.y - M) * inv;
            p.z = __expf(l.z - M) * inv;
            p.w = __expf(l.w - M) * inv;
            *(float4*)&arow[gidx] = p;
            As[r * 36 + c_ld]     = f2tf32f(p.x);
            As[r * 36 + c_ld + 1] = f2tf32f(p.y);
            As[r * 36 + c_ld + 2] = f2tf32f(p.z);
            As[r * 36 + c_ld + 3] = f2tf32f(p.w);
        }
        CP_WAIT(0);
        __syncthreads();

        #pragma unroll
        for (int ks = 0; ks < 4; ks++) {
            int kb = ks * 8;
            uint32_t a[4][4], b[2][2];
            #pragma unroll
            for (int i = 0; i < 4; i++) {
                a[i][0] = __float_as_uint(As[(mb + i * 16 + row) * 36 + kb + tig]);
                a[i][1] = __float_as_uint(As[(mb + i * 16 + row + 8) * 36 + kb + tig]);
                a[i][2] = __float_as_uint(As[(mb + i * 16 + row) * 36 + kb + tig + 4]);
                a[i][3] = __float_as_uint(As[(mb + i * 16 + row + 8) * 36 + kb + tig + 4]);
            }
            #pragma unroll
            for (int j = 0; j < 2; j++) {
                b[j][0] = __float_as_uint(Bs[(nb2 + j * 8 + row) * 36 + kb + tig]);
                b[j][1] = __float_as_uint(Bs[(nb2 + j * 8 + row) * 36 + kb + tig + 4]);
            }
            #pragma unroll
            for (int i = 0; i < 4; i++)
                #pragma unroll
                for (int j = 0; j < 2; j++)
                    MMA_TF32(oacc[i][j], a[i], b[j]);
        }
        __syncthreads();
    }

    int bi = bz >> 4, hh = bz & 15;
    #pragma unroll
    for (int i = 0; i < 4; i++) {
        int gm = m0 + mb + i * 16 + row;
        #pragma unroll
        for (int j = 0; j < 2; j++) {
            int gn = nb2 + j * 8 + tig * 2;
            #pragma unroll
            for (int half = 0; half < 2; half++) {
                int m = gm + half * 8;
                size_t idx = ((size_t)bi * Ss + m) * Dd + hh * DK + gn;
                *(float2*)&O[idx] = make_float2(
                    f2tf32f(oacc[i][j][half * 2]),
                    f2tf32f(oacc[i][j][half * 2 + 1]));
            }
        }
    }
}

// ---------------------------------------------------------------------------
extern "C" void kernel_launch(void* const* d_in, const int* in_sizes, int n_in,
                              void* d_out, int out_size)
{
    const float* x    = (const float*)d_in[0];
    const int*   mask = (const int*)d_in[1];
    const float* ln_a = (const float*)d_in[2];
    const float* ln_b = (const float*)d_in[3];
    const float* wq_w = (const float*)d_in[4];
    const float* wq_b = (const float*)d_in[5];
    const float* wk_w = (const float*)d_in[6];
    const float* wk_b = (const float*)d_in[7];
    const float* wv_w = (const float*)d_in[8];
    const float* wv_b = (const float*)d_in[9];
    const float* fc_w = (const float*)d_in[10];
    const float* fc_b = (const float*)d_in[11];
    float* out = (float*)d_out;

    void *ph, *pq, *pk, *pvt, *po, *pwq, *pwk, *pwv, *pwf;
    cudaGetSymbolAddress(&ph,  g_h);
    cudaGetSymbolAddress(&pq,  g_q);
    cudaGetSymbolAddress(&pk,  g_k);
    cudaGetSymbolAddress(&pvt, g_vt);
    cudaGetSymbolAddress(&po,  g_o);
    cudaGetSymbolAddress(&pwq, g_wq);
    cudaGetSymbolAddress(&pwk, g_wk);
    cudaGetSymbolAddress(&pwv, g_wv);
    cudaGetSymbolAddress(&pwf, g_wf);
    float* h   = (float*)ph;
    float* q   = (float*)pq;
    float* k   = (float*)pk;
    float* vt  = (float*)pvt;
    float* o   = (float*)po;

    float* attn = out + OUT_ELEMS;

    const int DSM_G = 73728;
    const int DSM_A = 27392 * 4;   // 109568
    cudaFuncSetAttribute(gemm_qkv, cudaFuncAttributeMaxDynamicSharedMemorySize, DSM_G);
    cudaFuncSetAttribute(gemm_fc,  cudaFuncAttributeMaxDynamicSharedMemorySize, DSM_G);
    cudaFuncSetAttribute(attn_fused, cudaFuncAttributeMaxDynamicSharedMemorySize, DSM_A);

    // 0. Pre-round weights to tf32
    wround_kernel<<<1024, 256>>>(wq_w, (float*)pwq);
    wround_kernel<<<1024, 256>>>(wk_w, (float*)pwk);
    wround_kernel<<<1024, 256>>>(wv_w, (float*)pwv);
    wround_kernel<<<1024, 256>>>(fc_w, (float*)pwf);

    // 1. LayerNorm
    ln_kernel<<<Bb * Ss, 256>>>(x, ln_a, ln_b, h);

    // 2. QKV projections (single launch, z selects weight)
    gemm_qkv<<<dim3(8, 64, 3), 256, DSM_G>>>(
        h, (float*)pwq, (float*)pwk, (float*)pwv,
        wq_b, wk_b, wv_b, q, k, vt);

    // 3+4+5. Fused scores + softmax + AV
    attn_fused<<<dim3(16, Bb * Hh), 256, DSM_A>>>(q, k, vt, mask, attn, o);

    // 6. FC + bias + residual
    gemm_fc<<<dim3(8, 64), 256, DSM_G>>>(o, (float*)pwf, fc_b, x, out);
}

// round 6
// speedup vs baseline: 2.7549x; 1.0052x over previous
#include <cuda_runtime.h>
#include <math.h>
#include <stdint.h>

#define Bb 4
#define Ss 2048
#define Dd 1024
#define Hh 16
#define DK 64

static const size_t OUT_ELEMS  = (size_t)Bb * Ss * Dd;        // 8388608

// Scratch (device globals — allocation-free per harness rules)
__device__ float g_h[(size_t)Bb * Ss * Dd];
__device__ float g_q[(size_t)Bb * Hh * Ss * DK];
__device__ float g_k[(size_t)Bb * Hh * Ss * DK];
__device__ float g_vt[(size_t)Bb * Hh * DK * Ss];   // V transposed: [bh][d][s]
__device__ float g_o[(size_t)Bb * Ss * Dd];
__device__ float g_wq[(size_t)Dd * Dd];
__device__ float g_wk[(size_t)Dd * Dd];
__device__ float g_wv[(size_t)Dd * Dd];
__device__ float g_wf[(size_t)Dd * Dd];

// ---------------------------------------------------------------------------
__device__ __forceinline__ float f2tf32f(float x) {
    uint32_t u;
    asm("cvt.rna.tf32.f32 %0, %1;" : "=r"(u) : "f"(x));
    return __uint_as_float(u);
}

#define CP16(dst_u32, src_ptr) \
    asm volatile("cp.async.cg.shared.global [%0], [%1], 16;\n" :: "r"(dst_u32), "l"(src_ptr))
#define CP_COMMIT() asm volatile("cp.async.commit_group;\n" ::)
#define CP_WAIT(N)  asm volatile("cp.async.wait_group %0;\n" :: "n"(N))

#define MMA_TF32(acc, a, b) \
    asm volatile( \
        "mma.sync.aligned.m16n8k8.row.col.f32.tf32.tf32.f32 " \
        "{%0,%1,%2,%3}, {%4,%5,%6,%7}, {%8,%9}, {%0,%1,%2,%3};" \
        : "+f"(acc[0]), "+f"(acc[1]), "+f"(acc[2]), "+f"(acc[3]) \
        : "r"(a[0]), "r"(a[1]), "r"(a[2]), "r"(a[3]), "r"(b[0]), "r"(b[1]))

__device__ __forceinline__ float blockReduceSum(float val) {
    __shared__ float sh[32];
    int lane = threadIdx.x & 31, wid = threadIdx.x >> 5;
    #pragma unroll
    for (int o = 16; o; o >>= 1) val += __shfl_down_sync(0xffffffffu, val, o);
    if (lane == 0) sh[wid] = val;
    __syncthreads();
    val = (threadIdx.x < 8) ? sh[lane] : 0.0f;
    if (wid == 0) {
        #pragma unroll
        for (int o = 4; o; o >>= 1) val += __shfl_down_sync(0xffffffffu, val, o);
    }
    __syncthreads();
    return val;
}

// ---------------------------------------------------------------------------
// LayerNorm — writes tf32-rounded h
// ---------------------------------------------------------------------------
__global__ __launch_bounds__(256) void ln_kernel(
    const float* __restrict__ x, const float* __restrict__ a,
    const float* __restrict__ bvec, float* __restrict__ h)
{
    int row = blockIdx.x;
    const float4* xr = (const float4*)(x + (size_t)row * Dd);
    float4 v = xr[threadIdx.x];

    float s = blockReduceSum(v.x + v.y + v.z + v.w);
    __shared__ float mean_s, inv_s;
    if (threadIdx.x == 0) mean_s = s * (1.0f / Dd);
    __syncthreads();
    float mean = mean_s;

    float dx = v.x - mean, dy = v.y - mean, dz = v.z - mean, dw = v.w - mean;
    float sq = blockReduceSum(dx * dx + dy * dy + dz * dz + dw * dw);
    if (threadIdx.x == 0) inv_s = 1.0f / (sqrtf(sq * (1.0f / (Dd - 1))) + 1e-6f);
    __syncthreads();
    float inv = inv_s;

    float4 av = ((const float4*)a)[threadIdx.x];
    float4 bv = ((const float4*)bvec)[threadIdx.x];
    float4 o;
    o.x = f2tf32f(av.x * dx * inv + bv.x);
    o.y = f2tf32f(av.y * dy * inv + bv.y);
    o.z = f2tf32f(av.z * dz * inv + bv.z);
    o.w = f2tf32f(av.w * dw * inv + bv.w);
    ((float4*)(h + (size_t)row * Dd))[threadIdx.x] = o;
}

__global__ __launch_bounds__(256) void wround_kernel(
    const float* __restrict__ src, float* __restrict__ dst)
{
    int i = blockIdx.x * 256 + threadIdx.x;
    float4 v = ((const float4*)src)[i];
    v.x = f2tf32f(v.x); v.y = f2tf32f(v.y);
    v.z = f2tf32f(v.z); v.w = f2tf32f(v.w);
    ((float4*)dst)[i] = v;
}

// ---------------------------------------------------------------------------
// Combined QKV projection GEMM. blockIdx.z selects {Q,K,V}.
// ---------------------------------------------------------------------------
__global__ __launch_bounds__(256, 2) void gemm_qkv(
    const float* __restrict__ A,
    const float* __restrict__ wq, const float* __restrict__ wk,
    const float* __restrict__ wv,
    const float* __restrict__ bq, const float* __restrict__ bk,
    const float* __restrict__ bv,
    float* __restrict__ q, float* __restrict__ k, float* __restrict__ vt)
{
    extern __shared__ __align__(16) float dsm[];
    const int ASTG = 4608, BOFF = 9216;
    uint32_t smem_u = (uint32_t)__cvta_generic_to_shared(dsm);

    int z = blockIdx.z;
    const float* B    = (z == 0) ? wq : (z == 1) ? wk : wv;
    const float* bias = (z == 0) ? bq : (z == 1) ? bk : bv;

    const int K = Dd;
    int tid = threadIdx.x;
    int m0 = blockIdx.y * 128, n0 = blockIdx.x * 128;
    int lane = tid & 31, warp = tid >> 5;
    int wm = warp >> 2, wn = warp & 3;
    int row = lane >> 2, tig = lane & 3;
    int mb = wm * 64, nb = wn * 32;

    float acc[4][4][4] = {};
    int r_ld = tid >> 3;
    int c_ld = (tid & 7) * 4;

    auto loadTile = [&](int kt, int s) {
        int kof = kt * 32;
        #pragma unroll
        for (int i = 0; i < 4; i++) {
            int r = r_ld + i * 32;
            CP16(smem_u + (s * ASTG + r * 36 + c_ld) * 4,
                 A + (size_t)(m0 + r) * K + kof + c_ld);
        }
        #pragma unroll
        for (int i = 0; i < 4; i++) {
            int r = r_ld + i * 32;
            CP16(smem_u + (BOFF + s * ASTG + r * 36 + c_ld) * 4,
                 B + (size_t)(n0 + r) * K + kof + c_ld);
        }
    };

    loadTile(0, 0);
    CP_COMMIT();

    for (int it = 0; it < 32; it++) {
        int s = it & 1;
        if (it + 1 < 32) {
            loadTile(it + 1, s ^ 1);
            CP_COMMIT();
            CP_WAIT(1);
        } else {
            CP_WAIT(0);
        }
        __syncthreads();

        const float* As = dsm + s * ASTG;
        const float* Bs = dsm + BOFF + s * ASTG;
        #pragma unroll
        for (int ks = 0; ks < 4; ks++) {
            int kb = ks * 8;
            uint32_t a[4][4], b[4][2];
            #pragma unroll
            for (int i = 0; i < 4; i++) {
                a[i][0] = __float_as_uint(As[(mb + i * 16 + row) * 36 + kb + tig]);
                a[i][1] = __float_as_uint(As[(mb + i * 16 + row + 8) * 36 + kb + tig]);
                a[i][2] = __float_as_uint(As[(mb + i * 16 + row) * 36 + kb + tig + 4]);
                a[i][3] = __float_as_uint(As[(mb + i * 16 + row + 8) * 36 + kb + tig + 4]);
            }
            #pragma unroll
            for (int j = 0; j < 4; j++) {
                b[j][0] = __float_as_uint(Bs[(nb + j * 8 + row) * 36 + kb + tig]);
                b[j][1] = __float_as_uint(Bs[(nb + j * 8 + row) * 36 + kb + tig + 4]);
            }
            #pragma unroll
            for (int i = 0; i < 4; i++)
                #pragma unroll
                for (int j = 0; j < 4; j++)
                    MMA_TF32(acc[i][j], a[i], b[j]);
        }
        __syncthreads();
    }

    #pragma unroll
    for (int i = 0; i < 4; i++) {
        int gm = m0 + mb + i * 16 + row;
        #pragma unroll
        for (int j = 0; j < 4; j++) {
            int gn = n0 + nb + j * 8 + tig * 2;
            #pragma unroll
            for (int half = 0; half < 2; half++) {
                int m = gm + half * 8;
                float v0 = f2tf32f(acc[i][j][half * 2] + bias[gn]);
                float v1 = f2tf32f(acc[i][j][half * 2 + 1] + bias[gn + 1]);
                int bi = m >> 11, s2 = m & (Ss - 1);
                int hh = gn >> 6, d = gn & 63;
                if (z < 2) {
                    float* C = (z == 0) ? q : k;
                    *(float2*)&C[(((size_t)(bi * Hh + hh) * Ss) + s2) * DK + d] =
                        make_float2(v0, v1);
                } else {
                    size_t base = ((size_t)(bi * Hh + hh) * DK + d) * Ss + s2;
                    vt[base]      = v0;
                    vt[base + Ss] = v1;
                }
            }
        }
    }
}

// ---------------------------------------------------------------------------
// FC GEMM + bias + residual
// ---------------------------------------------------------------------------
__global__ __launch_bounds__(256, 2) void gemm_fc(
    const float* __restrict__ A, const float* __restrict__ B,
    const float* __restrict__ bias, const float* __restrict__ xres,
    float* __restrict__ C)
{
    extern __shared__ __align__(16) float dsm[];
    const int ASTG = 4608, BOFF = 9216;
    uint32_t smem_u = (uint32_t)__cvta_generic_to_shared(dsm);

    const int K = Dd;
    int tid = threadIdx.x;
    int m0 = blockIdx.y * 128, n0 = blockIdx.x * 128;
    int lane = tid & 31, warp = tid >> 5;
    int wm = warp >> 2, wn = warp & 3;
    int row = lane >> 2, tig = lane & 3;
    int mb = wm * 64, nb = wn * 32;

    float acc[4][4][4] = {};
    int r_ld = tid >> 3;
    int c_ld = (tid & 7) * 4;

    auto loadTile = [&](int kt, int s) {
        int kof = kt * 32;
        #pragma unroll
        for (int i = 0; i < 4; i++) {
            int r = r_ld + i * 32;
            CP16(smem_u + (s * ASTG + r * 36 + c_ld) * 4,
                 A + (size_t)(m0 + r) * K + kof + c_ld);
        }
        #pragma unroll
        for (int i = 0; i < 4; i++) {
            int r = r_ld + i * 32;
            CP16(smem_u + (BOFF + s * ASTG + r * 36 + c_ld) * 4,
                 B + (size_t)(n0 + r) * K + kof + c_ld);
        }
    };

    loadTile(0, 0);
    CP_COMMIT();

    for (int it = 0; it < 32; it++) {
        int s = it & 1;
        if (it + 1 < 32) {
            loadTile(it + 1, s ^ 1);
            CP_COMMIT();
            CP_WAIT(1);
        } else {
            CP_WAIT(0);
        }
        __syncthreads();

        const float* As = dsm + s * ASTG;
        const float* Bs = dsm + BOFF + s * ASTG;
        #pragma unroll
        for (int ks = 0; ks < 4; ks++) {
            int kb = ks * 8;
            uint32_t a[4][4], b[4][2];
            #pragma unroll
            for (int i = 0; i < 4; i++) {
                a[i][0] = __float_as_uint(As[(mb + i * 16 + row) * 36 + kb + tig]);
                a[i][1] = __float_as_uint(As[(mb + i * 16 + row + 8) * 36 + kb + tig]);
                a[i][2] = __float_as_uint(As[(mb + i * 16 + row) * 36 + kb + tig + 4]);
                a[i][3] = __float_as_uint(As[(mb + i * 16 + row + 8) * 36 + kb + tig + 4]);
            }
            #pragma unroll
            for (int j = 0; j < 4; j++) {
                b[j][0] = __float_as_uint(Bs[(nb + j * 8 + row) * 36 + kb + tig]);
                b[j][1] = __float_as_uint(Bs[(nb + j * 8 + row) * 36 + kb + tig + 4]);
            }
            #pragma unroll
            for (int i = 0; i < 4; i++)
                #pragma unroll
                for (int j = 0; j < 4; j++)
                    MMA_TF32(acc[i][j], a[i], b[j]);
        }
        __syncthreads();
    }

    #pragma unroll
    for (int i = 0; i < 4; i++) {
        int gm = m0 + mb + i * 16 + row;
        #pragma unroll
        for (int j = 0; j < 4; j++) {
            int gn = n0 + nb + j * 8 + tig * 2;
            #pragma unroll
            for (int half = 0; half < 2; half++) {
                int m = gm + half * 8;
                size_t idx = (size_t)m * Dd + gn;
                float2 xv = *(const float2*)&xres[idx];
                *(float2*)&C[idx] = make_float2(
                    acc[i][j][half * 2] + bias[gn] + xv.x,
                    acc[i][j][half * 2 + 1] + bias[gn + 1] + xv.y);
            }
        }
    }
}

// ---------------------------------------------------------------------------
// Fused attention (recompute scheme):
//  pass A: S = 0.125*Q@K^T masked -> online (m, sumexp) only. NO gmem writes.
//  pass B: recompute S per 64-key tile, p=exp(s-M)*invZ -> write attn once,
//          stage p in smem, O += P@V (V tile co-resident).
// ---------------------------------------------------------------------------
__global__ __launch_bounds__(256, 2) void attn_fused(
    const float* __restrict__ Q, const float* __restrict__ Kk,
    const float* __restrict__ Vt, const int* __restrict__ mask,
    float* __restrict__ attn, float* __restrict__ O)
{
    extern __shared__ __align__(16) float dsm[];
    // floats: Q[128][68]@0
    // pass A: K double buf [2][128][68]@8704
    // pass B overlay: KT[64][68]@8704, VT[64][68]@13056, AS[128][68]@17408
    // stats: WSM@26112[512], WSS@26624[512], SMM@27136[128], SMI@27264[128]
    const int KA = 8704, KT = 8704, VTo = 13056, ASo = 17408;
    const int WSM = 26112, WSS = 26624, SMM = 27136, SMI = 27264;
    uint32_t smem_u = (uint32_t)__cvta_generic_to_shared(dsm);

    int tid = threadIdx.x;
    int bz = blockIdx.y;               // bh
    int m0 = blockIdx.x * 128;
    const float* Qp = Q  + (size_t)bz * Ss * DK;
    const float* Kp = Kk + (size_t)bz * Ss * DK;
    const float* Vp = Vt + (size_t)bz * DK * Ss;
    const int* mrow = mask + (size_t)(bz >> 4) * Ss * Ss;
    float* arow = attn + (size_t)bz * Ss * Ss;

    int lane = tid & 31, warp = tid >> 5;
    int wm = warp >> 2, wn = warp & 3;
    int row = lane >> 2, tig = lane & 3;
    int mb = wm * 64;

    // ---- load Q strip + first K tile (128 keys) ----
    #pragma unroll
    for (int i = 0; i < 8; i++) {
        int idx = tid + i * 256;
        int r = idx >> 4, c = (idx & 15) * 4;
        CP16(smem_u + (r * 68 + c) * 4, Qp + (size_t)(m0 + r) * DK + c);
    }
    #pragma unroll
    for (int i = 0; i < 8; i++) {
        int idx = tid + i * 256;
        int r = idx >> 4, c = (idx & 15) * 4;
        CP16(smem_u + (KA + r * 68 + c) * 4, Kp + (size_t)r * DK + c);
    }
    CP_COMMIT();

    float mrun[8], srun[8];
    #pragma unroll
    for (int s8 = 0; s8 < 8; s8++) { mrun[s8] = -INFINITY; srun[s8] = 0.0f; }

    // ================= pass A: stats only =================
    for (int kt = 0; kt < 16; kt++) {
        CP_WAIT(0);
        __syncthreads();

        const float* Ksb = dsm + KA + (kt & 1) * 8704;
        float acc[4][4][4] = {};
        #pragma unroll
        for (int ks = 0; ks < 8; ks++) {
            int kb = ks * 8;
            uint32_t a[4][4], b[4][2];
            #pragma unroll
            for (int i = 0; i < 4; i++) {
                a[i][0] = __float_as_uint(dsm[(mb + i * 16 + row) * 68 + kb + tig]);
                a[i][1] = __float_as_uint(dsm[(mb + i * 16 + row + 8) * 68 + kb + tig]);
                a[i][2] = __float_as_uint(dsm[(mb + i * 16 + row) * 68 + kb + tig + 4]);
                a[i][3] = __float_as_uint(dsm[(mb + i * 16 + row + 8) * 68 + kb + tig + 4]);
            }
            #pragma unroll
            for (int j = 0; j < 4; j++) {
                b[j][0] = __float_as_uint(Ksb[(wn * 32 + j * 8 + row) * 68 + kb + tig]);
                b[j][1] = __float_as_uint(Ksb[(wn * 32 + j * 8 + row) * 68 + kb + tig + 4]);
            }
            #pragma unroll
            for (int i = 0; i < 4; i++)
                #pragma unroll
                for (int j = 0; j < 4; j++)
                    MMA_TF32(acc[i][j], a[i], b[j]);
        }

        if (kt + 1 < 16) {
            int buf = (kt + 1) & 1;
            #pragma unroll
            for (int i = 0; i < 8; i++) {
                int idx = tid + i * 256;
                int r = idx >> 4, c = (idx & 15) * 4;
                CP16(smem_u + (KA + buf * 8704 + r * 68 + c) * 4,
                     Kp + (size_t)((kt + 1) * 128 + r) * DK + c);
            }
            CP_COMMIT();
        }

        #pragma unroll
        for (int i = 0; i < 4; i++) {
            #pragma unroll
            for (int half = 0; half < 2; half++) {
                int s8 = i * 2 + half;
                int m = m0 + mb + i * 16 + half * 8 + row;
                float vals[8];
                float lmax = -INFINITY;
                #pragma unroll
                for (int j = 0; j < 4; j++) {
                    int gn = kt * 128 + wn * 32 + j * 8 + tig * 2;
                    size_t idx = (size_t)m * Ss + gn;
                    float s0 = acc[i][j][half * 2] * 0.125f;
                    float s1 = acc[i][j][half * 2 + 1] * 0.125f;
                    int2 mv = *(const int2*)&mrow[idx];
                    if (mv.x == 0) s0 = -1e9f;
                    if (mv.y == 0) s1 = -1e9f;
                    vals[j * 2] = s0; vals[j * 2 + 1] = s1;
                    lmax = fmaxf(lmax, fmaxf(s0, s1));
                }
                float nm = fmaxf(mrun[s8], lmax);
                float se = 0.0f;
                #pragma unroll
                for (int j = 0; j < 8; j++) se += __expf(vals[j] - nm);
                srun[s8] = srun[s8] * __expf(mrun[s8] - nm) + se;
                mrun[s8] = nm;
            }
        }
    }

    // ---- stats merge ----
    #pragma unroll
    for (int s8 = 0; s8 < 8; s8++) {
        #pragma unroll
        for (int d = 1; d <= 2; d <<= 1) {
            float om = __shfl_xor_sync(0xffffffffu, mrun[s8], d);
            float os = __shfl_xor_sync(0xffffffffu, srun[s8], d);
            float nm = fmaxf(mrun[s8], om);
            srun[s8] = srun[s8] * __expf(mrun[s8] - nm) + os * __expf(om - nm);
            mrun[s8] = nm;
        }
    }
    if (tig == 0) {
        #pragma unroll
        for (int s8 = 0; s8 < 8; s8++) {
            int rloc = mb + (s8 >> 1) * 16 + (s8 & 1) * 8 + row;
            dsm[WSM + rloc * 4 + wn] = mrun[s8];
            dsm[WSS + rloc * 4 + wn] = srun[s8];
        }
    }
    __syncthreads();
    if (tid < 128) {
        float M = -INFINITY;
        #pragma unroll
        for (int w = 0; w < 4; w++) M = fmaxf(M, dsm[WSM + tid * 4 + w]);
        float Z = 0.0f;
        #pragma unroll
        for (int w = 0; w < 4; w++)
            Z += dsm[WSS + tid * 4 + w] * __expf(dsm[WSM + tid * 4 + w] - M);
        dsm[SMM + tid] = M;
        dsm[SMI + tid] = 1.0f / Z;
    }
    __syncthreads();

    // ================= pass B: recompute + normalize + P@V =================
    float oacc[4][2][4] = {};
    int nb2 = wn * 16;

    // preload tile 0: KT 64x64, VT 64x64 (4 float4 per thread each)
    #pragma unroll
    for (int i = 0; i < 4; i++) {
        int idx = tid + i * 256;
        int r = idx >> 4, c = (idx & 15) * 4;
        CP16(smem_u + (KT + r * 68 + c) * 4, Kp + (size_t)r * DK + c);
        CP16(smem_u + (VTo + r * 68 + c) * 4, Vp + (size_t)r * Ss + c);
    }
    CP_COMMIT();

    for (int t = 0; t < 32; t++) {
        CP_WAIT(0);
        __syncthreads();

        // --- recompute S for this 64-key tile (per warp n-slice 16 keys) ---
        float sacc[4][2][4] = {};
        #pragma unroll
        for (int ks = 0; ks < 8; ks++) {
            int kb = ks * 8;
            uint32_t a[4][4], b[2][2];
            #pragma unroll
            for (int i = 0; i < 4; i++) {
                a[i][0] = __float_as_uint(dsm[(mb + i * 16 + row) * 68 + kb + tig]);
                a[i][1] = __float_as_uint(dsm[(mb + i * 16 + row + 8) * 68 + kb + tig]);
                a[i][2] = __float_as_uint(dsm[(mb + i * 16 + row) * 68 + kb + tig + 4]);
                a[i][3] = __float_as_uint(dsm[(mb + i * 16 + row + 8) * 68 + kb + tig + 4]);
            }
            #pragma unroll
            for (int j = 0; j < 2; j++) {
                b[j][0] = __float_as_uint(dsm[KT + (nb2 + j * 8 + row) * 68 + kb + tig]);
                b[j][1] = __float_as_uint(dsm[KT + (nb2 + j * 8 + row) * 68 + kb + tig + 4]);
            }
            #pragma unroll
            for (int i = 0; i < 4; i++)
                #pragma unroll
                for (int j = 0; j < 2; j++)
                    MMA_TF32(sacc[i][j], a[i], b[j]);
        }
        __syncthreads();   // all warps done reading KT

        // prefetch next K tile into KT (overlaps epilogue + AV mma)
        if (t + 1 < 32) {
            #pragma unroll
            for (int i = 0; i < 4; i++) {
                int idx = tid + i * 256;
                int r = idx >> 4, c = (idx & 15) * 4;
                CP16(smem_u + (KT + r * 68 + c) * 4,
                     Kp + (size_t)((t + 1) * 64 + r) * DK + c);
            }
            CP_COMMIT();
        }

        // --- epilogue: p = exp(s-M)*invZ, write attn, stage to AS ---
        #pragma unroll
        for (int i = 0; i < 4; i++) {
            #pragma unroll
            for (int half = 0; half < 2; half++) {
                int rloc = mb + i * 16 + half * 8 + row;
                int m = m0 + rloc;
                float M = dsm[SMM + rloc], inv = dsm[SMI + rloc];
                #pragma unroll
                for (int j = 0; j < 2; j++) {
                    int kn = wn * 16 + j * 8 + tig * 2;     // key within tile
                    int gn = t * 64 + kn;
                    size_t idx = (size_t)m * Ss + gn;
                    float s0 = sacc[i][j][half * 2] * 0.125f;
                    float s1 = sacc[i][j][half * 2 + 1] * 0.125f;
                    int2 mv = *(const int2*)&mrow[idx];
                    if (mv.x == 0) s0 = -1e9f;
                    if (mv.y == 0) s1 = -1e9f;
                    float p0 = __expf(s0 - M) * inv;
                    float p1 = __expf(s1 - M) * inv;
                    *(float2*)&arow[idx] = make_float2(p0, p1);
                    dsm[ASo + rloc * 68 + kn]     = f2tf32f(p0);
                    dsm[ASo + rloc * 68 + kn + 1] = f2tf32f(p1);
                }
            }
        }
        __syncthreads();   // AS ready for all warps

        // --- AV: O += P(128x64) @ V(64 keys -> 64 d) ---
        #pragma unroll
        for (int ks = 0; ks < 8; ks++) {
            int kb = ks * 8;
            uint32_t a[4][4], b[2][2];
            #pragma unroll
            for (int i = 0; i < 4; i++) {
                a[i][0] = __float_as_uint(dsm[ASo + (mb + i * 16 + row) * 68 + kb + tig]);
                a[i][1] = __float_as_uint(dsm[ASo + (mb + i * 16 + row + 8) * 68 + kb + tig]);
                a[i][2] = __float_as_uint(dsm[ASo + (mb + i * 16 + row) * 68 + kb + tig + 4]);
                a[i][3] = __float_as_uint(dsm[ASo + (mb + i * 16 + row + 8) * 68 + kb + tig + 4]);
            }
            #pragma unroll
            for (int j = 0; j < 2; j++) {
                b[j][0] = __float_as_uint(dsm[VTo + (nb2 + j * 8 + row) * 68 + kb + tig]);
                b[j][1] = __float_as_uint(dsm[VTo + (nb2 + j * 8 + row) * 68 + kb + tig + 4]);
            }
            #pragma unroll
            for (int i = 0; i < 4; i++)
                #pragma unroll
                for (int j = 0; j < 2; j++)
                    MMA_TF32(oacc[i][j], a[i], b[j]);
        }
        __syncthreads();   // all warps done reading VT + AS

        // prefetch next V tile
        if (t + 1 < 32) {
            #pragma unroll
            for (int i = 0; i < 4; i++) {
                int idx = tid + i * 256;
                int r = idx >> 4, c = (idx & 15) * 4;
                CP16(smem_u + (VTo + r * 68 + c) * 4,
                     Vp + (size_t)r * Ss + (t + 1) * 64 + c);
            }
            CP_COMMIT();
        }
    }

    int bi = bz >> 4, hh = bz & 15;
    #pragma unroll
    for (int i = 0; i < 4; i++) {
        int gm = m0 + mb + i * 16 + row;
        #pragma unroll
        for (int j = 0; j < 2; j++) {
            int gn = nb2 + j * 8 + tig * 2;
            #pragma unroll
            for (int half = 0; half < 2; half++) {
                int m = gm + half * 8;
                size_t idx = ((size_t)bi * Ss + m) * Dd + hh * DK + gn;
                *(float2*)&O[idx] = make_float2(
                    f2tf32f(oacc[i][j][half * 2]),
                    f2tf32f(oacc[i][j][half * 2 + 1]));
            }
        }
    }
}

// ---------------------------------------------------------------------------
extern "C" void kernel_launch(void* const* d_in, const int* in_sizes, int n_in,
                              void* d_out, int out_size)
{
    const float* x    = (const float*)d_in[0];
    const int*   mask = (const int*)d_in[1];
    const float* ln_a = (const float*)d_in[2];
    const float* ln_b = (const float*)d_in[3];
    const float* wq_w = (const float*)d_in[4];
    const float* wq_b = (const float*)d_in[5];
    const float* wk_w = (const float*)d_in[6];
    const float* wk_b = (const float*)d_in[7];
    const float* wv_w = (const float*)d_in[8];
    const float* wv_b = (const float*)d_in[9];
    const float* fc_w = (const float*)d_in[10];
    const float* fc_b = (const float*)d_in[11];
    float* out = (float*)d_out;

    void *ph, *pq, *pk, *pvt, *po, *pwq, *pwk, *pwv, *pwf;
    cudaGetSymbolAddress(&ph,  g_h);
    cudaGetSymbolAddress(&pq,  g_q);
    cudaGetSymbolAddress(&pk,  g_k);
    cudaGetSymbolAddress(&pvt, g_vt);
    cudaGetSymbolAddress(&po,  g_o);
    cudaGetSymbolAddress(&pwq, g_wq);
    cudaGetSymbolAddress(&pwk, g_wk);
    cudaGetSymbolAddress(&pwv, g_wv);
    cudaGetSymbolAddress(&pwf, g_wf);
    float* h   = (float*)ph;
    float* q   = (float*)pq;
    float* k   = (float*)pk;
    float* vt  = (float*)pvt;
    float* o   = (float*)po;

    float* attn = out + OUT_ELEMS;

    const int DSM_G = 73728;
    const int DSM_A = 27392 * 4;   // 109568
    cudaFuncSetAttribute(gemm_qkv, cudaFuncAttributeMaxDynamicSharedMemorySize, DSM_G);
    cudaFuncSetAttribute(gemm_fc,  cudaFuncAttributeMaxDynamicSharedMemorySize, DSM_G);
    cudaFuncSetAttribute(attn_fused, cudaFuncAttributeMaxDynamicSharedMemorySize, DSM_A);

    // 0. Pre-round weights to tf32
    wround_kernel<<<1024, 256>>>(wq_w, (float*)pwq);
    wround_kernel<<<1024, 256>>>(wk_w, (float*)pwk);
    wround_kernel<<<1024, 256>>>(wv_w, (float*)pwv);
    wround_kernel<<<1024, 256>>>(fc_w, (float*)pwf);

    // 1. LayerNorm
    ln_kernel<<<Bb * Ss, 256>>>(x, ln_a, ln_b, h);

    // 2. QKV projections (single launch, z selects weight)
    gemm_qkv<<<dim3(8, 64, 3), 256, DSM_G>>>(
        h, (float*)pwq, (float*)pwk, (float*)pwv,
        wq_b, wk_b, wv_b, q, k, vt);

    // 3+4+5. Fused scores + softmax + AV (recompute scheme)
    attn_fused<<<dim3(16, Bb * Hh), 256, DSM_A>>>(q, k, vt, mask, attn, o);

    // 6. FC + bias + residual
    gemm_fc<<<dim3(8, 64), 256, DSM_G>>>(o, (float*)pwf, fc_b, x, out);
}

// round 7
// speedup vs baseline: 2.8027x; 1.0174x over previous
#include <cuda_runtime.h>
#include <math.h>
#include <stdint.h>

#define Bb 4
#define Ss 2048
#define Dd 1024
#define Hh 16
#define DK 64

static const size_t OUT_ELEMS  = (size_t)Bb * Ss * Dd;        // 8388608

// Scratch (device globals — allocation-free per harness rules)
__device__ float g_h[(size_t)Bb * Ss * Dd];
__device__ float g_q[(size_t)Bb * Hh * Ss * DK];
__device__ float g_k[(size_t)Bb * Hh * Ss * DK];
__device__ float g_vt[(size_t)Bb * Hh * DK * Ss];   // V transposed: [bh][d][s]
__device__ float g_o[(size_t)Bb * Ss * Dd];
__device__ float g_wq[(size_t)Dd * Dd];
__device__ float g_wk[(size_t)Dd * Dd];
__device__ float g_wv[(size_t)Dd * Dd];
__device__ float g_wf[(size_t)Dd * Dd];

// ---------------------------------------------------------------------------
__device__ __forceinline__ float f2tf32f(float x) {
    uint32_t u;
    asm("cvt.rna.tf32.f32 %0, %1;" : "=r"(u) : "f"(x));
    return __uint_as_float(u);
}

#define CP16(dst_u32, src_ptr) \
    asm volatile("cp.async.cg.shared.global [%0], [%1], 16;\n" :: "r"(dst_u32), "l"(src_ptr))
#define CP_COMMIT() asm volatile("cp.async.commit_group;\n" ::)
#define CP_WAIT(N)  asm volatile("cp.async.wait_group %0;\n" :: "n"(N))

#define MMA_TF32(acc, a, b) \
    asm volatile( \
        "mma.sync.aligned.m16n8k8.row.col.f32.tf32.tf32.f32 " \
        "{%0,%1,%2,%3}, {%4,%5,%6,%7}, {%8,%9}, {%0,%1,%2,%3};" \
        : "+f"(acc[0]), "+f"(acc[1]), "+f"(acc[2]), "+f"(acc[3]) \
        : "r"(a[0]), "r"(a[1]), "r"(a[2]), "r"(a[3]), "r"(b[0]), "r"(b[1]))

__device__ __forceinline__ float blockReduceSum(float val) {
    __shared__ float sh[32];
    int lane = threadIdx.x & 31, wid = threadIdx.x >> 5;
    #pragma unroll
    for (int o = 16; o; o >>= 1) val += __shfl_down_sync(0xffffffffu, val, o);
    if (lane == 0) sh[wid] = val;
    __syncthreads();
    val = (threadIdx.x < 8) ? sh[lane] : 0.0f;
    if (wid == 0) {
        #pragma unroll
        for (int o = 4; o; o >>= 1) val += __shfl_down_sync(0xffffffffu, val, o);
    }
    __syncthreads();
    return val;
}

// ---------------------------------------------------------------------------
// LayerNorm — writes tf32-rounded h
// ---------------------------------------------------------------------------
__global__ __launch_bounds__(256) void ln_kernel(
    const float* __restrict__ x, const float* __restrict__ a,
    const float* __restrict__ bvec, float* __restrict__ h)
{
    int row = blockIdx.x;
    const float4* xr = (const float4*)(x + (size_t)row * Dd);
    float4 v = xr[threadIdx.x];

    float s = blockReduceSum(v.x + v.y + v.z + v.w);
    __shared__ float mean_s, inv_s;
    if (threadIdx.x == 0) mean_s = s * (1.0f / Dd);
    __syncthreads();
    float mean = mean_s;

    float dx = v.x - mean, dy = v.y - mean, dz = v.z - mean, dw = v.w - mean;
    float sq = blockReduceSum(dx * dx + dy * dy + dz * dz + dw * dw);
    if (threadIdx.x == 0) inv_s = 1.0f / (sqrtf(sq * (1.0f / (Dd - 1))) + 1e-6f);
    __syncthreads();
    float inv = inv_s;

    float4 av = ((const float4*)a)[threadIdx.x];
    float4 bv = ((const float4*)bvec)[threadIdx.x];
    float4 o;
    o.x = f2tf32f(av.x * dx * inv + bv.x);
    o.y = f2tf32f(av.y * dy * inv + bv.y);
    o.z = f2tf32f(av.z * dz * inv + bv.z);
    o.w = f2tf32f(av.w * dw * inv + bv.w);
    ((float4*)(h + (size_t)row * Dd))[threadIdx.x] = o;
}

__global__ __launch_bounds__(256) void wround_kernel(
    const float* __restrict__ src, float* __restrict__ dst)
{
    int i = blockIdx.x * 256 + threadIdx.x;
    float4 v = ((const float4*)src)[i];
    v.x = f2tf32f(v.x); v.y = f2tf32f(v.y);
    v.z = f2tf32f(v.z); v.w = f2tf32f(v.w);
    ((float4*)dst)[i] = v;
}

// ---------------------------------------------------------------------------
// Combined QKV projection GEMM. blockIdx.z selects {Q,K,V}.
// ---------------------------------------------------------------------------
__global__ __launch_bounds__(256, 2) void gemm_qkv(
    const float* __restrict__ A,
    const float* __restrict__ wq, const float* __restrict__ wk,
    const float* __restrict__ wv,
    const float* __restrict__ bq, const float* __restrict__ bk,
    const float* __restrict__ bv,
    float* __restrict__ q, float* __restrict__ k, float* __restrict__ vt)
{
    extern __shared__ __align__(16) float dsm[];
    const int ASTG = 4608, BOFF = 9216;
    uint32_t smem_u = (uint32_t)__cvta_generic_to_shared(dsm);

    int z = blockIdx.z;
    const float* B    = (z == 0) ? wq : (z == 1) ? wk : wv;
    const float* bias = (z == 0) ? bq : (z == 1) ? bk : bv;

    const int K = Dd;
    int tid = threadIdx.x;
    int m0 = blockIdx.y * 128, n0 = blockIdx.x * 128;
    int lane = tid & 31, warp = tid >> 5;
    int wm = warp >> 2, wn = warp & 3;
    int row = lane >> 2, tig = lane & 3;
    int mb = wm * 64, nb = wn * 32;

    float acc[4][4][4] = {};
    int r_ld = tid >> 3;
    int c_ld = (tid & 7) * 4;

    auto loadTile = [&](int kt, int s) {
        int kof = kt * 32;
        #pragma unroll
        for (int i = 0; i < 4; i++) {
            int r = r_ld + i * 32;
            CP16(smem_u + (s * ASTG + r * 36 + c_ld) * 4,
                 A + (size_t)(m0 + r) * K + kof + c_ld);
        }
        #pragma unroll
        for (int i = 0; i < 4; i++) {
            int r = r_ld + i * 32;
            CP16(smem_u + (BOFF + s * ASTG + r * 36 + c_ld) * 4,
                 B + (size_t)(n0 + r) * K + kof + c_ld);
        }
    };

    loadTile(0, 0);
    CP_COMMIT();

    for (int it = 0; it < 32; it++) {
        int s = it & 1;
        if (it + 1 < 32) {
            loadTile(it + 1, s ^ 1);
            CP_COMMIT();
            CP_WAIT(1);
        } else {
            CP_WAIT(0);
        }
        __syncthreads();

        const float* As = dsm + s * ASTG;
        const float* Bs = dsm + BOFF + s * ASTG;
        #pragma unroll
        for (int ks = 0; ks < 4; ks++) {
            int kb = ks * 8;
            uint32_t a[4][4], b[4][2];
            #pragma unroll
            for (int i = 0; i < 4; i++) {
                a[i][0] = __float_as_uint(As[(mb + i * 16 + row) * 36 + kb + tig]);
                a[i][1] = __float_as_uint(As[(mb + i * 16 + row + 8) * 36 + kb + tig]);
                a[i][2] = __float_as_uint(As[(mb + i * 16 + row) * 36 + kb + tig + 4]);
                a[i][3] = __float_as_uint(As[(mb + i * 16 + row + 8) * 36 + kb + tig + 4]);
            }
            #pragma unroll
            for (int j = 0; j < 4; j++) {
                b[j][0] = __float_as_uint(Bs[(nb + j * 8 + row) * 36 + kb + tig]);
                b[j][1] = __float_as_uint(Bs[(nb + j * 8 + row) * 36 + kb + tig + 4]);
            }
            #pragma unroll
            for (int i = 0; i < 4; i++)
                #pragma unroll
                for (int j = 0; j < 4; j++)
                    MMA_TF32(acc[i][j], a[i], b[j]);
        }
        __syncthreads();
    }

    #pragma unroll
    for (int i = 0; i < 4; i++) {
        int gm = m0 + mb + i * 16 + row;
        #pragma unroll
        for (int j = 0; j < 4; j++) {
            int gn = n0 + nb + j * 8 + tig * 2;
            #pragma unroll
            for (int half = 0; half < 2; half++) {
                int m = gm + half * 8;
                float v0 = f2tf32f(acc[i][j][half * 2] + bias[gn]);
                float v1 = f2tf32f(acc[i][j][half * 2 + 1] + bias[gn + 1]);
                int bi = m >> 11, s2 = m & (Ss - 1);
                int hh = gn >> 6, d = gn & 63;
                if (z < 2) {
                    float* C = (z == 0) ? q : k;
                    *(float2*)&C[(((size_t)(bi * Hh + hh) * Ss) + s2) * DK + d] =
                        make_float2(v0, v1);
                } else {
                    size_t base = ((size_t)(bi * Hh + hh) * DK + d) * Ss + s2;
                    vt[base]      = v0;
                    vt[base + Ss] = v1;
                }
            }
        }
    }
}

// ---------------------------------------------------------------------------
// FC GEMM + bias + residual
// ---------------------------------------------------------------------------
__global__ __launch_bounds__(256, 2) void gemm_fc(
    const float* __restrict__ A, const float* __restrict__ B,
    const float* __restrict__ bias, const float* __restrict__ xres,
    float* __restrict__ C)
{
    extern __shared__ __align__(16) float dsm[];
    const int ASTG = 4608, BOFF = 9216;
    uint32_t smem_u = (uint32_t)__cvta_generic_to_shared(dsm);

    const int K = Dd;
    int tid = threadIdx.x;
    int m0 = blockIdx.y * 128, n0 = blockIdx.x * 128;
    int lane = tid & 31, warp = tid >> 5;
    int wm = warp >> 2, wn = warp & 3;
    int row = lane >> 2, tig = lane & 3;
    int mb = wm * 64, nb = wn * 32;

    float acc[4][4][4] = {};
    int r_ld = tid >> 3;
    int c_ld = (tid & 7) * 4;

    auto loadTile = [&](int kt, int s) {
        int kof = kt * 32;
        #pragma unroll
        for (int i = 0; i < 4; i++) {
            int r = r_ld + i * 32;
            CP16(smem_u + (s * ASTG + r * 36 + c_ld) * 4,
                 A + (size_t)(m0 + r) * K + kof + c_ld);
        }
        #pragma unroll
        for (int i = 0; i < 4; i++) {
            int r = r_ld + i * 32;
            CP16(smem_u + (BOFF + s * ASTG + r * 36 + c_ld) * 4,
                 B + (size_t)(n0 + r) * K + kof + c_ld);
        }
    };

    loadTile(0, 0);
    CP_COMMIT();

    for (int it = 0; it < 32; it++) {
        int s = it & 1;
        if (it + 1 < 32) {
            loadTile(it + 1, s ^ 1);
            CP_COMMIT();
            CP_WAIT(1);
        } else {
            CP_WAIT(0);
        }
        __syncthreads();

        const float* As = dsm + s * ASTG;
        const float* Bs = dsm + BOFF + s * ASTG;
        #pragma unroll
        for (int ks = 0; ks < 4; ks++) {
            int kb = ks * 8;
            uint32_t a[4][4], b[4][2];
            #pragma unroll
            for (int i = 0; i < 4; i++) {
                a[i][0] = __float_as_uint(As[(mb + i * 16 + row) * 36 + kb + tig]);
                a[i][1] = __float_as_uint(As[(mb + i * 16 + row + 8) * 36 + kb + tig]);
                a[i][2] = __float_as_uint(As[(mb + i * 16 + row) * 36 + kb + tig + 4]);
                a[i][3] = __float_as_uint(As[(mb + i * 16 + row + 8) * 36 + kb + tig + 4]);
            }
            #pragma unroll
            for (int j = 0; j < 4; j++) {
                b[j][0] = __float_as_uint(Bs[(nb + j * 8 + row) * 36 + kb + tig]);
                b[j][1] = __float_as_uint(Bs[(nb + j * 8 + row) * 36 + kb + tig + 4]);
            }
            #pragma unroll
            for (int i = 0; i < 4; i++)
                #pragma unroll
                for (int j = 0; j < 4; j++)
                    MMA_TF32(acc[i][j], a[i], b[j]);
        }
        __syncthreads();
    }

    #pragma unroll
    for (int i = 0; i < 4; i++) {
        int gm = m0 + mb + i * 16 + row;
        #pragma unroll
        for (int j = 0; j < 4; j++) {
            int gn = n0 + nb + j * 8 + tig * 2;
            #pragma unroll
            for (int half = 0; half < 2; half++) {
                int m = gm + half * 8;
                size_t idx = (size_t)m * Dd + gn;
                float2 xv = *(const float2*)&xres[idx];
                *(float2*)&C[idx] = make_float2(
                    acc[i][j][half * 2] + bias[gn] + xv.x,
                    acc[i][j][half * 2 + 1] + bias[gn + 1] + xv.y);
            }
        }
    }
}

// ---------------------------------------------------------------------------
// Fused attention, no-max softmax, register-P pass B.
//  pass A: S = Q@K^T masked -> Z = sum(exp(0.125*s)) only. No gmem writes.
//  pass B: per warp-exclusive 16 rows: recompute S for all 64 keys/tile,
//          p = exp(s)*invZ -> write attn, permute acc->A-frag in registers,
//          O += P@V. One __syncthreads per tile.
// ---------------------------------------------------------------------------
__global__ __launch_bounds__(256, 2) void attn_fused(
    const float* __restrict__ Q, const float* __restrict__ Kk,
    const float* __restrict__ Vt, const int* __restrict__ mask,
    float* __restrict__ attn, float* __restrict__ O)
{
    extern __shared__ __align__(16) float dsm[];
    // floats: Q[128][68]@0
    // pass A: K dbuf [2][128][68]@8704 (stride 8704)
    // pass B: Kb [2][64][68]@8704 (stride 4352), Vb [2][64][68]@17408 (stride 4352)
    // WSS@26112[512], SMI@26624[128]
    const int KA = 8704, KB = 8704, VB = 17408;
    const int WSS = 26112, SMI = 26624;
    uint32_t smem_u = (uint32_t)__cvta_generic_to_shared(dsm);

    int tid = threadIdx.x;
    int bz = blockIdx.y;               // bh
    int m0 = blockIdx.x * 128;
    const float* Qp = Q  + (size_t)bz * Ss * DK;
    const float* Kp = Kk + (size_t)bz * Ss * DK;
    const float* Vp = Vt + (size_t)bz * DK * Ss;
    const int* mrow = mask + (size_t)(bz >> 4) * Ss * Ss;
    float* arow = attn + (size_t)bz * Ss * Ss;

    int lane = tid & 31, warp = tid >> 5;
    int wm = warp >> 2, wn = warp & 3;
    int row = lane >> 2, tig = lane & 3;
    int mbA = wm * 64;                 // pass A m-block (64 rows)
    int mbB = warp * 16;               // pass B m-block (16 rows, exclusive)
    int src0 = (lane & ~3) | (tig >> 1);

    // ---- load Q strip + first 128-key K tile ----
    #pragma unroll
    for (int i = 0; i < 8; i++) {
        int idx = tid + i * 256;
        int r = idx >> 4, c = (idx & 15) * 4;
        CP16(smem_u + (r * 68 + c) * 4, Qp + (size_t)(m0 + r) * DK + c);
    }
    #pragma unroll
    for (int i = 0; i < 8; i++) {
        int idx = tid + i * 256;
        int r = idx >> 4, c = (idx & 15) * 4;
        CP16(smem_u + (KA + r * 68 + c) * 4, Kp + (size_t)r * DK + c);
    }
    CP_COMMIT();

    float zs[8];
    #pragma unroll
    for (int s8 = 0; s8 < 8; s8++) zs[s8] = 0.0f;

    // ================= pass A: Z only =================
    for (int kt = 0; kt < 16; kt++) {
        CP_WAIT(0);
        __syncthreads();

        if (kt + 1 < 16) {
            int bo = KA + ((kt + 1) & 1) * 8704;
            #pragma unroll
            for (int i = 0; i < 8; i++) {
                int idx = tid + i * 256;
                int r = idx >> 4, c = (idx & 15) * 4;
                CP16(smem_u + (bo + r * 68 + c) * 4,
                     Kp + (size_t)((kt + 1) * 128 + r) * DK + c);
            }
            CP_COMMIT();
        }

        const float* Ksb = dsm + KA + (kt & 1) * 8704;
        float acc[4][4][4] = {};
        #pragma unroll
        for (int ks = 0; ks < 8; ks++) {
            int kb = ks * 8;
            uint32_t a[4][4], b[4][2];
            #pragma unroll
            for (int i = 0; i < 4; i++) {
                a[i][0] = __float_as_uint(dsm[(mbA + i * 16 + row) * 68 + kb + tig]);
                a[i][1] = __float_as_uint(dsm[(mbA + i * 16 + row + 8) * 68 + kb + tig]);
                a[i][2] = __float_as_uint(dsm[(mbA + i * 16 + row) * 68 + kb + tig + 4]);
                a[i][3] = __float_as_uint(dsm[(mbA + i * 16 + row + 8) * 68 + kb + tig + 4]);
            }
            #pragma unroll
            for (int j = 0; j < 4; j++) {
                b[j][0] = __float_as_uint(Ksb[(wn * 32 + j * 8 + row) * 68 + kb + tig]);
                b[j][1] = __float_as_uint(Ksb[(wn * 32 + j * 8 + row) * 68 + kb + tig + 4]);
            }
            #pragma unroll
            for (int i = 0; i < 4; i++)
                #pragma unroll
                for (int j = 0; j < 4; j++)
                    MMA_TF32(acc[i][j], a[i], b[j]);
        }

        // epilogue: masked exp-sum (no max)
        #pragma unroll
        for (int i = 0; i < 4; i++) {
            #pragma unroll
            for (int half = 0; half < 2; half++) {
                int s8 = i * 2 + half;
                int m = m0 + mbA + i * 16 + half * 8 + row;
                float se = 0.0f;
                #pragma unroll
                for (int j = 0; j < 4; j++) {
                    int gn = kt * 128 + wn * 32 + j * 8 + tig * 2;
                    int2 mv = *(const int2*)&mrow[(size_t)m * Ss + gn];
                    if (mv.x) se += __expf(acc[i][j][half * 2] * 0.125f);
                    if (mv.y) se += __expf(acc[i][j][half * 2 + 1] * 0.125f);
                }
                zs[s8] += se;
            }
        }
    }

    // quad-reduce (tig lanes share a row-slice), write per-warp partials
    #pragma unroll
    for (int s8 = 0; s8 < 8; s8++) {
        zs[s8] += __shfl_xor_sync(0xffffffffu, zs[s8], 1);
        zs[s8] += __shfl_xor_sync(0xffffffffu, zs[s8], 2);
    }
    if (tig == 0) {
        #pragma unroll
        for (int s8 = 0; s8 < 8; s8++) {
            int rloc = mbA + (s8 >> 1) * 16 + (s8 & 1) * 8 + row;
            dsm[WSS + rloc * 4 + wn] = zs[s8];
        }
    }
    __syncthreads();   // all warps done with pass A mma + WSS written

    // preload pass-B tile 0 (K -> KB buf0, V -> VB buf0)
    #pragma unroll
    for (int i = 0; i < 4; i++) {
        int idx = tid + i * 256;
        int r = idx >> 4, c = (idx & 15) * 4;
        CP16(smem_u + (KB + r * 68 + c) * 4, Kp + (size_t)r * DK + c);
        CP16(smem_u + (VB + r * 68 + c) * 4, Vp + (size_t)r * Ss + c);
    }
    CP_COMMIT();

    if (tid < 128) {
        float Z = dsm[WSS + tid * 4] + dsm[WSS + tid * 4 + 1] +
                  dsm[WSS + tid * 4 + 2] + dsm[WSS + tid * 4 + 3];
        dsm[SMI + tid] = 1.0f / Z;
    }
    __syncthreads();

    float invlo = dsm[SMI + mbB + row];
    float invhi = dsm[SMI + mbB + row + 8];

    // ================= pass B: recompute + normalize + P@V (register P) ====
    float oacc[8][4] = {};

    for (int t = 0; t < 32; t++) {
        CP_WAIT(0);
        __syncthreads();

        if (t + 1 < 32) {
            int kbo = KB + ((t + 1) & 1) * 4352;
            int vbo = VB + ((t + 1) & 1) * 4352;
            #pragma unroll
            for (int i = 0; i < 4; i++) {
                int idx = tid + i * 256;
                int r = idx >> 4, c = (idx & 15) * 4;
                CP16(smem_u + (kbo + r * 68 + c) * 4,
                     Kp + (size_t)((t + 1) * 64 + r) * DK + c);
                CP16(smem_u + (vbo + r * 68 + c) * 4,
                     Vp + (size_t)r * Ss + (t + 1) * 64 + c);
            }
            CP_COMMIT();
        }

        const float* Ks = dsm + KB + (t & 1) * 4352;
        const float* Vs = dsm + VB + (t & 1) * 4352;

        // --- S for all 64 keys of this tile, rows mbB..mbB+15 ---
        float sacc[8][4] = {};
        #pragma unroll
        for (int ks = 0; ks < 8; ks++) {
            int kb = ks * 8;
            uint32_t a[4], b[8][2];
            a[0] = __float_as_uint(dsm[(mbB + row) * 68 + kb + tig]);
            a[1] = __float_as_uint(dsm[(mbB + row + 8) * 68 + kb + tig]);
            a[2] = __float_as_uint(dsm[(mbB + row) * 68 + kb + tig + 4]);
            a[3] = __float_as_uint(dsm[(mbB + row + 8) * 68 + kb + tig + 4]);
            #pragma unroll
            for (int j = 0; j < 8; j++) {
                b[j][0] = __float_as_uint(Ks[(j * 8 + row) * 68 + kb + tig]);
                b[j][1] = __float_as_uint(Ks[(j * 8 + row) * 68 + kb + tig + 4]);
            }
            #pragma unroll
            for (int j = 0; j < 8; j++)
                MMA_TF32(sacc[j], a, b[j]);
        }

        // --- epilogue: p = exp(s)*invZ, write attn, keep tf32 p in sacc ---
        int mlo = m0 + mbB + row, mhi = mlo + 8;
        #pragma unroll
        for (int j = 0; j < 8; j++) {
            int gn = t * 64 + j * 8 + tig * 2;
            size_t i0 = (size_t)mlo * Ss + gn;
            size_t i1 = (size_t)mhi * Ss + gn;
            int2 v0 = *(const int2*)&mrow[i0];
            int2 v1 = *(const int2*)&mrow[i1];
            float p0 = v0.x ? __expf(sacc[j][0] * 0.125f) * invlo : 0.0f;
            float p1 = v0.y ? __expf(sacc[j][1] * 0.125f) * invlo : 0.0f;
            float p2 = v1.x ? __expf(sacc[j][2] * 0.125f) * invhi : 0.0f;
            float p3 = v1.y ? __expf(sacc[j][3] * 0.125f) * invhi : 0.0f;
            *(float2*)&arow[i0] = make_float2(p0, p1);
            *(float2*)&arow[i1] = make_float2(p2, p3);
            sacc[j][0] = f2tf32f(p0);
            sacc[j][1] = f2tf32f(p1);
            sacc[j][2] = f2tf32f(p2);
            sacc[j][3] = f2tf32f(p3);
        }

        // --- AV: permute acc->A-frag in registers, O += P@V ---
        #pragma unroll
        for (int jS = 0; jS < 8; jS++) {
            uint32_t c0 = __float_as_uint(sacc[jS][0]);
            uint32_t c1 = __float_as_uint(sacc[jS][1]);
            uint32_t c2 = __float_as_uint(sacc[jS][2]);
            uint32_t c3 = __float_as_uint(sacc[jS][3]);
            uint32_t a[4], x0, x1;
            x0 = __shfl_sync(0xffffffffu, c0, src0);
            x1 = __shfl_sync(0xffffffffu, c1, src0);
            a[0] = (tig & 1) ? x1 : x0;
            x0 = __shfl_sync(0xffffffffu, c2, src0);
            x1 = __shfl_sync(0xffffffffu, c3, src0);
            a[1] = (tig & 1) ? x1 : x0;
            x0 = __shfl_sync(0xffffffffu, c0, src0 + 2);
            x1 = __shfl_sync(0xffffffffu, c1, src0 + 2);
            a[2] = (tig & 1) ? x1 : x0;
            x0 = __shfl_sync(0xffffffffu, c2, src0 + 2);
            x1 = __shfl_sync(0xffffffffu, c3, src0 + 2);
            a[3] = (tig & 1) ? x1 : x0;

            int kb = jS * 8;
            #pragma unroll
            for (int j2 = 0; j2 < 8; j2++) {
                uint32_t b[2];
                b[0] = __float_as_uint(Vs[(j2 * 8 + row) * 68 + kb + tig]);
                b[1] = __float_as_uint(Vs[(j2 * 8 + row) * 68 + kb + tig + 4]);
                MMA_TF32(oacc[j2], a, b);
            }
        }
    }

    // ---- O epilogue ----
    int bi = bz >> 4, hh = bz & 15;
    int mlo = m0 + mbB + row;
    #pragma unroll
    for (int j2 = 0; j2 < 8; j2++) {
        int d = hh * 64 + j2 * 8 + tig * 2;
        *(float2*)&O[((size_t)bi * Ss + mlo) * Dd + d] =
            make_float2(f2tf32f(oacc[j2][0]), f2tf32f(oacc[j2][1]));
        *(float2*)&O[((size_t)bi * Ss + mlo + 8) * Dd + d] =
            make_float2(f2tf32f(oacc[j2][2]), f2tf32f(oacc[j2][3]));
    }
}

// ---------------------------------------------------------------------------
extern "C" void kernel_launch(void* const* d_in, const int* in_sizes, int n_in,
                              void* d_out, int out_size)
{
    const float* x    = (const float*)d_in[0];
    const int*   mask = (const int*)d_in[1];
    const float* ln_a = (const float*)d_in[2];
    const float* ln_b = (const float*)d_in[3];
    const float* wq_w = (const float*)d_in[4];
    const float* wq_b = (const float*)d_in[5];
    const float* wk_w = (const float*)d_in[6];
    const float* wk_b = (const float*)d_in[7];
    const float* wv_w = (const float*)d_in[8];
    const float* wv_b = (const float*)d_in[9];
    const float* fc_w = (const float*)d_in[10];
    const float* fc_b = (const float*)d_in[11];
    float* out = (float*)d_out;

    void *ph, *pq, *pk, *pvt, *po, *pwq, *pwk, *pwv, *pwf;
    cudaGetSymbolAddress(&ph,  g_h);
    cudaGetSymbolAddress(&pq,  g_q);
    cudaGetSymbolAddress(&pk,  g_k);
    cudaGetSymbolAddress(&pvt, g_vt);
    cudaGetSymbolAddress(&po,  g_o);
    cudaGetSymbolAddress(&pwq, g_wq);
    cudaGetSymbolAddress(&pwk, g_wk);
    cudaGetSymbolAddress(&pwv, g_wv);
    cudaGetSymbolAddress(&pwf, g_wf);
    float* h   = (float*)ph;
    float* q   = (float*)pq;
    float* k   = (float*)pk;
    float* vt  = (float*)pvt;
    float* o   = (float*)po;

    float* attn = out + OUT_ELEMS;

    const int DSM_G = 73728;
    const int DSM_A = 26752 * 4;   // 107008
    cudaFuncSetAttribute(gemm_qkv, cudaFuncAttributeMaxDynamicSharedMemorySize, DSM_G);
    cudaFuncSetAttribute(gemm_fc,  cudaFuncAttributeMaxDynamicSharedMemorySize, DSM_G);
    cudaFuncSetAttribute(attn_fused, cudaFuncAttributeMaxDynamicSharedMemorySize, DSM_A);

    // 0. Pre-round weights to tf32
    wround_kernel<<<1024, 256>>>(wq_w, (float*)pwq);
    wround_kernel<<<1024, 256>>>(wk_w, (float*)pwk);
    wround_kernel<<<1024, 256>>>(wv_w, (float*)pwv);
    wround_kernel<<<1024, 256>>>(fc_w, (float*)pwf);

    // 1. LayerNorm
    ln_kernel<<<Bb * Ss, 256>>>(x, ln_a, ln_b, h);

    // 2. QKV projections (single launch, z selects weight)
    gemm_qkv<<<dim3(8, 64, 3), 256, DSM_G>>>(
        h, (float*)pwq, (float*)pwk, (float*)pwv,
        wq_b, wk_b, wv_b, q, k, vt);

    // 3+4+5. Fused attention (no-max softmax, register P)
    attn_fused<<<dim3(16, Bb * Hh), 256, DSM_A>>>(q, k, vt, mask, attn, o);

    // 6. FC + bias + residual
    gemm_fc<<<dim3(8, 64), 256, DSM_G>>>(o, (float*)pwf, fc_b, x, out);
}

// round 9
// speedup vs baseline: 4.4570x; 1.5903x over previous
#include <cuda_runtime.h>
#include <cuda_fp16.h>
#include <math.h>
#include <stdint.h>

#define Bb 4
#define Ss 2048
#define Dd 1024
#define Hh 16
#define DK 64

static const size_t OUT_ELEMS = (size_t)Bb * Ss * Dd;   // 8388608

// Scratch (device globals — allocation-free per harness rules)
__device__ __half g_h[(size_t)Bb * Ss * Dd];
__device__ __half g_q[(size_t)Bb * Hh * Ss * DK];
__device__ __half g_k[(size_t)Bb * Hh * Ss * DK];
__device__ __half g_vt[(size_t)Bb * Hh * DK * Ss];  // V^T: [bh][d][s]
__device__ __half g_o[(size_t)Bb * Ss * Dd];
__device__ __half g_wq[(size_t)Dd * Dd];
__device__ __half g_wk[(size_t)Dd * Dd];
__device__ __half g_wv[(size_t)Dd * Dd];
__device__ __half g_wf[(size_t)Dd * Dd];

// ---------------------------------------------------------------------------
#define CP16(dst_u32, src_ptr) \
    asm volatile("cp.async.cg.shared.global [%0], [%1], 16;\n" :: "r"(dst_u32), "l"(src_ptr))
#define CP_COMMIT() asm volatile("cp.async.commit_group;\n" ::)
#define CP_WAIT(N)  asm volatile("cp.async.wait_group %0;\n" :: "n"(N))

#define MMA_F16(acc, a, b) \
    asm volatile( \
        "mma.sync.aligned.m16n8k16.row.col.f32.f16.f16.f32 " \
        "{%0,%1,%2,%3}, {%4,%5,%6,%7}, {%8,%9}, {%0,%1,%2,%3};" \
        : "+f"(acc[0]), "+f"(acc[1]), "+f"(acc[2]), "+f"(acc[3]) \
        : "r"(a[0]), "r"(a[1]), "r"(a[2]), "r"(a[3]), "r"(b[0]), "r"(b[1]))

__device__ __forceinline__ uint32_t ldh2(const __half* p) {
    return *(const uint32_t*)p;
}
__device__ __forceinline__ uint32_t packh2(float lo, float hi) {
    __half2 h = __floats2half2_rn(lo, hi);
    return *(uint32_t*)&h;
}

__device__ __forceinline__ float blockReduceSum(float val) {
    __shared__ float sh[32];
    int lane = threadIdx.x & 31, wid = threadIdx.x >> 5;
    #pragma unroll
    for (int o = 16; o; o >>= 1) val += __shfl_down_sync(0xffffffffu, val, o);
    if (lane == 0) sh[wid] = val;
    __syncthreads();
    val = (threadIdx.x < 8) ? sh[lane] : 0.0f;
    if (wid == 0) {
        #pragma unroll
        for (int o = 4; o; o >>= 1) val += __shfl_down_sync(0xffffffffu, val, o);
    }
    __syncthreads();
    return val;
}

// ---------------------------------------------------------------------------
// LayerNorm — writes fp16 h
// ---------------------------------------------------------------------------
__global__ __launch_bounds__(256) void ln_kernel(
    const float* __restrict__ x, const float* __restrict__ a,
    const float* __restrict__ bvec, __half* __restrict__ h)
{
    int row = blockIdx.x;
    const float4* xr = (const float4*)(x + (size_t)row * Dd);
    float4 v = xr[threadIdx.x];

    float s = blockReduceSum(v.x + v.y + v.z + v.w);
    __shared__ float mean_s, inv_s;
    if (threadIdx.x == 0) mean_s = s * (1.0f / Dd);
    __syncthreads();
    float mean = mean_s;

    float dx = v.x - mean, dy = v.y - mean, dz = v.z - mean, dw = v.w - mean;
    float sq = blockReduceSum(dx * dx + dy * dy + dz * dz + dw * dw);
    if (threadIdx.x == 0) inv_s = 1.0f / (sqrtf(sq * (1.0f / (Dd - 1))) + 1e-6f);
    __syncthreads();
    float inv = inv_s;

    float4 av = ((const float4*)a)[threadIdx.x];
    float4 bv = ((const float4*)bvec)[threadIdx.x];
    uint2 o;
    o.x = packh2(av.x * dx * inv + bv.x, av.y * dy * inv + bv.y);
    o.y = packh2(av.z * dz * inv + bv.z, av.w * dw * inv + bv.w);
    *(uint2*)(h + (size_t)row * Dd + threadIdx.x * 4) = o;
}

// ---------------------------------------------------------------------------
// Weight conversion fp32 -> fp16
// ---------------------------------------------------------------------------
__global__ __launch_bounds__(256) void whalf_kernel(
    const float* __restrict__ src, __half* __restrict__ dst)
{
    int i = blockIdx.x * 256 + threadIdx.x;
    float4 v = ((const float4*)src)[i];
    uint2 o;
    o.x = packh2(v.x, v.y);
    o.y = packh2(v.z, v.w);
    *(uint2*)(dst + (size_t)i * 4) = o;
}

// ---------------------------------------------------------------------------
// fp16 GEMM core: C = A(MxK half) @ B(NxK half)^T, BM=128, BN=128, BK=64,
// cp.async double-buffered. 8 warps (2x4), warp tile 64x32.
// Tiles stored [r][72] halves (stride-72 => conflict-free fragments).
// MODE 0/1/2 = Q/K/V proj epilogues, MODE 4 = FC (+bias+residual fp32 out).
// ---------------------------------------------------------------------------
template<int MODE>
__global__ __launch_bounds__(256, 2) void gemm_h(
    const __half* __restrict__ A, const __half* __restrict__ B,
    const float* __restrict__ bias, const float* __restrict__ xres,
    void* __restrict__ Cv)
{
    extern __shared__ __align__(16) __half hsm[];
    // A dbuf: 2 x 128x72 @0 (stride 9216), B dbuf @18432
    const int AST = 9216, BOFF = 18432;
    uint32_t smem_u = (uint32_t)__cvta_generic_to_shared(hsm);

    const int K = Dd;
    int tid = threadIdx.x;
    int m0 = blockIdx.y * 128, n0 = blockIdx.x * 128;
    int lane = tid & 31, warp = tid >> 5;
    int wm = warp >> 2, wn = warp & 3;
    int g = lane >> 2, tig = lane & 3;
    int mb = wm * 64, nb = wn * 32;

    float acc[4][4][4] = {};

    // loads: 128x64 halves = 1024 16B-chunks, 4 per thread
    int r_ld = tid >> 3;            // 0..31
    int c_ld = (tid & 7) * 8;       // half offset 0..56

    auto loadTile = [&](int kt, int s) {
        int kof = kt * 64;
        #pragma unroll
        for (int i = 0; i < 4; i++) {
            int r = r_ld + i * 32;
            CP16(smem_u + (s * AST + r * 72 + c_ld) * 2,
                 A + (size_t)(m0 + r) * K + kof + c_ld);
        }
        #pragma unroll
        for (int i = 0; i < 4; i++) {
            int r = r_ld + i * 32;
            CP16(smem_u + (BOFF + s * AST + r * 72 + c_ld) * 2,
                 B + (size_t)(n0 + r) * K + kof + c_ld);
        }
    };

    loadTile(0, 0);
    CP_COMMIT();

    for (int it = 0; it < 16; it++) {
        int s = it & 1;
        if (it + 1 < 16) {
            loadTile(it + 1, s ^ 1);
            CP_COMMIT();
            CP_WAIT(1);
        } else {
            CP_WAIT(0);
        }
        __syncthreads();

        const __half* As = hsm + s * AST;
        const __half* Bs = hsm + BOFF + s * AST;
        #pragma unroll
        for (int ks = 0; ks < 4; ks++) {
            int kb = ks * 16;
            uint32_t a[4][4], b[4][2];
            #pragma unroll
            for (int i = 0; i < 4; i++) {
                a[i][0] = ldh2(&As[(mb + i * 16 + g) * 72 + kb + tig * 2]);
                a[i][1] = ldh2(&As[(mb + i * 16 + g + 8) * 72 + kb + tig * 2]);
                a[i][2] = ldh2(&As[(mb + i * 16 + g) * 72 + kb + tig * 2 + 8]);
                a[i][3] = ldh2(&As[(mb + i * 16 + g + 8) * 72 + kb + tig * 2 + 8]);
            }
            #pragma unroll
            for (int j = 0; j < 4; j++) {
                b[j][0] = ldh2(&Bs[(nb + j * 8 + g) * 72 + kb + tig * 2]);
                b[j][1] = ldh2(&Bs[(nb + j * 8 + g) * 72 + kb + tig * 2 + 8]);
            }
            #pragma unroll
            for (int i = 0; i < 4; i++)
                #pragma unroll
                for (int j = 0; j < 4; j++)
                    MMA_F16(acc[i][j], a[i], b[j]);
        }
        __syncthreads();
    }

    #pragma unroll
    for (int i = 0; i < 4; i++) {
        int gm = m0 + mb + i * 16 + g;
        #pragma unroll
        for (int j = 0; j < 4; j++) {
            int gn = n0 + nb + j * 8 + tig * 2;
            #pragma unroll
            for (int half_ = 0; half_ < 2; half_++) {
                int m = gm + half_ * 8;
                float v0 = acc[i][j][half_ * 2];
                float v1 = acc[i][j][half_ * 2 + 1];
                if (MODE == 4) {
                    float* C = (float*)Cv;
                    size_t idx = (size_t)m * Dd + gn;
                    float2 xv = *(const float2*)&xres[idx];
                    *(float2*)&C[idx] = make_float2(v0 + bias[gn] + xv.x,
                                                    v1 + bias[gn + 1] + xv.y);
                } else {
                    __half* C = (__half*)Cv;
                    int bi = m >> 11, s2 = m & (Ss - 1);
                    int hh = gn >> 6, d = gn & 63;
                    if (MODE < 2) {
                        uint32_t pv = packh2(v0 + bias[gn], v1 + bias[gn + 1]);
                        *(uint32_t*)&C[(((size_t)(bi * Hh + hh) * Ss) + s2) * DK + d] = pv;
                    } else {
                        size_t base = ((size_t)(bi * Hh + hh) * DK + d) * Ss + s2;
                        C[base]      = __float2half(v0 + bias[gn]);
                        C[base + Ss] = __float2half(v1 + bias[gn + 1]);
                    }
                }
            }
        }
    }
}

// ---------------------------------------------------------------------------
// Fused attention, fp16 mma, no-max softmax, register-P pass B.
// ---------------------------------------------------------------------------
__global__ __launch_bounds__(256, 2) void attn_fused(
    const __half* __restrict__ Q, const __half* __restrict__ Kk,
    const __half* __restrict__ Vt, const int* __restrict__ mask,
    float* __restrict__ attn, __half* __restrict__ O)
{
    extern __shared__ __align__(16) __half hsm[];
    float* fsm = (float*)hsm;
    // halves: Q[128][72]@0; pass A K dbuf 2x[128][72]@9216 (stride 9216);
    // pass B: Kb 2x[64][72]@9216 (stride 4608), Vb 2x[64][72]@18432 (stride 4608)
    // floats (beyond half idx 27648 = byte 55296): WSS@13824[512], SMI@14336[128]
    const int KA = 9216, KB = 9216, VB = 18432;
    const int WSS = 13824, SMI = 14336;
    uint32_t smem_u = (uint32_t)__cvta_generic_to_shared(hsm);

    int tid = threadIdx.x;
    int bz = blockIdx.y;               // bh
    int m0 = blockIdx.x * 128;
    const __half* Qp = Q  + (size_t)bz * Ss * DK;
    const __half* Kp = Kk + (size_t)bz * Ss * DK;
    const __half* Vp = Vt + (size_t)bz * DK * Ss;
    const int* mrow = mask + (size_t)(bz >> 4) * Ss * Ss;
    float* arow = attn + (size_t)bz * Ss * Ss;

    int lane = tid & 31, warp = tid >> 5;
    int wm = warp >> 2, wn = warp & 3;
    int g = lane >> 2, tig = lane & 3;
    int mbA = wm * 64;
    int mbB = warp * 16;

    // ---- load Q strip + first K tile: 128 rows x 64 halves = 1024 chunks ----
    #pragma unroll
    for (int i = 0; i < 4; i++) {
        int idx = tid + i * 256;
        int r = idx >> 3, c = (idx & 7) * 8;
        CP16(smem_u + (r * 72 + c) * 2, Qp + (size_t)(m0 + r) * DK + c);
    }
    #pragma unroll
    for (int i = 0; i < 4; i++) {
        int idx = tid + i * 256;
        int r = idx >> 3, c = (idx & 7) * 8;
        CP16(smem_u + (KA + r * 72 + c) * 2, Kp + (size_t)r * DK + c);
    }
    CP_COMMIT();

    float zs[8];
    #pragma unroll
    for (int s8 = 0; s8 < 8; s8++) zs[s8] = 0.0f;

    // ================= pass A: Z only =================
    for (int kt = 0; kt < 16; kt++) {
        CP_WAIT(0);
        __syncthreads();

        if (kt + 1 < 16) {
            int bo = KA + ((kt + 1) & 1) * 9216;
            #pragma unroll
            for (int i = 0; i < 4; i++) {
                int idx = tid + i * 256;
                int r = idx >> 3, c = (idx & 7) * 8;
                CP16(smem_u + (bo + r * 72 + c) * 2,
                     Kp + (size_t)((kt + 1) * 128 + r) * DK + c);
            }
            CP_COMMIT();
        }

        const __half* Ksb = hsm + KA + (kt & 1) * 9216;
        float acc[4][4][4] = {};
        #pragma unroll
        for (int ks = 0; ks < 4; ks++) {
            int kb = ks * 16;
            uint32_t a[4][4], b[4][2];
            #pragma unroll
            for (int i = 0; i < 4; i++) {
                a[i][0] = ldh2(&hsm[(mbA + i * 16 + g) * 72 + kb + tig * 2]);
                a[i][1] = ldh2(&hsm[(mbA + i * 16 + g + 8) * 72 + kb + tig * 2]);
                a[i][2] = ldh2(&hsm[(mbA + i * 16 + g) * 72 + kb + tig * 2 + 8]);
                a[i][3] = ldh2(&hsm[(mbA + i * 16 + g + 8) * 72 + kb + tig * 2 + 8]);
            }
            #pragma unroll
            for (int j = 0; j < 4; j++) {
                b[j][0] = ldh2(&Ksb[(wn * 32 + j * 8 + g) * 72 + kb + tig * 2]);
                b[j][1] = ldh2(&Ksb[(wn * 32 + j * 8 + g) * 72 + kb + tig * 2 + 8]);
            }
            #pragma unroll
            for (int i = 0; i < 4; i++)
                #pragma unroll
                for (int j = 0; j < 4; j++)
                    MMA_F16(acc[i][j], a[i], b[j]);
        }

        // epilogue: masked exp-sum (no max)
        #pragma unroll
        for (int i = 0; i < 4; i++) {
            #pragma unroll
            for (int half_ = 0; half_ < 2; half_++) {
                int s8 = i * 2 + half_;
                int m = m0 + mbA + i * 16 + half_ * 8 + g;
                float se = 0.0f;
                #pragma unroll
                for (int j = 0; j < 4; j++) {
                    int gn = kt * 128 + wn * 32 + j * 8 + tig * 2;
                    int2 mv = *(const int2*)&mrow[(size_t)m * Ss + gn];
                    if (mv.x) se += __expf(acc[i][j][half_ * 2] * 0.125f);
                    if (mv.y) se += __expf(acc[i][j][half_ * 2 + 1] * 0.125f);
                }
                zs[s8] += se;
            }
        }
    }

    // quad-reduce, per-warp partials
    #pragma unroll
    for (int s8 = 0; s8 < 8; s8++) {
        zs[s8] += __shfl_xor_sync(0xffffffffu, zs[s8], 1);
        zs[s8] += __shfl_xor_sync(0xffffffffu, zs[s8], 2);
    }
    if (tig == 0) {
        #pragma unroll
        for (int s8 = 0; s8 < 8; s8++) {
            int rloc = mbA + (s8 >> 1) * 16 + (s8 & 1) * 8 + g;
            fsm[WSS + rloc * 4 + wn] = zs[s8];
        }
    }
    __syncthreads();

    // preload pass-B tile 0 (K, V: 64 rows x 64 halves = 512 chunks each)
    #pragma unroll
    for (int i = 0; i < 2; i++) {
        int idx = tid + i * 256;
        int r = idx >> 3, c = (idx & 7) * 8;
        CP16(smem_u + (KB + r * 72 + c) * 2, Kp + (size_t)r * DK + c);
        CP16(smem_u + (VB + r * 72 + c) * 2, Vp + (size_t)r * Ss + c);
    }
    CP_COMMIT();

    if (tid < 128) {
        float Z = fsm[WSS + tid * 4] + fsm[WSS + tid * 4 + 1] +
                  fsm[WSS + tid * 4 + 2] + fsm[WSS + tid * 4 + 3];
        fsm[SMI + tid] = 1.0f / Z;
    }
    __syncthreads();

    float invlo = fsm[SMI + mbB + g];
    float invhi = fsm[SMI + mbB + g + 8];

    // ================= pass B =================
    float oacc[8][4] = {};

    for (int tt = 0; tt < 32; tt++) {
        CP_WAIT(0);
        __syncthreads();

        if (tt + 1 < 32) {
            int kbo = KB + ((tt + 1) & 1) * 4608;
            int vbo = VB + ((tt + 1) & 1) * 4608;
            #pragma unroll
            for (int i = 0; i < 2; i++) {
                int idx = tid + i * 256;
                int r = idx >> 3, c = (idx & 7) * 8;
                CP16(smem_u + (kbo + r * 72 + c) * 2,
                     Kp + (size_t)((tt + 1) * 64 + r) * DK + c);
                CP16(smem_u + (vbo + r * 72 + c) * 2,
                     Vp + (size_t)r * Ss + (tt + 1) * 64 + c);
            }
            CP_COMMIT();
        }

        const __half* Ks = hsm + KB + (tt & 1) * 4608;
        const __half* Vs = hsm + VB + (tt & 1) * 4608;

        // --- S for all 64 keys, warp-exclusive rows mbB..mbB+15 ---
        float sacc[8][4] = {};
        #pragma unroll
        for (int ks = 0; ks < 4; ks++) {
            int kb = ks * 16;
            uint32_t a[4], b[8][2];
            a[0] = ldh2(&hsm[(mbB + g) * 72 + kb + tig * 2]);
            a[1] = ldh2(&hsm[(mbB + g + 8) * 72 + kb + tig * 2]);
            a[2] = ldh2(&hsm[(mbB + g) * 72 + kb + tig * 2 + 8]);
            a[3] = ldh2(&hsm[(mbB + g + 8) * 72 + kb + tig * 2 + 8]);
            #pragma unroll
            for (int j = 0; j < 8; j++) {
                b[j][0] = ldh2(&Ks[(j * 8 + g) * 72 + kb + tig * 2]);
                b[j][1] = ldh2(&Ks[(j * 8 + g) * 72 + kb + tig * 2 + 8]);
            }
            #pragma unroll
            for (int j = 0; j < 8; j++)
                MMA_F16(sacc[j], a, b[j]);
        }

        // --- epilogue: p = exp(0.125*s)*invZ; write attn; keep p in sacc ---
        int mlo = m0 + mbB + g, mhi = mlo + 8;
        #pragma unroll
        for (int j = 0; j < 8; j++) {
            int gn = tt * 64 + j * 8 + tig * 2;
            size_t i0 = (size_t)mlo * Ss + gn;
            size_t i1 = (size_t)mhi * Ss + gn;
            int2 v0 = *(const int2*)&mrow[i0];
            int2 v1 = *(const int2*)&mrow[i1];
            float p0 = v0.x ? __expf(sacc[j][0] * 0.125f) * invlo : 0.0f;
            float p1 = v0.y ? __expf(sacc[j][1] * 0.125f) * invlo : 0.0f;
            float p2 = v1.x ? __expf(sacc[j][2] * 0.125f) * invhi : 0.0f;
            float p3 = v1.y ? __expf(sacc[j][3] * 0.125f) * invhi : 0.0f;
            *(float2*)&arow[i0] = make_float2(p0, p1);
            *(float2*)&arow[i1] = make_float2(p2, p3);
            sacc[j][0] = p0; sacc[j][1] = p1;
            sacc[j][2] = p2; sacc[j][3] = p3;
        }

        // --- AV: pack S-frag -> A-frag in registers (no shuffles) ---
        #pragma unroll
        for (int q = 0; q < 4; q++) {
            uint32_t a[4];
            a[0] = packh2(sacc[2 * q][0],     sacc[2 * q][1]);
            a[1] = packh2(sacc[2 * q][2],     sacc[2 * q][3]);
            a[2] = packh2(sacc[2 * q + 1][0], sacc[2 * q + 1][1]);
            a[3] = packh2(sacc[2 * q + 1][2], sacc[2 * q + 1][3]);

            int kb = q * 16;
            #pragma unroll
            for (int j2 = 0; j2 < 8; j2++) {
                uint32_t b[2];
                b[0] = ldh2(&Vs[(j2 * 8 + g) * 72 + kb + tig * 2]);
                b[1] = ldh2(&Vs[(j2 * 8 + g) * 72 + kb + tig * 2 + 8]);
                MMA_F16(oacc[j2], a, b);
            }
        }
    }

    // ---- O epilogue (fp16 O feeds FC) ----
    int bi = bz >> 4, hh = bz & 15;
    int mlo = m0 + mbB + g;
    #pragma unroll
    for (int j2 = 0; j2 < 8; j2++) {
        int d = hh * 64 + j2 * 8 + tig * 2;
        *(uint32_t*)&O[((size_t)bi * Ss + mlo) * Dd + d] =
            packh2(oacc[j2][0], oacc[j2][1]);
        *(uint32_t*)&O[((size_t)bi * Ss + mlo + 8) * Dd + d] =
            packh2(oacc[j2][2], oacc[j2][3]);
    }
}

// ---------------------------------------------------------------------------
extern "C" void kernel_launch(void* const* d_in, const int* in_sizes, int n_in,
                              void* d_out, int out_size)
{
    const float* x    = (const float*)d_in[0];
    const int*   mask = (const int*)d_in[1];
    const float* ln_a = (const float*)d_in[2];
    const float* ln_b = (const float*)d_in[3];
    const float* wq_w = (const float*)d_in[4];
    const float* wq_b = (const float*)d_in[5];
    const float* wk_w = (const float*)d_in[6];
    const float* wk_b = (const float*)d_in[7];
    const float* wv_w = (const float*)d_in[8];
    const float* wv_b = (const float*)d_in[9];
    const float* fc_w = (const float*)d_in[10];
    const float* fc_b = (const float*)d_in[11];
    float* out = (float*)d_out;

    void *ph, *pq, *pk, *pvt, *po, *pwq, *pwk, *pwv, *pwf;
    cudaGetSymbolAddress(&ph,  g_h);
    cudaGetSymbolAddress(&pq,  g_q);
    cudaGetSymbolAddress(&pk,  g_k);
    cudaGetSymbolAddress(&pvt, g_vt);
    cudaGetSymbolAddress(&po,  g_o);
    cudaGetSymbolAddress(&pwq, g_wq);
    cudaGetSymbolAddress(&pwk, g_wk);
    cudaGetSymbolAddress(&pwv, g_wv);
    cudaGetSymbolAddress(&pwf, g_wf);
    __half* h   = (__half*)ph;
    __half* q   = (__half*)pq;
    __half* k   = (__half*)pk;
    __half* vt  = (__half*)pvt;
    __half* o   = (__half*)po;

    float* attn = out + OUT_ELEMS;

    const int DSM_G = 73728;       // gemm smem bytes
    const int DSM_A = 57856;       // attn smem bytes
    cudaFuncSetAttribute(gemm_h<0>, cudaFuncAttributeMaxDynamicSharedMemorySize, DSM_G);
    cudaFuncSetAttribute(gemm_h<1>, cudaFuncAttributeMaxDynamicSharedMemorySize, DSM_G);
    cudaFuncSetAttribute(gemm_h<2>, cudaFuncAttributeMaxDynamicSharedMemorySize, DSM_G);
    cudaFuncSetAttribute(gemm_h<4>, cudaFuncAttributeMaxDynamicSharedMemorySize, DSM_G);
    cudaFuncSetAttribute(attn_fused, cudaFuncAttributeMaxDynamicSharedMemorySize, DSM_A);

    // 0. Weights -> fp16
    whalf_kernel<<<1024, 256>>>(wq_w, (__half*)pwq);
    whalf_kernel<<<1024, 256>>>(wk_w, (__half*)pwk);
    whalf_kernel<<<1024, 256>>>(wv_w, (__half*)pwv);
    whalf_kernel<<<1024, 256>>>(fc_w, (__half*)pwf);

    // 1. LayerNorm (fp16 out)
    ln_kernel<<<Bb * Ss, 256>>>(x, ln_a, ln_b, h);

    // 2. QKV projections
    gemm_h<0><<<dim3(8, 64), 256, DSM_G>>>(h, (__half*)pwq, wq_b, nullptr, q);
    gemm_h<1><<<dim3(8, 64), 256, DSM_G>>>(h, (__half*)pwk, wk_b, nullptr, k);
    gemm_h<2><<<dim3(8, 64), 256, DSM_G>>>(h, (__half*)pwv, wv_b, nullptr, vt);

    // 3+4+5. Fused attention
    attn_fused<<<dim3(16, Bb * Hh), 256, DSM_A>>>(q, k, vt, mask, attn, o);

    // 6. FC + bias + residual
    gemm_h<4><<<dim3(8, 64), 256, DSM_G>>>(o, (__half*)pwf, fc_b, x, out);
}

// round 10
// speedup vs baseline: 4.8608x; 1.0906x over previous
#include <cuda_runtime.h>
#include <cuda_fp16.h>
#include <math.h>
#include <stdint.h>

#define Bb 4
#define Ss 2048
#define Dd 1024
#define Hh 16
#define DK 64

static const size_t OUT_ELEMS = (size_t)Bb * Ss * Dd;   // 8388608

// Scratch (device globals — allocation-free per harness rules)
__device__ __half g_h[(size_t)Bb * Ss * Dd];
__device__ __half g_q[(size_t)Bb * Hh * Ss * DK];
__device__ __half g_k[(size_t)Bb * Hh * Ss * DK];
__device__ __half g_vt[(size_t)Bb * Hh * DK * Ss];  // V^T: [bh][d][s]
__device__ __half g_o[(size_t)Bb * Ss * Dd];
__device__ __half g_wq[(size_t)Dd * Dd];
__device__ __half g_wk[(size_t)Dd * Dd];
__device__ __half g_wv[(size_t)Dd * Dd];
__device__ __half g_wf[(size_t)Dd * Dd];

// ---------------------------------------------------------------------------
#define CP16(dst_u32, src_ptr) \
    asm volatile("cp.async.cg.shared.global [%0], [%1], 16;\n" :: "r"(dst_u32), "l"(src_ptr))
#define CP_COMMIT() asm volatile("cp.async.commit_group;\n" ::)
#define CP_WAIT(N)  asm volatile("cp.async.wait_group %0;\n" :: "n"(N))

#define MMA_F16(acc, a, b) \
    asm volatile( \
        "mma.sync.aligned.m16n8k16.row.col.f32.f16.f16.f32 " \
        "{%0,%1,%2,%3}, {%4,%5,%6,%7}, {%8,%9}, {%0,%1,%2,%3};" \
        : "+f"(acc[0]), "+f"(acc[1]), "+f"(acc[2]), "+f"(acc[3]) \
        : "r"(a[0]), "r"(a[1]), "r"(a[2]), "r"(a[3]), "r"(b[0]), "r"(b[1]))

#define LDSM4(R0, R1, R2, R3, ADDR) \
    asm volatile("ldmatrix.sync.aligned.m8n8.x4.shared.b16 {%0,%1,%2,%3}, [%4];" \
        : "=r"(R0), "=r"(R1), "=r"(R2), "=r"(R3) : "r"(ADDR))

__device__ __forceinline__ uint32_t packh2(float lo, float hi) {
    __half2 h = __floats2half2_rn(lo, hi);
    return *(uint32_t*)&h;
}

__device__ __forceinline__ float blockReduceSum(float val) {
    __shared__ float sh[32];
    int lane = threadIdx.x & 31, wid = threadIdx.x >> 5;
    #pragma unroll
    for (int o = 16; o; o >>= 1) val += __shfl_down_sync(0xffffffffu, val, o);
    if (lane == 0) sh[wid] = val;
    __syncthreads();
    val = (threadIdx.x < 8) ? sh[lane] : 0.0f;
    if (wid == 0) {
        #pragma unroll
        for (int o = 4; o; o >>= 1) val += __shfl_down_sync(0xffffffffu, val, o);
    }
    __syncthreads();
    return val;
}

// ---------------------------------------------------------------------------
// LayerNorm — writes fp16 h
// ---------------------------------------------------------------------------
__global__ __launch_bounds__(256) void ln_kernel(
    const float* __restrict__ x, const float* __restrict__ a,
    const float* __restrict__ bvec, __half* __restrict__ h)
{
    int row = blockIdx.x;
    const float4* xr = (const float4*)(x + (size_t)row * Dd);
    float4 v = xr[threadIdx.x];

    float s = blockReduceSum(v.x + v.y + v.z + v.w);
    __shared__ float mean_s, inv_s;
    if (threadIdx.x == 0) mean_s = s * (1.0f / Dd);
    __syncthreads();
    float mean = mean_s;

    float dx = v.x - mean, dy = v.y - mean, dz = v.z - mean, dw = v.w - mean;
    float sq = blockReduceSum(dx * dx + dy * dy + dz * dz + dw * dw);
    if (threadIdx.x == 0) inv_s = 1.0f / (sqrtf(sq * (1.0f / (Dd - 1))) + 1e-6f);
    __syncthreads();
    float inv = inv_s;

    float4 av = ((const float4*)a)[threadIdx.x];
    float4 bv = ((const float4*)bvec)[threadIdx.x];
    uint2 o;
    o.x = packh2(av.x * dx * inv + bv.x, av.y * dy * inv + bv.y);
    o.y = packh2(av.z * dz * inv + bv.z, av.w * dw * inv + bv.w);
    *(uint2*)(h + (size_t)row * Dd + threadIdx.x * 4) = o;
}

__global__ __launch_bounds__(256) void whalf_kernel(
    const float* __restrict__ src, __half* __restrict__ dst)
{
    int i = blockIdx.x * 256 + threadIdx.x;
    float4 v = ((const float4*)src)[i];
    uint2 o;
    o.x = packh2(v.x, v.y);
    o.y = packh2(v.z, v.w);
    *(uint2*)(dst + (size_t)i * 4) = o;
}

// ---------------------------------------------------------------------------
// fp16 GEMM core (ldmatrix fragments). BM=128, BN=128, BK=64, 8 warps.
// QKV==1: blockIdx.z selects Q/K/V weight + scatter epilogue.
// QKV==0: FC (+bias+residual, fp32 out).
// ---------------------------------------------------------------------------
template<int QKV>
__global__ __launch_bounds__(256, 2) void gemm_h(
    const __half* __restrict__ A,
    const __half* __restrict__ w0, const __half* __restrict__ w1,
    const __half* __restrict__ w2,
    const float* __restrict__ b0, const float* __restrict__ b1,
    const float* __restrict__ b2,
    const float* __restrict__ xres,
    void* __restrict__ c0, void* __restrict__ c1, void* __restrict__ c2)
{
    extern __shared__ __align__(16) __half hsm[];
    const int AST = 9216, BOFF = 18432;    // half units
    uint32_t smem_u = (uint32_t)__cvta_generic_to_shared(hsm);

    int z = QKV ? blockIdx.z : 0;
    const __half* B    = (z == 0) ? w0 : (z == 1) ? w1 : w2;
    const float* bias  = (z == 0) ? b0 : (z == 1) ? b1 : b2;

    const int K = Dd;
    int tid = threadIdx.x;
    int m0 = blockIdx.y * 128, n0 = blockIdx.x * 128;
    int lane = tid & 31, warp = tid >> 5;
    int wm = warp >> 2, wn = warp & 3;
    int g = lane >> 2, tig = lane & 3;
    int mb = wm * 64, nb = wn * 32;

    // ldmatrix lane-address components (half units)
    int aRow = lane & 15;
    int aCol = (lane >> 4) << 3;
    int bRow = ((lane >> 4) << 3) + (lane & 7);
    int bCol = ((lane >> 3) & 1) << 3;

    float acc[4][4][4] = {};

    int r_ld = tid >> 3;
    int c_ld = (tid & 7) * 8;

    auto loadTile = [&](int kt, int s) {
        int kof = kt * 64;
        #pragma unroll
        for (int i = 0; i < 4; i++) {
            int r = r_ld + i * 32;
            CP16(smem_u + (s * AST + r * 72 + c_ld) * 2,
                 A + (size_t)(m0 + r) * K + kof + c_ld);
        }
        #pragma unroll
        for (int i = 0; i < 4; i++) {
            int r = r_ld + i * 32;
            CP16(smem_u + (BOFF + s * AST + r * 72 + c_ld) * 2,
                 B + (size_t)(n0 + r) * K + kof + c_ld);
        }
    };

    loadTile(0, 0);
    CP_COMMIT();

    for (int it = 0; it < 16; it++) {
        int s = it & 1;
        if (it + 1 < 16) {
            loadTile(it + 1, s ^ 1);
            CP_COMMIT();
            CP_WAIT(1);
        } else {
            CP_WAIT(0);
        }
        __syncthreads();

        int sa = s * AST, sb = BOFF + s * AST;
        #pragma unroll
        for (int ks = 0; ks < 4; ks++) {
            int kb = ks * 16;
            uint32_t a[4][4], b4[2][4];
            #pragma unroll
            for (int i = 0; i < 4; i++)
                LDSM4(a[i][0], a[i][1], a[i][2], a[i][3],
                      smem_u + (sa + (mb + i * 16 + aRow) * 72 + kb + aCol) * 2);
            #pragma unroll
            for (int jp = 0; jp < 2; jp++)
                LDSM4(b4[jp][0], b4[jp][1], b4[jp][2], b4[jp][3],
                      smem_u + (sb + (nb + jp * 16 + bRow) * 72 + kb + bCol) * 2);
            #pragma unroll
            for (int i = 0; i < 4; i++)
                #pragma unroll
                for (int j = 0; j < 4; j++) {
                    uint32_t bb[2] = { b4[j >> 1][(j & 1) * 2],
                                       b4[j >> 1][(j & 1) * 2 + 1] };
                    MMA_F16(acc[i][j], a[i], bb);
                }
        }
        __syncthreads();
    }

    #pragma unroll
    for (int i = 0; i < 4; i++) {
        int gm = m0 + mb + i * 16 + g;
        #pragma unroll
        for (int j = 0; j < 4; j++) {
            int gn = n0 + nb + j * 8 + tig * 2;
            #pragma unroll
            for (int half_ = 0; half_ < 2; half_++) {
                int m = gm + half_ * 8;
                float v0 = acc[i][j][half_ * 2];
                float v1 = acc[i][j][half_ * 2 + 1];
                if (!QKV) {
                    float* C = (float*)c0;
                    size_t idx = (size_t)m * Dd + gn;
                    float2 xv = *(const float2*)&xres[idx];
                    *(float2*)&C[idx] = make_float2(v0 + b0[gn] + xv.x,
                                                    v1 + b0[gn + 1] + xv.y);
                } else {
                    int bi = m >> 11, s2 = m & (Ss - 1);
                    int hh = gn >> 6, d = gn & 63;
                    if (z < 2) {
                        __half* C = (__half*)((z == 0) ? c0 : c1);
                        uint32_t pv = packh2(v0 + bias[gn], v1 + bias[gn + 1]);
                        *(uint32_t*)&C[(((size_t)(bi * Hh + hh) * Ss) + s2) * DK + d] = pv;
                    } else {
                        __half* C = (__half*)c2;
                        size_t base = ((size_t)(bi * Hh + hh) * DK + d) * Ss + s2;
                        C[base]      = __float2half(v0 + bias[gn]);
                        C[base + Ss] = __float2half(v1 + bias[gn + 1]);
                    }
                }
            }
        }
    }
}

// ---------------------------------------------------------------------------
// Fused attention, fp16 mma + ldmatrix, no-max softmax, register-P pass B.
// ---------------------------------------------------------------------------
__global__ __launch_bounds__(256, 2) void attn_fused(
    const __half* __restrict__ Q, const __half* __restrict__ Kk,
    const __half* __restrict__ Vt, const int* __restrict__ mask,
    float* __restrict__ attn, __half* __restrict__ O)
{
    extern __shared__ __align__(16) __half hsm[];
    float* fsm = (float*)hsm;
    // halves: Q[128][72]@0; pass A K dbuf 2x[128][72]@9216 (stride 9216);
    // pass B: Kb 2x[64][72]@9216 (stride 4608), Vb 2x[64][72]@18432 (stride 4608)
    // floats: WSS@13824[512], SMI@14336[128]
    const int KA = 9216, KB = 9216, VB = 18432;
    const int WSS = 13824, SMI = 14336;
    uint32_t smem_u = (uint32_t)__cvta_generic_to_shared(hsm);

    int tid = threadIdx.x;
    int bz = blockIdx.y;               // bh
    int m0 = blockIdx.x * 128;
    const __half* Qp = Q  + (size_t)bz * Ss * DK;
    const __half* Kp = Kk + (size_t)bz * Ss * DK;
    const __half* Vp = Vt + (size_t)bz * DK * Ss;
    const int* mrow = mask + (size_t)(bz >> 4) * Ss * Ss;
    float* arow = attn + (size_t)bz * Ss * Ss;

    int lane = tid & 31, warp = tid >> 5;
    int wm = warp >> 2, wn = warp & 3;
    int g = lane >> 2, tig = lane & 3;
    int mbA = wm * 64;
    int mbB = warp * 16;

    int aRow = lane & 15;
    int aCol = (lane >> 4) << 3;
    int bRow = ((lane >> 4) << 3) + (lane & 7);
    int bCol = ((lane >> 3) & 1) << 3;

    // ---- load Q strip + first K tile: 128 rows x 64 halves = 1024 chunks ----
    #pragma unroll
    for (int i = 0; i < 4; i++) {
        int idx = tid + i * 256;
        int r = idx >> 3, c = (idx & 7) * 8;
        CP16(smem_u + (r * 72 + c) * 2, Qp + (size_t)(m0 + r) * DK + c);
    }
    #pragma unroll
    for (int i = 0; i < 4; i++) {
        int idx = tid + i * 256;
        int r = idx >> 3, c = (idx & 7) * 8;
        CP16(smem_u + (KA + r * 72 + c) * 2, Kp + (size_t)r * DK + c);
    }
    CP_COMMIT();

    float zs[8];
    #pragma unroll
    for (int s8 = 0; s8 < 8; s8++) zs[s8] = 0.0f;

    // ================= pass A: Z only =================
    for (int kt = 0; kt < 16; kt++) {
        CP_WAIT(0);
        __syncthreads();

        if (kt + 1 < 16) {
            int bo = KA + ((kt + 1) & 1) * 9216;
            #pragma unroll
            for (int i = 0; i < 4; i++) {
                int idx = tid + i * 256;
                int r = idx >> 3, c = (idx & 7) * 8;
                CP16(smem_u + (bo + r * 72 + c) * 2,
                     Kp + (size_t)((kt + 1) * 128 + r) * DK + c);
            }
            CP_COMMIT();
        }

        int ko = KA + (kt & 1) * 9216;
        float acc[4][4][4] = {};
        #pragma unroll
        for (int ks = 0; ks < 4; ks++) {
            int kb = ks * 16;
            uint32_t a[4][4], b4[2][4];
            #pragma unroll
            for (int i = 0; i < 4; i++)
                LDSM4(a[i][0], a[i][1], a[i][2], a[i][3],
                      smem_u + ((mbA + i * 16 + aRow) * 72 + kb + aCol) * 2);
            #pragma unroll
            for (int jp = 0; jp < 2; jp++)
                LDSM4(b4[jp][0], b4[jp][1], b4[jp][2], b4[jp][3],
                      smem_u + (ko + (wn * 32 + jp * 16 + bRow) * 72 + kb + bCol) * 2);
            #pragma unroll
            for (int i = 0; i < 4; i++)
                #pragma unroll
                for (int j = 0; j < 4; j++) {
                    uint32_t bb[2] = { b4[j >> 1][(j & 1) * 2],
                                       b4[j >> 1][(j & 1) * 2 + 1] };
                    MMA_F16(acc[i][j], a[i], bb);
                }
        }

        // epilogue: masked exp-sum (no max)
        #pragma unroll
        for (int i = 0; i < 4; i++) {
            #pragma unroll
            for (int half_ = 0; half_ < 2; half_++) {
                int s8 = i * 2 + half_;
                int m = m0 + mbA + i * 16 + half_ * 8 + g;
                float se = 0.0f;
                #pragma unroll
                for (int j = 0; j < 4; j++) {
                    int gn = kt * 128 + wn * 32 + j * 8 + tig * 2;
                    int2 mv = *(const int2*)&mrow[(size_t)m * Ss + gn];
                    if (mv.x) se += __expf(acc[i][j][half_ * 2] * 0.125f);
                    if (mv.y) se += __expf(acc[i][j][half_ * 2 + 1] * 0.125f);
                }
                zs[s8] += se;
            }
        }
    }

    // quad-reduce, per-warp partials
    #pragma unroll
    for (int s8 = 0; s8 < 8; s8++) {
        zs[s8] += __shfl_xor_sync(0xffffffffu, zs[s8], 1);
        zs[s8] += __shfl_xor_sync(0xffffffffu, zs[s8], 2);
    }
    if (tig == 0) {
        #pragma unroll
        for (int s8 = 0; s8 < 8; s8++) {
            int rloc = mbA + (s8 >> 1) * 16 + (s8 & 1) * 8 + g;
            fsm[WSS + rloc * 4 + wn] = zs[s8];
        }
    }
    __syncthreads();

    // preload pass-B tile 0 (K, V: 64 rows x 64 halves = 512 chunks each)
    #pragma unroll
    for (int i = 0; i < 2; i++) {
        int idx = tid + i * 256;
        int r = idx >> 3, c = (idx & 7) * 8;
        CP16(smem_u + (KB + r * 72 + c) * 2, Kp + (size_t)r * DK + c);
        CP16(smem_u + (VB + r * 72 + c) * 2, Vp + (size_t)r * Ss + c);
    }
    CP_COMMIT();

    if (tid < 128) {
        float Z = fsm[WSS + tid * 4] + fsm[WSS + tid * 4 + 1] +
                  fsm[WSS + tid * 4 + 2] + fsm[WSS + tid * 4 + 3];
        fsm[SMI + tid] = 1.0f / Z;
    }
    __syncthreads();

    float invlo = fsm[SMI + mbB + g];
    float invhi = fsm[SMI + mbB + g + 8];

    // ================= pass B =================
    float oacc[8][4] = {};

    for (int tt = 0; tt < 32; tt++) {
        CP_WAIT(0);
        __syncthreads();

        if (tt + 1 < 32) {
            int kbo = KB + ((tt + 1) & 1) * 4608;
            int vbo = VB + ((tt + 1) & 1) * 4608;
            #pragma unroll
            for (int i = 0; i < 2; i++) {
                int idx = tid + i * 256;
                int r = idx >> 3, c = (idx & 7) * 8;
                CP16(smem_u + (kbo + r * 72 + c) * 2,
                     Kp + (size_t)((tt + 1) * 64 + r) * DK + c);
                CP16(smem_u + (vbo + r * 72 + c) * 2,
                     Vp + (size_t)r * Ss + (tt + 1) * 64 + c);
            }
            CP_COMMIT();
        }

        int ko = KB + (tt & 1) * 4608;
        int vo = VB + (tt & 1) * 4608;

        // --- S for all 64 keys, warp-exclusive rows mbB..mbB+15 ---
        float sacc[8][4] = {};
        #pragma unroll
        for (int ks = 0; ks < 4; ks++) {
            int kb = ks * 16;
            uint32_t a[4], b4[4][4];
            LDSM4(a[0], a[1], a[2], a[3],
                  smem_u + ((mbB + aRow) * 72 + kb + aCol) * 2);
            #pragma unroll
            for (int jp = 0; jp < 4; jp++)
                LDSM4(b4[jp][0], b4[jp][1], b4[jp][2], b4[jp][3],
                      smem_u + (ko + (jp * 16 + bRow) * 72 + kb + bCol) * 2);
            #pragma unroll
            for (int j = 0; j < 8; j++) {
                uint32_t bb[2] = { b4[j >> 1][(j & 1) * 2],
                                   b4[j >> 1][(j & 1) * 2 + 1] };
                MMA_F16(sacc[j], a, bb);
            }
        }

        // --- epilogue: p = exp(0.125*s)*invZ; write attn; keep p in sacc ---
        int mlo = m0 + mbB + g, mhi = mlo + 8;
        #pragma unroll
        for (int j = 0; j < 8; j++) {
            int gn = tt * 64 + j * 8 + tig * 2;
            size_t i0 = (size_t)mlo * Ss + gn;
            size_t i1 = (size_t)mhi * Ss + gn;
            int2 v0 = *(const int2*)&mrow[i0];
            int2 v1 = *(const int2*)&mrow[i1];
            float p0 = v0.x ? __expf(sacc[j][0] * 0.125f) * invlo : 0.0f;
            float p1 = v0.y ? __expf(sacc[j][1] * 0.125f) * invlo : 0.0f;
            float p2 = v1.x ? __expf(sacc[j][2] * 0.125f) * invhi : 0.0f;
            float p3 = v1.y ? __expf(sacc[j][3] * 0.125f) * invhi : 0.0f;
            *(float2*)&arow[i0] = make_float2(p0, p1);
            *(float2*)&arow[i1] = make_float2(p2, p3);
            sacc[j][0] = p0; sacc[j][1] = p1;
            sacc[j][2] = p2; sacc[j][3] = p3;
        }

        // --- AV: pack S-frag -> A-frag in registers; O += P@V ---
        #pragma unroll
        for (int q = 0; q < 4; q++) {
            uint32_t a[4];
            a[0] = packh2(sacc[2 * q][0],     sacc[2 * q][1]);
            a[1] = packh2(sacc[2 * q][2],     sacc[2 * q][3]);
            a[2] = packh2(sacc[2 * q + 1][0], sacc[2 * q + 1][1]);
            a[3] = packh2(sacc[2 * q + 1][2], sacc[2 * q + 1][3]);

            int kb = q * 16;
            uint32_t b4[4][4];
            #pragma unroll
            for (int jp = 0; jp < 4; jp++)
                LDSM4(b4[jp][0], b4[jp][1], b4[jp][2], b4[jp][3],
                      smem_u + (vo + (jp * 16 + bRow) * 72 + kb + bCol) * 2);
            #pragma unroll
            for (int j2 = 0; j2 < 8; j2++) {
                uint32_t bb[2] = { b4[j2 >> 1][(j2 & 1) * 2],
                                   b4[j2 >> 1][(j2 & 1) * 2 + 1] };
                MMA_F16(oacc[j2], a, bb);
            }
        }
    }

    // ---- O epilogue (fp16 O feeds FC) ----
    int bi = bz >> 4, hh = bz & 15;
    int mlo = m0 + mbB + g;
    #pragma unroll
    for (int j2 = 0; j2 < 8; j2++) {
        int d = hh * 64 + j2 * 8 + tig * 2;
        *(uint32_t*)&O[((size_t)bi * Ss + mlo) * Dd + d] =
            packh2(oacc[j2][0], oacc[j2][1]);
        *(uint32_t*)&O[((size_t)bi * Ss + mlo + 8) * Dd + d] =
            packh2(oacc[j2][2], oacc[j2][3]);
    }
}

// ---------------------------------------------------------------------------
extern "C" void kernel_launch(void* const* d_in, const int* in_sizes, int n_in,
                              void* d_out, int out_size)
{
    const float* x    = (const float*)d_in[0];
    const int*   mask = (const int*)d_in[1];
    const float* ln_a = (const float*)d_in[2];
    const float* ln_b = (const float*)d_in[3];
    const float* wq_w = (const float*)d_in[4];
    const float* wq_b = (const float*)d_in[5];
    const float* wk_w = (const float*)d_in[6];
    const float* wk_b = (const float*)d_in[7];
    const float* wv_w = (const float*)d_in[8];
    const float* wv_b = (const float*)d_in[9];
    const float* fc_w = (const float*)d_in[10];
    const float* fc_b = (const float*)d_in[11];
    float* out = (float*)d_out;

    void *ph, *pq, *pk, *pvt, *po, *pwq, *pwk, *pwv, *pwf;
    cudaGetSymbolAddress(&ph,  g_h);
    cudaGetSymbolAddress(&pq,  g_q);
    cudaGetSymbolAddress(&pk,  g_k);
    cudaGetSymbolAddress(&pvt, g_vt);
    cudaGetSymbolAddress(&po,  g_o);
    cudaGetSymbolAddress(&pwq, g_wq);
    cudaGetSymbolAddress(&pwk, g_wk);
    cudaGetSymbolAddress(&pwv, g_wv);
    cudaGetSymbolAddress(&pwf, g_wf);
    __half* h   = (__half*)ph;
    __half* q   = (__half*)pq;
    __half* k   = (__half*)pk;
    __half* vt  = (__half*)pvt;
    __half* o   = (__half*)po;

    float* attn = out + OUT_ELEMS;

    const int DSM_G = 73728;       // gemm smem bytes
    const int DSM_A = 57856;       // attn smem bytes
    cudaFuncSetAttribute(gemm_h<1>, cudaFuncAttributeMaxDynamicSharedMemorySize, DSM_G);
    cudaFuncSetAttribute(gemm_h<0>, cudaFuncAttributeMaxDynamicSharedMemorySize, DSM_G);
    cudaFuncSetAttribute(attn_fused, cudaFuncAttributeMaxDynamicSharedMemorySize, DSM_A);

    // 0. Weights -> fp16
    whalf_kernel<<<1024, 256>>>(wq_w, (__half*)pwq);
    whalf_kernel<<<1024, 256>>>(wk_w, (__half*)pwk);
    whalf_kernel<<<1024, 256>>>(wv_w, (__half*)pwv);
    whalf_kernel<<<1024, 256>>>(fc_w, (__half*)pwf);

    // 1. LayerNorm (fp16 out)
    ln_kernel<<<Bb * Ss, 256>>>(x, ln_a, ln_b, h);

    // 2. QKV projections (single z-indexed launch)
    gemm_h<1><<<dim3(8, 64, 3), 256, DSM_G>>>(
        h, (__half*)pwq, (__half*)pwk, (__half*)pwv,
        wq_b, wk_b, wv_b, nullptr, q, k, vt);

    // 3+4+5. Fused attention
    attn_fused<<<dim3(16, Bb * Hh), 256, DSM_A>>>(q, k, vt, mask, attn, o);

    // 6. FC + bias + residual
    gemm_h<0><<<dim3(8, 64, 1), 256, DSM_G>>>(
        o, (__half*)pwf, nullptr, nullptr,
        fc_b, nullptr, nullptr, x, out, nullptr, nullptr);
}

// round 11
// speedup vs baseline: 5.8927x; 1.2123x over previous
#include <cuda_runtime.h>
#include <cuda_fp16.h>
#include <math.h>
#include <stdint.h>

#define Bb 4
#define Ss 2048
#define Dd 1024
#define Hh 16
#define DK 64

static const size_t OUT_ELEMS = (size_t)Bb * Ss * Dd;   // 8388608

// Scratch (device globals — allocation-free per harness rules)
__device__ __half g_h[(size_t)Bb * Ss * Dd];
__device__ __half g_q[(size_t)Bb * Hh * Ss * DK];
__device__ __half g_k[(size_t)Bb * Hh * Ss * DK];
__device__ __half g_vt[(size_t)Bb * Hh * DK * Ss];  // V^T: [bh][d][s]
__device__ __half g_o[(size_t)Bb * Ss * Dd];
__device__ __half g_wq[(size_t)Dd * Dd];
__device__ __half g_wk[(size_t)Dd * Dd];
__device__ __half g_wv[(size_t)Dd * Dd];
__device__ __half g_wf[(size_t)Dd * Dd];
__device__ uint32_t g_mbits[(size_t)Bb * Ss * (Ss / 32)];   // 1 bit / key

// ---------------------------------------------------------------------------
#define CP16(dst_u32, src_ptr) \
    asm volatile("cp.async.cg.shared.global [%0], [%1], 16;\n" :: "r"(dst_u32), "l"(src_ptr))
#define CP_COMMIT() asm volatile("cp.async.commit_group;\n" ::)
#define CP_WAIT(N)  asm volatile("cp.async.wait_group %0;\n" :: "n"(N))

#define MMA_F16(acc, a, b) \
    asm volatile( \
        "mma.sync.aligned.m16n8k16.row.col.f32.f16.f16.f32 " \
        "{%0,%1,%2,%3}, {%4,%5,%6,%7}, {%8,%9}, {%0,%1,%2,%3};" \
        : "+f"(acc[0]), "+f"(acc[1]), "+f"(acc[2]), "+f"(acc[3]) \
        : "r"(a[0]), "r"(a[1]), "r"(a[2]), "r"(a[3]), "r"(b[0]), "r"(b[1]))

#define LDSM4(R0, R1, R2, R3, ADDR) \
    asm volatile("ldmatrix.sync.aligned.m8n8.x4.shared.b16 {%0,%1,%2,%3}, [%4];" \
        : "=r"(R0), "=r"(R1), "=r"(R2), "=r"(R3) : "r"(ADDR))

__device__ __forceinline__ uint32_t packh2(float lo, float hi) {
    __half2 h = __floats2half2_rn(lo, hi);
    return *(uint32_t*)&h;
}
// exp(0.125*s) = 2^(s * 0.125*log2(e))
#define EXP_SC 0.1803368801111244f
__device__ __forceinline__ float ex2f(float x) {
    float r;
    asm("ex2.approx.f32 %0, %1;" : "=f"(r) : "f"(x));
    return r;
}

__device__ __forceinline__ float blockReduceSum(float val) {
    __shared__ float sh[32];
    int lane = threadIdx.x & 31, wid = threadIdx.x >> 5;
    #pragma unroll
    for (int o = 16; o; o >>= 1) val += __shfl_down_sync(0xffffffffu, val, o);
    if (lane == 0) sh[wid] = val;
    __syncthreads();
    val = (threadIdx.x < 8) ? sh[lane] : 0.0f;
    if (wid == 0) {
        #pragma unroll
        for (int o = 4; o; o >>= 1) val += __shfl_down_sync(0xffffffffu, val, o);
    }
    __syncthreads();
    return val;
}

// ---------------------------------------------------------------------------
// mask (int32) -> bitmap (1 bit per element), warp-ballot, fully coalesced
// ---------------------------------------------------------------------------
__global__ __launch_bounds__(256) void mask_bits_kernel(
    const int* __restrict__ mask, uint32_t* __restrict__ bits)
{
    int warp = threadIdx.x >> 5, lane = threadIdx.x & 31;
    size_t w0 = (size_t)blockIdx.x * 256 + warp * 32;
    #pragma unroll 4
    for (int i = 0; i < 32; i++) {
        size_t w = w0 + i;
        int v = mask[w * 32 + lane];
        uint32_t bm = __ballot_sync(0xffffffffu, v != 0);
        if (lane == 0) bits[w] = bm;
    }
}

// ---------------------------------------------------------------------------
// LayerNorm — writes fp16 h
// ---------------------------------------------------------------------------
__global__ __launch_bounds__(256) void ln_kernel(
    const float* __restrict__ x, const float* __restrict__ a,
    const float* __restrict__ bvec, __half* __restrict__ h)
{
    int row = blockIdx.x;
    const float4* xr = (const float4*)(x + (size_t)row * Dd);
    float4 v = xr[threadIdx.x];

    float s = blockReduceSum(v.x + v.y + v.z + v.w);
    __shared__ float mean_s, inv_s;
    if (threadIdx.x == 0) mean_s = s * (1.0f / Dd);
    __syncthreads();
    float mean = mean_s;

    float dx = v.x - mean, dy = v.y - mean, dz = v.z - mean, dw = v.w - mean;
    float sq = blockReduceSum(dx * dx + dy * dy + dz * dz + dw * dw);
    if (threadIdx.x == 0) inv_s = 1.0f / (sqrtf(sq * (1.0f / (Dd - 1))) + 1e-6f);
    __syncthreads();
    float inv = inv_s;

    float4 av = ((const float4*)a)[threadIdx.x];
    float4 bv = ((const float4*)bvec)[threadIdx.x];
    uint2 o;
    o.x = packh2(av.x * dx * inv + bv.x, av.y * dy * inv + bv.y);
    o.y = packh2(av.z * dz * inv + bv.z, av.w * dw * inv + bv.w);
    *(uint2*)(h + (size_t)row * Dd + threadIdx.x * 4) = o;
}

__global__ __launch_bounds__(256) void whalf_kernel(
    const float* __restrict__ src, __half* __restrict__ dst)
{
    int i = blockIdx.x * 256 + threadIdx.x;
    float4 v = ((const float4*)src)[i];
    uint2 o;
    o.x = packh2(v.x, v.y);
    o.y = packh2(v.z, v.w);
    *(uint2*)(dst + (size_t)i * 4) = o;
}

// ---------------------------------------------------------------------------
// fp16 GEMM core (ldmatrix fragments). BM=128, BN=128, BK=64, 8 warps.
// QKV==1: blockIdx.z selects Q/K/V weight + scatter epilogue.
// QKV==0: FC (+bias+residual, fp32 out).
// ---------------------------------------------------------------------------
template<int QKV>
__global__ __launch_bounds__(256, 2) void gemm_h(
    const __half* __restrict__ A,
    const __half* __restrict__ w0, const __half* __restrict__ w1,
    const __half* __restrict__ w2,
    const float* __restrict__ b0, const float* __restrict__ b1,
    const float* __restrict__ b2,
    const float* __restrict__ xres,
    void* __restrict__ c0, void* __restrict__ c1, void* __restrict__ c2)
{
    extern __shared__ __align__(16) __half hsm[];
    const int AST = 9216, BOFF = 18432;    // half units
    uint32_t smem_u = (uint32_t)__cvta_generic_to_shared(hsm);

    int z = QKV ? blockIdx.z : 0;
    const __half* B    = (z == 0) ? w0 : (z == 1) ? w1 : w2;
    const float* bias  = (z == 0) ? b0 : (z == 1) ? b1 : b2;

    const int K = Dd;
    int tid = threadIdx.x;
    int m0 = blockIdx.y * 128, n0 = blockIdx.x * 128;
    int lane = tid & 31, warp = tid >> 5;
    int wm = warp >> 2, wn = warp & 3;
    int g = lane >> 2, tig = lane & 3;
    int mb = wm * 64, nb = wn * 32;

    int aRow = lane & 15;
    int aCol = (lane >> 4) << 3;
    int bRow = ((lane >> 4) << 3) + (lane & 7);
    int bCol = ((lane >> 3) & 1) << 3;

    float acc[4][4][4] = {};

    int r_ld = tid >> 3;
    int c_ld = (tid & 7) * 8;

    auto loadTile = [&](int kt, int s) {
        int kof = kt * 64;
        #pragma unroll
        for (int i = 0; i < 4; i++) {
            int r = r_ld + i * 32;
            CP16(smem_u + (s * AST + r * 72 + c_ld) * 2,
                 A + (size_t)(m0 + r) * K + kof + c_ld);
        }
        #pragma unroll
        for (int i = 0; i < 4; i++) {
            int r = r_ld + i * 32;
            CP16(smem_u + (BOFF + s * AST + r * 72 + c_ld) * 2,
                 B + (size_t)(n0 + r) * K + kof + c_ld);
        }
    };

    loadTile(0, 0);
    CP_COMMIT();

    for (int it = 0; it < 16; it++) {
        int s = it & 1;
        if (it + 1 < 16) {
            loadTile(it + 1, s ^ 1);
            CP_COMMIT();
            CP_WAIT(1);
        } else {
            CP_WAIT(0);
        }
        __syncthreads();

        int sa = s * AST, sb = BOFF + s * AST;
        #pragma unroll
        for (int ks = 0; ks < 4; ks++) {
            int kb = ks * 16;
            uint32_t a[4][4], b4[2][4];
            #pragma unroll
            for (int i = 0; i < 4; i++)
                LDSM4(a[i][0], a[i][1], a[i][2], a[i][3],
                      smem_u + (sa + (mb + i * 16 + aRow) * 72 + kb + aCol) * 2);
            #pragma unroll
            for (int jp = 0; jp < 2; jp++)
                LDSM4(b4[jp][0], b4[jp][1], b4[jp][2], b4[jp][3],
                      smem_u + (sb + (nb + jp * 16 + bRow) * 72 + kb + bCol) * 2);
            #pragma unroll
            for (int i = 0; i < 4; i++)
                #pragma unroll
                for (int j = 0; j < 4; j++) {
                    uint32_t bb[2] = { b4[j >> 1][(j & 1) * 2],
                                       b4[j >> 1][(j & 1) * 2 + 1] };
                    MMA_F16(acc[i][j], a[i], bb);
                }
        }
        __syncthreads();
    }

    #pragma unroll
    for (int i = 0; i < 4; i++) {
        int gm = m0 + mb + i * 16 + g;
        #pragma unroll
        for (int j = 0; j < 4; j++) {
            int gn = n0 + nb + j * 8 + tig * 2;
            #pragma unroll
            for (int half_ = 0; half_ < 2; half_++) {
                int m = gm + half_ * 8;
                float v0 = acc[i][j][half_ * 2];
                float v1 = acc[i][j][half_ * 2 + 1];
                if (!QKV) {
                    float* C = (float*)c0;
                    size_t idx = (size_t)m * Dd + gn;
                    float2 xv = *(const float2*)&xres[idx];
                    *(float2*)&C[idx] = make_float2(v0 + b0[gn] + xv.x,
                                                    v1 + b0[gn + 1] + xv.y);
                } else {
                    int bi = m >> 11, s2 = m & (Ss - 1);
                    int hh = gn >> 6, d = gn & 63;
                    if (z < 2) {
                        __half* C = (__half*)((z == 0) ? c0 : c1);
                        uint32_t pv = packh2(v0 + bias[gn], v1 + bias[gn + 1]);
                        *(uint32_t*)&C[(((size_t)(bi * Hh + hh) * Ss) + s2) * DK + d] = pv;
                    } else {
                        __half* C = (__half*)c2;
                        size_t base = ((size_t)(bi * Hh + hh) * DK + d) * Ss + s2;
                        C[base]      = __float2half(v0 + bias[gn]);
                        C[base + Ss] = __float2half(v1 + bias[gn + 1]);
                    }
                }
            }
        }
    }
}

// ---------------------------------------------------------------------------
// Fused attention, fp16 mma + ldmatrix, bitmask, no-max softmax, register-P.
// ---------------------------------------------------------------------------
__global__ __launch_bounds__(256, 2) void attn_fused(
    const __half* __restrict__ Q, const __half* __restrict__ Kk,
    const __half* __restrict__ Vt, const uint32_t* __restrict__ mbits,
    float* __restrict__ attn, __half* __restrict__ O)
{
    extern __shared__ __align__(16) __half hsm[];
    float* fsm = (float*)hsm;
    const int KA = 9216, KB = 9216, VB = 18432;
    const int WSS = 13824, SMI = 14336;
    uint32_t smem_u = (uint32_t)__cvta_generic_to_shared(hsm);

    int tid = threadIdx.x;
    int bz = blockIdx.y;               // bh
    int m0 = blockIdx.x * 128;
    const __half* Qp = Q  + (size_t)bz * Ss * DK;
    const __half* Kp = Kk + (size_t)bz * Ss * DK;
    const __half* Vp = Vt + (size_t)bz * DK * Ss;
    const uint32_t* mb_ = mbits + (size_t)(bz >> 4) * Ss * (Ss / 32);
    float* arow = attn + (size_t)bz * Ss * Ss;

    int lane = tid & 31, warp = tid >> 5;
    int wm = warp >> 2, wn = warp & 3;
    int g = lane >> 2, tig = lane & 3;
    int mbA = wm * 64;
    int mbB = warp * 16;

    int aRow = lane & 15;
    int aCol = (lane >> 4) << 3;
    int bRow = ((lane >> 4) << 3) + (lane & 7);
    int bCol = ((lane >> 3) & 1) << 3;

    // ---- load Q strip + first K tile: 128 rows x 64 halves = 1024 chunks ----
    #pragma unroll
    for (int i = 0; i < 4; i++) {
        int idx = tid + i * 256;
        int r = idx >> 3, c = (idx & 7) * 8;
        CP16(smem_u + (r * 72 + c) * 2, Qp + (size_t)(m0 + r) * DK + c);
    }
    #pragma unroll
    for (int i = 0; i < 4; i++) {
        int idx = tid + i * 256;
        int r = idx >> 3, c = (idx & 7) * 8;
        CP16(smem_u + (KA + r * 72 + c) * 2, Kp + (size_t)r * DK + c);
    }
    CP_COMMIT();

    float zs[8];
    #pragma unroll
    for (int s8 = 0; s8 < 8; s8++) zs[s8] = 0.0f;

    // ================= pass A: Z only =================
    for (int kt = 0; kt < 16; kt++) {
        CP_WAIT(0);
        __syncthreads();

        if (kt + 1 < 16) {
            int bo = KA + ((kt + 1) & 1) * 9216;
            #pragma unroll
            for (int i = 0; i < 4; i++) {
                int idx = tid + i * 256;
                int r = idx >> 3, c = (idx & 7) * 8;
                CP16(smem_u + (bo + r * 72 + c) * 2,
                     Kp + (size_t)((kt + 1) * 128 + r) * DK + c);
            }
            CP_COMMIT();
        }

        int ko = KA + (kt & 1) * 9216;
        float acc[4][4][4] = {};
        #pragma unroll
        for (int ks = 0; ks < 4; ks++) {
            int kb = ks * 16;
            uint32_t a[4][4], b4[2][4];
            #pragma unroll
            for (int i = 0; i < 4; i++)
                LDSM4(a[i][0], a[i][1], a[i][2], a[i][3],
                      smem_u + ((mbA + i * 16 + aRow) * 72 + kb + aCol) * 2);
            #pragma unroll
            for (int jp = 0; jp < 2; jp++)
                LDSM4(b4[jp][0], b4[jp][1], b4[jp][2], b4[jp][3],
                      smem_u + (ko + (wn * 32 + jp * 16 + bRow) * 72 + kb + bCol) * 2);
            #pragma unroll
            for (int i = 0; i < 4; i++)
                #pragma unroll
                for (int j = 0; j < 4; j++) {
                    uint32_t bb[2] = { b4[j >> 1][(j & 1) * 2],
                                       b4[j >> 1][(j & 1) * 2 + 1] };
                    MMA_F16(acc[i][j], a[i], bb);
                }
        }

        // epilogue: bitmask exp-sum (no max); one u32 load per row-slice
        #pragma unroll
        for (int i = 0; i < 4; i++) {
            #pragma unroll
            for (int half_ = 0; half_ < 2; half_++) {
                int s8 = i * 2 + half_;
                int m = m0 + mbA + i * 16 + half_ * 8 + g;
                uint32_t bm = mb_[(size_t)m * 64 + kt * 4 + wn];
                float se = 0.0f;
                #pragma unroll
                for (int j = 0; j < 4; j++) {
                    int bp = j * 8 + tig * 2;
                    if ((bm >> bp) & 1)
                        se += ex2f(acc[i][j][half_ * 2] * EXP_SC);
                    if ((bm >> (bp + 1)) & 1)
                        se += ex2f(acc[i][j][half_ * 2 + 1] * EXP_SC);
                }
                zs[s8] += se;
            }
        }
    }

    // quad-reduce, per-warp partials
    #pragma unroll
    for (int s8 = 0; s8 < 8; s8++) {
        zs[s8] += __shfl_xor_sync(0xffffffffu, zs[s8], 1);
        zs[s8] += __shfl_xor_sync(0xffffffffu, zs[s8], 2);
    }
    if (tig == 0) {
        #pragma unroll
        for (int s8 = 0; s8 < 8; s8++) {
            int rloc = mbA + (s8 >> 1) * 16 + (s8 & 1) * 8 + g;
            fsm[WSS + rloc * 4 + wn] = zs[s8];
        }
    }
    __syncthreads();

    // preload pass-B tile 0
    #pragma unroll
    for (int i = 0; i < 2; i++) {
        int idx = tid + i * 256;
        int r = idx >> 3, c = (idx & 7) * 8;
        CP16(smem_u + (KB + r * 72 + c) * 2, Kp + (size_t)r * DK + c);
        CP16(smem_u + (VB + r * 72 + c) * 2, Vp + (size_t)r * Ss + c);
    }
    CP_COMMIT();

    if (tid < 128) {
        float Z = fsm[WSS + tid * 4] + fsm[WSS + tid * 4 + 1] +
                  fsm[WSS + tid * 4 + 2] + fsm[WSS + tid * 4 + 3];
        fsm[SMI + tid] = 1.0f / Z;
    }
    __syncthreads();

    float invlo = fsm[SMI + mbB + g];
    float invhi = fsm[SMI + mbB + g + 8];

    // ================= pass B =================
    float oacc[8][4] = {};

    for (int tt = 0; tt < 32; tt++) {
        CP_WAIT(0);
        __syncthreads();

        if (tt + 1 < 32) {
            int kbo = KB + ((tt + 1) & 1) * 4608;
            int vbo = VB + ((tt + 1) & 1) * 4608;
            #pragma unroll
            for (int i = 0; i < 2; i++) {
                int idx = tid + i * 256;
                int r = idx >> 3, c = (idx & 7) * 8;
                CP16(smem_u + (kbo + r * 72 + c) * 2,
                     Kp + (size_t)((tt + 1) * 64 + r) * DK + c);
                CP16(smem_u + (vbo + r * 72 + c) * 2,
                     Vp + (size_t)r * Ss + (tt + 1) * 64 + c);
            }
            CP_COMMIT();
        }

        int ko = KB + (tt & 1) * 4608;
        int vo = VB + (tt & 1) * 4608;

        // --- S for all 64 keys, warp-exclusive rows mbB..mbB+15 ---
        float sacc[8][4] = {};
        #pragma unroll
        for (int ks = 0; ks < 4; ks++) {
            int kb = ks * 16;
            uint32_t a[4], b4[4][4];
            LDSM4(a[0], a[1], a[2], a[3],
                  smem_u + ((mbB + aRow) * 72 + kb + aCol) * 2);
            #pragma unroll
            for (int jp = 0; jp < 4; jp++)
                LDSM4(b4[jp][0], b4[jp][1], b4[jp][2], b4[jp][3],
                      smem_u + (ko + (jp * 16 + bRow) * 72 + kb + bCol) * 2);
            #pragma unroll
            for (int j = 0; j < 8; j++) {
                uint32_t bb[2] = { b4[j >> 1][(j & 1) * 2],
                                   b4[j >> 1][(j & 1) * 2 + 1] };
                MMA_F16(sacc[j], a, bb);
            }
        }

        // --- epilogue: p = exp(0.125*s)*invZ via bitmask; write attn ---
        int mlo = m0 + mbB + g, mhi = mlo + 8;
        uint2 bmlo = *(const uint2*)&mb_[(size_t)mlo * 64 + tt * 2];
        uint2 bmhi = *(const uint2*)&mb_[(size_t)mhi * 64 + tt * 2];
        #pragma unroll
        for (int j = 0; j < 8; j++) {
            int gn = tt * 64 + j * 8 + tig * 2;
            size_t i0 = (size_t)mlo * Ss + gn;
            size_t i1 = (size_t)mhi * Ss + gn;
            int bp = j * 8 + tig * 2;
            uint32_t wlo = (j < 4) ? bmlo.x : bmlo.y;
            uint32_t whi = (j < 4) ? bmhi.x : bmhi.y;
            int sh = bp & 31;
            float p0 = ((wlo >> sh) & 1)       ? ex2f(sacc[j][0] * EXP_SC) * invlo : 0.0f;
            float p1 = ((wlo >> (sh + 1)) & 1) ? ex2f(sacc[j][1] * EXP_SC) * invlo : 0.0f;
            float p2 = ((whi >> sh) & 1)       ? ex2f(sacc[j][2] * EXP_SC) * invhi : 0.0f;
            float p3 = ((whi >> (sh + 1)) & 1) ? ex2f(sacc[j][3] * EXP_SC) * invhi : 0.0f;
            *(float2*)&arow[i0] = make_float2(p0, p1);
            *(float2*)&arow[i1] = make_float2(p2, p3);
            sacc[j][0] = p0; sacc[j][1] = p1;
            sacc[j][2] = p2; sacc[j][3] = p3;
        }

        // --- AV: pack S-frag -> A-frag in registers; O += P@V ---
        #pragma unroll
        for (int q = 0; q < 4; q++) {
            uint32_t a[4];
            a[0] = packh2(sacc[2 * q][0],     sacc[2 * q][1]);
            a[1] = packh2(sacc[2 * q][2],     sacc[2 * q][3]);
            a[2] = packh2(sacc[2 * q + 1][0], sacc[2 * q + 1][1]);
            a[3] = packh2(sacc[2 * q + 1][2], sacc[2 * q + 1][3]);

            int kb = q * 16;
            uint32_t b4[4][4];
            #pragma unroll
            for (int jp = 0; jp < 4; jp++)
                LDSM4(b4[jp][0], b4[jp][1], b4[jp][2], b4[jp][3],
                      smem_u + (vo + (jp * 16 + bRow) * 72 + kb + bCol) * 2);
            #pragma unroll
            for (int j2 = 0; j2 < 8; j2++) {
                uint32_t bb[2] = { b4[j2 >> 1][(j2 & 1) * 2],
                                   b4[j2 >> 1][(j2 & 1) * 2 + 1] };
                MMA_F16(oacc[j2], a, bb);
            }
        }
    }

    // ---- O epilogue (fp16 O feeds FC) ----
    int bi = bz >> 4, hh = bz & 15;
    int mlo = m0 + mbB + g;
    #pragma unroll
    for (int j2 = 0; j2 < 8; j2++) {
        int d = hh * 64 + j2 * 8 + tig * 2;
        *(uint32_t*)&O[((size_t)bi * Ss + mlo) * Dd + d] =
            packh2(oacc[j2][0], oacc[j2][1]);
        *(uint32_t*)&O[((size_t)bi * Ss + mlo + 8) * Dd + d] =
            packh2(oacc[j2][2], oacc[j2][3]);
    }
}

// ---------------------------------------------------------------------------
extern "C" void kernel_launch(void* const* d_in, const int* in_sizes, int n_in,
                              void* d_out, int out_size)
{
    const float* x    = (const float*)d_in[0];
    const int*   mask = (const int*)d_in[1];
    const float* ln_a = (const float*)d_in[2];
    const float* ln_b = (const float*)d_in[3];
    const float* wq_w = (const float*)d_in[4];
    const float* wq_b = (const float*)d_in[5];
    const float* wk_w = (const float*)d_in[6];
    const float* wk_b = (const float*)d_in[7];
    const float* wv_w = (const float*)d_in[8];
    const float* wv_b = (const float*)d_in[9];
    const float* fc_w = (const float*)d_in[10];
    const float* fc_b = (const float*)d_in[11];
    float* out = (float*)d_out;

    void *ph, *pq, *pk, *pvt, *po, *pwq, *pwk, *pwv, *pwf, *pmb;
    cudaGetSymbolAddress(&ph,  g_h);
    cudaGetSymbolAddress(&pq,  g_q);
    cudaGetSymbolAddress(&pk,  g_k);
    cudaGetSymbolAddress(&pvt, g_vt);
    cudaGetSymbolAddress(&po,  g_o);
    cudaGetSymbolAddress(&pwq, g_wq);
    cudaGetSymbolAddress(&pwk, g_wk);
    cudaGetSymbolAddress(&pwv, g_wv);
    cudaGetSymbolAddress(&pwf, g_wf);
    cudaGetSymbolAddress(&pmb, g_mbits);
    __half* h   = (__half*)ph;
    __half* q   = (__half*)pq;
    __half* k   = (__half*)pk;
    __half* vt  = (__half*)pvt;
    __half* o   = (__half*)po;

    float* attn = out + OUT_ELEMS;

    const int DSM_G = 73728;
    const int DSM_A = 57856;
    cudaFuncSetAttribute(gemm_h<1>, cudaFuncAttributeMaxDynamicSharedMemorySize, DSM_G);
    cudaFuncSetAttribute(gemm_h<0>, cudaFuncAttributeMaxDynamicSharedMemorySize, DSM_G);
    cudaFuncSetAttribute(attn_fused, cudaFuncAttributeMaxDynamicSharedMemorySize, DSM_A);

    // 0a. mask -> bitmap  (B*S*S/32 words / 256 per block)
    mask_bits_kernel<<<(Bb * Ss * (Ss / 32)) / 256, 256>>>(mask, (uint32_t*)pmb);

    // 0b. Weights -> fp16
    whalf_kernel<<<1024, 256>>>(wq_w, (__half*)pwq);
    whalf_kernel<<<1024, 256>>>(wk_w, (__half*)pwk);
    whalf_kernel<<<1024, 256>>>(wv_w, (__half*)pwv);
    whalf_kernel<<<1024, 256>>>(fc_w, (__half*)pwf);

    // 1. LayerNorm (fp16 out)
    ln_kernel<<<Bb * Ss, 256>>>(x, ln_a, ln_b, h);

    // 2. QKV projections (single z-indexed launch)
    gemm_h<1><<<dim3(8, 64, 3), 256, DSM_G>>>(
        h, (__half*)pwq, (__half*)pwk, (__half*)pwv,
        wq_b, wk_b, wv_b, nullptr, q, k, vt);

    // 3+4+5. Fused attention (bitmask)
    attn_fused<<<dim3(16, Bb * Hh), 256, DSM_A>>>(
        q, k, vt, (const uint32_t*)pmb, attn, o);

    // 6. FC + bias + residual
    gemm_h<0><<<dim3(8, 64, 1), 256, DSM_G>>>(
        o, (__half*)pwf, nullptr, nullptr,
        fc_b, nullptr, nullptr, x, out, nullptr, nullptr);
}